// round 1
// baseline (speedup 1.0000x reference)
#include <cuda_runtime.h>
#include <math.h>

// Problem constants
#define B_    2
#define L_    1728            // 12*12*12
#define NTOK  3456            // B_*L_
#define C_    256
#define U_    256
#define H_    8
#define HD    32
#define FF_   1024
#define EPS_  1e-3f

// ---------------- scratch (device globals; no allocation allowed) ----------
__device__ float d_h   [NTOK*U_];
__device__ float d_hhat[NTOK*U_];
__device__ float d_q1  [NTOK*U_];
__device__ float d_k1  [NTOK*U_];
__device__ float d_v1  [NTOK*U_];
__device__ float d_q2  [NTOK*U_];
__device__ float d_k2  [NTOK*U_];
__device__ float d_v2  [NTOK*U_];
__device__ float d_O1  [NTOK*U_];
__device__ float d_O2  [NTOK*U_];
__device__ float d_f1  [NTOK*FF_];
__device__ float d_ffo [NTOK*U_];
__device__ float d_acc [NTOK*U_];

__device__ float d_Wpin[C_*U_];
__device__ float d_Wq1 [U_*U_];
__device__ float d_Wq2 [U_*U_];
__device__ float d_Wff1[U_*FF_];
__device__ float d_bpin[U_];
__device__ float d_bq1 [U_];
__device__ float d_bq2 [U_];
__device__ float d_bff1[FF_];

// ---------------- prep: fold BN into pin, fold LN gammas/betas into q/ff1 --
__global__ void prep_kernel(
    const float* __restrict__ bn_g, const float* __restrict__ bn_b,
    const float* __restrict__ bn_m, const float* __restrict__ bn_v,
    const float* __restrict__ ln1_g, const float* __restrict__ ln1_b,
    const float* __restrict__ ln2_g, const float* __restrict__ ln2_b,
    const float* __restrict__ ln3_g, const float* __restrict__ ln3_b,
    const float* __restrict__ pin_w, const float* __restrict__ pin_b,
    const float* __restrict__ q_w,  const float* __restrict__ q_b,
    const float* __restrict__ ff1_w, const float* __restrict__ ff1_b)
{
    int u = blockIdx.x * blockDim.x + threadIdx.x;   // 0..1023
    if (u < U_) {
        float accP = pin_b[u];
        float accQ1 = q_b[u];
        float accQ2 = q_b[u];
        for (int c = 0; c < C_; c++) {
            float sc = rsqrtf(bn_v[c] + EPS_) * bn_g[c];
            float sh = bn_b[c] - bn_m[c] * sc;
            float pw = pin_w[c*U_ + u];
            d_Wpin[c*U_ + u] = sc * pw;
            accP += sh * pw;
            float qw = q_w[c*U_ + u];
            d_Wq1[c*U_ + u] = ln1_g[c] * qw;
            accQ1 += ln1_b[c] * qw;
            d_Wq2[c*U_ + u] = ln2_g[c] * qw;
            accQ2 += ln2_b[c] * qw;
        }
        d_bpin[u] = accP;
        d_bq1[u]  = accQ1;
        d_bq2[u]  = accQ2;
    }
    // ff1 columns (all 1024 u)
    {
        float accF = ff1_b[u];
        for (int c = 0; c < C_; c++) {
            float fw = ff1_w[c*FF_ + u];
            d_Wff1[c*FF_ + u] = ln3_g[c] * fw;
            accF += ln3_b[c] * fw;
        }
        d_bff1[u] = accF;
    }
}

// ---------------- generic fp32 GEMM: C = op(A@W + bias) [+ resid] ----------
// A: [M,K] row-major, W: [K,N] row-major. BM=32, BN=64, BK=16, 128 threads.
// MODE 0: none, 1: relu, 2: relu then += resid
template<int MODE>
__global__ void gemm32(const float* __restrict__ A, const float* __restrict__ W,
                       const float* __restrict__ bias, const float* __restrict__ resid,
                       float* __restrict__ Cout, int M, int N, int K)
{
    const int BM = 32, BN = 64, BK = 16;
    __shared__ float As[BK][BM + 4];   // padded, transposed A tile
    __shared__ float Ws[BK][BN];
    int tid = threadIdx.x;
    int m0 = blockIdx.x * BM;
    int n0 = blockIdx.y * BN;
    int ty = tid >> 4;    // 0..7  -> rows ty*4..ty*4+3
    int tx = tid & 15;    // 0..15 -> cols tx*4..tx*4+3

    float acc[4][4] = {};

    for (int k0 = 0; k0 < K; k0 += BK) {
        // A tile: 32x16 = 128 float4, one per thread (store transposed)
        {
            int v = tid;
            int m = v >> 2, kq = v & 3;
            float4 t = *(const float4*)&A[(size_t)(m0 + m) * K + k0 + kq * 4];
            As[kq*4+0][m] = t.x; As[kq*4+1][m] = t.y;
            As[kq*4+2][m] = t.z; As[kq*4+3][m] = t.w;
        }
        // W tile: 16x64 = 256 float4, two per thread
        #pragma unroll
        for (int i = 0; i < 2; i++) {
            int v = tid + i * 128;
            int kk = v >> 4, nq = v & 15;
            *(float4*)&Ws[kk][nq*4] =
                *(const float4*)&W[(size_t)(k0 + kk) * N + n0 + nq * 4];
        }
        __syncthreads();
        #pragma unroll
        for (int kk = 0; kk < BK; kk++) {
            float4 a4 = *(const float4*)&As[kk][ty*4];
            float4 w4 = *(const float4*)&Ws[kk][tx*4];
            float a[4] = {a4.x, a4.y, a4.z, a4.w};
            float w[4] = {w4.x, w4.y, w4.z, w4.w};
            #pragma unroll
            for (int i = 0; i < 4; i++)
                #pragma unroll
                for (int j = 0; j < 4; j++)
                    acc[i][j] += a[i] * w[j];
        }
        __syncthreads();
    }

    #pragma unroll
    for (int i = 0; i < 4; i++) {
        int m = m0 + ty*4 + i;
        #pragma unroll
        for (int j = 0; j < 4; j++) {
            int n = n0 + tx*4 + j;
            float val = acc[i][j] + bias[n];
            if (MODE >= 1) val = fmaxf(val, 0.f);
            if (MODE == 2) val += resid[(size_t)m * N + n];
            Cout[(size_t)m * N + n] = val;
        }
    }
}

// ---------------- LayerNorm (normalize only; g/b folded into weights) ------
__global__ void lnorm_kernel(const float* __restrict__ h, float* __restrict__ hh)
{
    int row = blockIdx.x;
    int tid = threadIdx.x;
    float v = h[(size_t)row * 256 + tid];
    __shared__ float red[8];
    float s = v;
    #pragma unroll
    for (int o = 16; o > 0; o >>= 1) s += __shfl_xor_sync(0xffffffffu, s, o);
    if ((tid & 31) == 0) red[tid >> 5] = s;
    __syncthreads();
    float tot = 0.f;
    #pragma unroll
    for (int i = 0; i < 8; i++) tot += red[i];
    float mu = tot * (1.f / 256.f);
    float d = v - mu;
    float s2 = d * d;
    #pragma unroll
    for (int o = 16; o > 0; o >>= 1) s2 += __shfl_xor_sync(0xffffffffu, s2, o);
    __syncthreads();   // all reads of red done before overwrite
    if ((tid & 31) == 0) red[tid >> 5] = s2;
    __syncthreads();
    float tot2 = 0.f;
    #pragma unroll
    for (int i = 0; i < 8; i++) tot2 += red[i];
    float var = tot2 * (1.f / 256.f);
    hh[(size_t)row * 256 + tid] = d * rsqrtf(var + EPS_);
}

// ---------------- Flash attention: per-(b,h,qtile) block, 1 thread/query --
// Q,K,V buffers are [B*L, 256] with head hh slice at column hh*32.
__global__ void attn_kernel(const float* __restrict__ Q, const float* __restrict__ Kb,
                            const float* __restrict__ Vb, float* __restrict__ Ob)
{
    __shared__ float Ks[32][36];
    __shared__ float Vs[32][36];
    int tid = threadIdx.x;                 // 0..63
    int b  = blockIdx.z;
    int hh = blockIdx.y;
    int qrow = blockIdx.x * 64 + tid;
    const float scale = 0.0625f;           // UNITS^-0.5 = 1/16

    float q[32], O[32];
    const float* qp = Q + (size_t)(b * L_ + qrow) * U_ + hh * HD;
    #pragma unroll
    for (int d = 0; d < 32; d += 4) {
        float4 t = *(const float4*)&qp[d];
        q[d] = t.x * scale; q[d+1] = t.y * scale;
        q[d+2] = t.z * scale; q[d+3] = t.w * scale;
    }
    #pragma unroll
    for (int d = 0; d < 32; d++) O[d] = 0.f;
    float m = -1e30f, l = 0.f;

    for (int kt = 0; kt < L_; kt += 32) {
        // cooperative K/V tile load: 32x32 each = 256 float4, 4/thread
        #pragma unroll
        for (int i = 0; i < 4; i++) {
            int v = tid + i * 64;
            int j = v >> 3, dq = v & 7;
            size_t go = (size_t)(b * L_ + kt + j) * U_ + hh * HD + dq * 4;
            *(float4*)&Ks[j][dq*4] = *(const float4*)&Kb[go];
            *(float4*)&Vs[j][dq*4] = *(const float4*)&Vb[go];
        }
        __syncthreads();

        float s[32];
        #pragma unroll
        for (int j = 0; j < 32; j++) {
            float a = 0.f;
            #pragma unroll
            for (int d = 0; d < 32; d += 4) {
                float4 k4 = *(const float4*)&Ks[j][d];
                a += q[d] * k4.x + q[d+1] * k4.y + q[d+2] * k4.z + q[d+3] * k4.w;
            }
            s[j] = a;
        }
        float tmax = m;
        #pragma unroll
        for (int j = 0; j < 32; j++) tmax = fmaxf(tmax, s[j]);
        float corr = __expf(m - tmax);
        l *= corr;
        #pragma unroll
        for (int d = 0; d < 32; d++) O[d] *= corr;
        #pragma unroll
        for (int j = 0; j < 32; j++) {
            float p = __expf(s[j] - tmax);
            l += p;
            #pragma unroll
            for (int d = 0; d < 32; d += 4) {
                float4 v4 = *(const float4*)&Vs[j][d];
                O[d]   += p * v4.x; O[d+1] += p * v4.y;
                O[d+2] += p * v4.z; O[d+3] += p * v4.w;
            }
        }
        m = tmax;
        __syncthreads();
    }

    float inv = 1.f / l;
    float* op = Ob + (size_t)(b * L_ + qrow) * U_ + hh * HD;
    #pragma unroll
    for (int d = 0; d < 32; d += 4) {
        float4 t;
        t.x = O[d] * inv; t.y = O[d+1] * inv;
        t.z = O[d+2] * inv; t.w = O[d+3] * inv;
        *(float4*)&op[d] = t;
    }
}

// ---------------- elementwise: acc = h + O1 + O2 + ffo ---------------------
__global__ void sum4_kernel(const float* __restrict__ a, const float* __restrict__ b,
                            const float* __restrict__ c, const float* __restrict__ d,
                            float* __restrict__ out)
{
    int i = blockIdx.x * blockDim.x + threadIdx.x;
    out[i] = a[i] + b[i] + c[i] + d[i];
}

// ---------------- launch ----------------------------------------------------
extern "C" void kernel_launch(void* const* d_in, const int* in_sizes, int n_in,
                              void* d_out, int out_size)
{
    const float* x       = (const float*)d_in[0];
    const float* context = (const float*)d_in[1];
    const float* bn_g = (const float*)d_in[2];
    const float* bn_b = (const float*)d_in[3];
    const float* bn_m = (const float*)d_in[4];
    const float* bn_v = (const float*)d_in[5];
    const float* ln1_g = (const float*)d_in[6];
    const float* ln1_b = (const float*)d_in[7];
    const float* ln2_g = (const float*)d_in[8];
    const float* ln2_b = (const float*)d_in[9];
    const float* ln3_g = (const float*)d_in[10];
    const float* ln3_b = (const float*)d_in[11];
    const float* pin_w = (const float*)d_in[12];
    const float* pin_b = (const float*)d_in[13];
    const float* q_w   = (const float*)d_in[14];
    const float* q_b   = (const float*)d_in[15];
    const float* k_w   = (const float*)d_in[16];
    const float* k_b   = (const float*)d_in[17];
    const float* v_w   = (const float*)d_in[18];
    const float* v_b   = (const float*)d_in[19];
    const float* ff1_w = (const float*)d_in[20];
    const float* ff1_b = (const float*)d_in[21];
    const float* ff2_w = (const float*)d_in[22];
    const float* ff2_b = (const float*)d_in[23];
    const float* pout_w = (const float*)d_in[24];
    const float* pout_b = (const float*)d_in[25];
    float* out = (float*)d_out;

    // resolve device-global scratch addresses
    float *p_h, *p_hhat, *p_q1, *p_k1, *p_v1, *p_q2, *p_k2, *p_v2;
    float *p_O1, *p_O2, *p_f1, *p_ffo, *p_acc;
    float *p_Wpin, *p_Wq1, *p_Wq2, *p_Wff1, *p_bpin, *p_bq1, *p_bq2, *p_bff1;
    cudaGetSymbolAddress((void**)&p_h,    d_h);
    cudaGetSymbolAddress((void**)&p_hhat, d_hhat);
    cudaGetSymbolAddress((void**)&p_q1,   d_q1);
    cudaGetSymbolAddress((void**)&p_k1,   d_k1);
    cudaGetSymbolAddress((void**)&p_v1,   d_v1);
    cudaGetSymbolAddress((void**)&p_q2,   d_q2);
    cudaGetSymbolAddress((void**)&p_k2,   d_k2);
    cudaGetSymbolAddress((void**)&p_v2,   d_v2);
    cudaGetSymbolAddress((void**)&p_O1,   d_O1);
    cudaGetSymbolAddress((void**)&p_O2,   d_O2);
    cudaGetSymbolAddress((void**)&p_f1,   d_f1);
    cudaGetSymbolAddress((void**)&p_ffo,  d_ffo);
    cudaGetSymbolAddress((void**)&p_acc,  d_acc);
    cudaGetSymbolAddress((void**)&p_Wpin, d_Wpin);
    cudaGetSymbolAddress((void**)&p_Wq1,  d_Wq1);
    cudaGetSymbolAddress((void**)&p_Wq2,  d_Wq2);
    cudaGetSymbolAddress((void**)&p_Wff1, d_Wff1);
    cudaGetSymbolAddress((void**)&p_bpin, d_bpin);
    cudaGetSymbolAddress((void**)&p_bq1,  d_bq1);
    cudaGetSymbolAddress((void**)&p_bq2,  d_bq2);
    cudaGetSymbolAddress((void**)&p_bff1, d_bff1);

    // 1. fold BN / LN affine params into weights
    prep_kernel<<<4, 256>>>(bn_g, bn_b, bn_m, bn_v,
                            ln1_g, ln1_b, ln2_g, ln2_b, ln3_g, ln3_b,
                            pin_w, pin_b, q_w, q_b, ff1_w, ff1_b);

    dim3 g256(NTOK/32, U_/64);     // (108, 4)
    dim3 gff (NTOK/32, FF_/64);    // (108, 16)

    // 2. h = relu(x @ Wpin + bpin)
    gemm32<1><<<g256, 128>>>(x, p_Wpin, p_bpin, nullptr, p_h, NTOK, U_, C_);

    // 3. hhat = normalize(h)   (shared by ln1/ln2/ln3)
    lnorm_kernel<<<NTOK, 256>>>(p_h, p_hhat);

    // 4. projections
    gemm32<0><<<g256, 128>>>(p_hhat, p_Wq1, p_bq1, nullptr, p_q1, NTOK, U_, U_);
    gemm32<0><<<g256, 128>>>(p_h,    k_w,   k_b,   nullptr, p_k1, NTOK, U_, U_);
    gemm32<0><<<g256, 128>>>(p_h,    v_w,   v_b,   nullptr, p_v1, NTOK, U_, U_);
    gemm32<0><<<g256, 128>>>(p_hhat, p_Wq2, p_bq2, nullptr, p_q2, NTOK, U_, U_);
    gemm32<0><<<g256, 128>>>(context, k_w,  k_b,   nullptr, p_k2, NTOK, U_, U_);
    gemm32<0><<<g256, 128>>>(context, v_w,  v_b,   nullptr, p_v2, NTOK, U_, U_);

    // 5. attention (self + cross)
    dim3 ga(L_/64, H_, B_);        // (27, 8, 2)
    attn_kernel<<<ga, 64>>>(p_q1, p_k1, p_v1, p_O1);
    attn_kernel<<<ga, 64>>>(p_q2, p_k2, p_v2, p_O2);

    // 6. FFN
    gemm32<1><<<gff,  128>>>(p_hhat, p_Wff1, p_bff1, nullptr, p_f1, NTOK, FF_, U_);
    gemm32<0><<<g256, 128>>>(p_f1,   ff2_w,  ff2_b,  nullptr, p_ffo, NTOK, U_, FF_);

    // 7. acc = h + O1 + O2 + ff
    sum4_kernel<<<NTOK, 256>>>(p_h, p_O1, p_O2, p_ffo, p_acc);

    // 8. out = relu(acc @ pout_w + pout_b) + x
    gemm32<2><<<g256, 128>>>(p_acc, pout_w, pout_b, x, out, NTOK, U_, U_);
}

// round 2
// speedup vs baseline: 1.1235x; 1.1235x over previous
#include <cuda_runtime.h>
#include <math.h>

typedef unsigned long long ull;

#define B_    2
#define L_    1728
#define NTOK  3456
#define C_    256
#define U_    256
#define H_    8
#define HD    32
#define FF_   1024
#define EPS_  1e-3f
#define SPLITS 6
#define KT_PER_SPLIT 9   /* 9 tiles of 32 keys = 288 keys per split */

// ---------------- packed fp32x2 helpers ------------------------------------
__device__ __forceinline__ ull pk(float lo, float hi) {
    ull r; asm("mov.b64 %0,{%1,%2};" : "=l"(r) : "f"(lo), "f"(hi)); return r;
}
__device__ __forceinline__ void upk(ull v, float& lo, float& hi) {
    asm("mov.b64 {%0,%1},%2;" : "=f"(lo), "=f"(hi) : "l"(v));
}
__device__ __forceinline__ ull fma2(ull a, ull b, ull c) {
    ull d; asm("fma.rn.f32x2 %0,%1,%2,%3;" : "=l"(d) : "l"(a), "l"(b), "l"(c)); return d;
}
__device__ __forceinline__ ull mul2(ull a, ull b) {
    ull d; asm("mul.rn.f32x2 %0,%1,%2;" : "=l"(d) : "l"(a), "l"(b)); return d;
}

// ---------------- scratch ---------------------------------------------------
__device__ float d_h   [NTOK*U_];
__device__ float d_hhat[NTOK*U_];
__device__ float d_q1  [NTOK*U_];
__device__ float d_k1  [NTOK*U_];
__device__ float d_v1  [NTOK*U_];
__device__ float d_q2  [NTOK*U_];
__device__ float d_k2  [NTOK*U_];
__device__ float d_v2  [NTOK*U_];
__device__ float d_f1  [NTOK*FF_];
__device__ float d_ffo [NTOK*U_];
__device__ float d_acc [NTOK*U_];
__device__ float d_Opart[2*B_*H_*SPLITS*L_*32];
__device__ float2 d_ML  [2*B_*H_*SPLITS*L_];

__device__ float d_Wpin[C_*U_];
__device__ float d_Wq1 [U_*U_];
__device__ float d_Wq2 [U_*U_];
__device__ float d_Wff1[U_*FF_];
__device__ float d_bpin[U_];
__device__ float d_bq1 [U_];
__device__ float d_bq2 [U_];
__device__ float d_bff1[FF_];

// ---------------- prep: fold BN into pin, LN affines into q/ff1 ------------
__global__ void prep_kernel(
    const float* __restrict__ bn_g, const float* __restrict__ bn_b,
    const float* __restrict__ bn_m, const float* __restrict__ bn_v,
    const float* __restrict__ ln1_g, const float* __restrict__ ln1_b,
    const float* __restrict__ ln2_g, const float* __restrict__ ln2_b,
    const float* __restrict__ ln3_g, const float* __restrict__ ln3_b,
    const float* __restrict__ pin_w, const float* __restrict__ pin_b,
    const float* __restrict__ q_w,  const float* __restrict__ q_b,
    const float* __restrict__ ff1_w, const float* __restrict__ ff1_b)
{
    int u = blockIdx.x * blockDim.x + threadIdx.x;   // 0..1023
    if (u < U_) {
        float accP = pin_b[u], accQ1 = q_b[u], accQ2 = q_b[u];
        for (int c = 0; c < C_; c++) {
            float sc = rsqrtf(bn_v[c] + EPS_) * bn_g[c];
            float sh = bn_b[c] - bn_m[c] * sc;
            float pw = pin_w[c*U_ + u];
            d_Wpin[c*U_ + u] = sc * pw;
            accP += sh * pw;
            float qw = q_w[c*U_ + u];
            d_Wq1[c*U_ + u] = ln1_g[c] * qw;  accQ1 += ln1_b[c] * qw;
            d_Wq2[c*U_ + u] = ln2_g[c] * qw;  accQ2 += ln2_b[c] * qw;
        }
        d_bpin[u] = accP; d_bq1[u] = accQ1; d_bq2[u] = accQ2;
    }
    {
        float accF = ff1_b[u];
        for (int c = 0; c < C_; c++) {
            float fw = ff1_w[c*FF_ + u];
            d_Wff1[c*FF_ + u] = ln3_g[c] * fw;
            accF += ln3_b[c] * fw;
        }
        d_bff1[u] = accF;
    }
}

// ---------------- batched GEMM (descriptor table, f32x2 inner) --------------
// Each op: out = op(A[NTOK,K] @ W[K,N] + bias) (+resid). Tiles 32x64, BK=16.
struct GOp {
    const float* A; const float* W; const float* bias; const float* resid;
    float* out; int N; int K; int mode; int tileStart;
};
struct GBatch { GOp op[8]; int nops; };

__global__ void __launch_bounds__(128) gemmB(GBatch P)
{
    __shared__ __align__(16) ull   As2[16][34];  // [k][m] duplicated pairs
    __shared__ __align__(16) float Ws [16][64];
    int bid = blockIdx.x;
    int sel = 0;
    #pragma unroll
    for (int i = 1; i < 8; i++)
        if (i < P.nops && bid >= P.op[i].tileStart) sel = i;
    GOp g = P.op[sel];

    int local = bid - g.tileStart;
    int ntn = g.N >> 6;
    int mt = local / ntn;
    int nt = local - mt * ntn;
    int m0 = mt * 32, n0 = nt * 64;
    int tid = threadIdx.x;
    int ty = tid >> 4;     // 0..7 -> rows ty*4..+3
    int tx = tid & 15;     // cols tx*4..+3

    ull acc2[4][2] = {};

    for (int k0 = 0; k0 < g.K; k0 += 16) {
        {   // A tile 32x16 -> transposed, duplicated pairs
            int m = tid >> 2, kq = tid & 3;
            float4 t = *(const float4*)&g.A[(size_t)(m0 + m) * g.K + k0 + kq*4];
            As2[kq*4+0][m] = pk(t.x, t.x);
            As2[kq*4+1][m] = pk(t.y, t.y);
            As2[kq*4+2][m] = pk(t.z, t.z);
            As2[kq*4+3][m] = pk(t.w, t.w);
        }
        #pragma unroll
        for (int i = 0; i < 2; i++) {   // W tile 16x64
            int v = tid + i * 128;
            int kk = v >> 4, nq = v & 15;
            *(float4*)&Ws[kk][nq*4] =
                *(const float4*)&g.W[(size_t)(k0 + kk) * g.N + n0 + nq*4];
        }
        __syncthreads();
        #pragma unroll
        for (int kk = 0; kk < 16; kk++) {
            ull a0 = As2[kk][ty*4+0], a1 = As2[kk][ty*4+1];
            ull a2 = As2[kk][ty*4+2], a3 = As2[kk][ty*4+3];
            const ull* wr = (const ull*)&Ws[kk][tx*4];
            ull w0 = wr[0], w1 = wr[1];
            acc2[0][0] = fma2(a0, w0, acc2[0][0]); acc2[0][1] = fma2(a0, w1, acc2[0][1]);
            acc2[1][0] = fma2(a1, w0, acc2[1][0]); acc2[1][1] = fma2(a1, w1, acc2[1][1]);
            acc2[2][0] = fma2(a2, w0, acc2[2][0]); acc2[2][1] = fma2(a2, w1, acc2[2][1]);
            acc2[3][0] = fma2(a3, w0, acc2[3][0]); acc2[3][1] = fma2(a3, w1, acc2[3][1]);
        }
        __syncthreads();
    }

    float4 b4 = *(const float4*)&g.bias[n0 + tx*4];
    #pragma unroll
    for (int i = 0; i < 4; i++) {
        int mrow = m0 + ty*4 + i;
        float v0, v1, v2, v3;
        upk(acc2[i][0], v0, v1);
        upk(acc2[i][1], v2, v3);
        float4 r = make_float4(v0 + b4.x, v1 + b4.y, v2 + b4.z, v3 + b4.w);
        if (g.mode >= 1) {
            r.x = fmaxf(r.x, 0.f); r.y = fmaxf(r.y, 0.f);
            r.z = fmaxf(r.z, 0.f); r.w = fmaxf(r.w, 0.f);
        }
        if (g.mode == 2) {
            float4 rr = *(const float4*)&g.resid[(size_t)mrow * g.N + n0 + tx*4];
            r.x += rr.x; r.y += rr.y; r.z += rr.z; r.w += rr.w;
        }
        *(float4*)&g.out[(size_t)mrow * g.N + n0 + tx*4] = r;
    }
}

// ---------------- LayerNorm (normalize only) --------------------------------
__global__ void __launch_bounds__(256) lnorm_kernel(const float* __restrict__ h,
                                                    float* __restrict__ hh)
{
    int row = blockIdx.x;
    int tid = threadIdx.x;
    float v = h[(size_t)row * 256 + tid];
    __shared__ float red[8];
    float s = v;
    #pragma unroll
    for (int o = 16; o > 0; o >>= 1) s += __shfl_xor_sync(0xffffffffu, s, o);
    if ((tid & 31) == 0) red[tid >> 5] = s;
    __syncthreads();
    float tot = 0.f;
    #pragma unroll
    for (int i = 0; i < 8; i++) tot += red[i];
    float mu = tot * (1.f / 256.f);
    float d = v - mu;
    float s2 = d * d;
    #pragma unroll
    for (int o = 16; o > 0; o >>= 1) s2 += __shfl_xor_sync(0xffffffffu, s2, o);
    __syncthreads();
    if ((tid & 31) == 0) red[tid >> 5] = s2;
    __syncthreads();
    float tot2 = 0.f;
    #pragma unroll
    for (int i = 0; i < 8; i++) tot2 += red[i];
    float var = tot2 * (1.f / 256.f);
    hh[(size_t)row * 256 + tid] = d * rsqrtf(var + EPS_);
}

// ---------------- split-K flash attention (both branches, one launch) ------
__global__ void __launch_bounds__(64) attn_split(
    const float* __restrict__ Q1, const float* __restrict__ K1, const float* __restrict__ V1,
    const float* __restrict__ Q2, const float* __restrict__ K2, const float* __restrict__ V2,
    float* __restrict__ Opart, float2* __restrict__ ML)
{
    __shared__ __align__(16) float Ks[32][36];
    __shared__ __align__(16) float Vs[32][36];
    int tid = threadIdx.x;
    int br = blockIdx.z >> 1;
    int b  = blockIdx.z & 1;
    int hh = blockIdx.y / SPLITS;
    int sp = blockIdx.y - hh * SPLITS;
    int q  = blockIdx.x * 64 + tid;
    const float* Q  = br ? Q2 : Q1;
    const float* Kb = br ? K2 : K1;
    const float* Vb = br ? V2 : V1;
    const float scale = 0.0625f;   // UNITS^-0.5

    ull q2[16], O2[16];
    {
        const float* qp = Q + ((size_t)(b * L_) + q) * U_ + hh * HD;
        #pragma unroll
        for (int d = 0; d < 32; d += 4) {
            float4 t = *(const float4*)&qp[d];
            q2[d/2]   = pk(t.x * scale, t.y * scale);
            q2[d/2+1] = pk(t.z * scale, t.w * scale);
        }
    }
    #pragma unroll
    for (int i = 0; i < 16; i++) O2[i] = pk(0.f, 0.f);
    float m = -1e30f, l = 0.f;

    for (int t0 = 0; t0 < KT_PER_SPLIT; t0++) {
        int kt = (sp * KT_PER_SPLIT + t0) * 32;
        #pragma unroll
        for (int i = 0; i < 4; i++) {
            int v = tid + i * 64;
            int j = v >> 3, dq = v & 7;
            size_t go = (size_t)(b * L_ + kt + j) * U_ + hh * HD + dq * 4;
            *(float4*)&Ks[j][dq*4] = *(const float4*)&Kb[go];
            *(float4*)&Vs[j][dq*4] = *(const float4*)&Vb[go];
        }
        __syncthreads();

        float s[32];
        #pragma unroll
        for (int j = 0; j < 32; j++) {
            const ull* kr = (const ull*)&Ks[j][0];
            ull acc = pk(0.f, 0.f);
            #pragma unroll
            for (int d2 = 0; d2 < 16; d2++) acc = fma2(q2[d2], kr[d2], acc);
            float lo, hi; upk(acc, lo, hi);
            s[j] = lo + hi;
        }
        float tmax = m;
        #pragma unroll
        for (int j = 0; j < 32; j++) tmax = fmaxf(tmax, s[j]);
        float corr = __expf(m - tmax);
        l *= corr;
        ull corr2 = pk(corr, corr);
        #pragma unroll
        for (int d2 = 0; d2 < 16; d2++) O2[d2] = mul2(O2[d2], corr2);
        #pragma unroll
        for (int j = 0; j < 32; j++) {
            float p = __expf(s[j] - tmax);
            l += p;
            ull p2 = pk(p, p);
            const ull* vr = (const ull*)&Vs[j][0];
            #pragma unroll
            for (int d2 = 0; d2 < 16; d2++) O2[d2] = fma2(p2, vr[d2], O2[d2]);
        }
        m = tmax;
        __syncthreads();
    }

    size_t obase = ((size_t)(((br*B_ + b)*H_ + hh)*SPLITS + sp)) * L_ + q;
    ull* op = (ull*)(Opart + obase * 32);
    #pragma unroll
    for (int d2 = 0; d2 < 16; d2++) op[d2] = O2[d2];
    ML[obase] = make_float2(m, l);
}

// ---------------- combine splits + sum all branches into acc ----------------
__global__ void __launch_bounds__(256) combine_kernel(
    const float* __restrict__ Opart, const float2* __restrict__ ML,
    const float* __restrict__ h, const float* __restrict__ ffo,
    float* __restrict__ acc)
{
    int tok = blockIdx.x;
    int u = threadIdx.x;
    int b = tok / L_, l = tok - b * L_;
    int hh = u >> 5, d = u & 31;
    float res = 0.f;
    #pragma unroll
    for (int br = 0; br < 2; br++) {
        int base = ((br*B_ + b)*H_ + hh) * SPLITS;
        float2 ml[SPLITS];
        float m = -1e30f;
        #pragma unroll
        for (int sp = 0; sp < SPLITS; sp++) {
            ml[sp] = ML[(size_t)(base + sp) * L_ + l];
            m = fmaxf(m, ml[sp].x);
        }
        float Osum = 0.f, lsum = 0.f;
        #pragma unroll
        for (int sp = 0; sp < SPLITS; sp++) {
            float w = __expf(ml[sp].x - m);
            lsum += w * ml[sp].y;
            Osum += w * Opart[((size_t)(base + sp) * L_ + l) * 32 + d];
        }
        res += Osum / lsum;
    }
    size_t i = (size_t)tok * 256 + u;
    acc[i] = h[i] + ffo[i] + res;
}

// ---------------- launch -----------------------------------------------------
extern "C" void kernel_launch(void* const* d_in, const int* in_sizes, int n_in,
                              void* d_out, int out_size)
{
    const float* x       = (const float*)d_in[0];
    const float* context = (const float*)d_in[1];
    const float* bn_g = (const float*)d_in[2];
    const float* bn_b = (const float*)d_in[3];
    const float* bn_m = (const float*)d_in[4];
    const float* bn_v = (const float*)d_in[5];
    const float* ln1_g = (const float*)d_in[6];
    const float* ln1_b = (const float*)d_in[7];
    const float* ln2_g = (const float*)d_in[8];
    const float* ln2_b = (const float*)d_in[9];
    const float* ln3_g = (const float*)d_in[10];
    const float* ln3_b = (const float*)d_in[11];
    const float* pin_w = (const float*)d_in[12];
    const float* pin_b = (const float*)d_in[13];
    const float* q_w   = (const float*)d_in[14];
    const float* q_b   = (const float*)d_in[15];
    const float* k_w   = (const float*)d_in[16];
    const float* k_b   = (const float*)d_in[17];
    const float* v_w   = (const float*)d_in[18];
    const float* v_b   = (const float*)d_in[19];
    const float* ff1_w = (const float*)d_in[20];
    const float* ff1_b = (const float*)d_in[21];
    const float* ff2_w = (const float*)d_in[22];
    const float* ff2_b = (const float*)d_in[23];
    const float* pout_w = (const float*)d_in[24];
    const float* pout_b = (const float*)d_in[25];
    float* out = (float*)d_out;

    float *p_h, *p_hhat, *p_q1, *p_k1, *p_v1, *p_q2, *p_k2, *p_v2;
    float *p_f1, *p_ffo, *p_acc, *p_Opart;
    float2* p_ML;
    float *p_Wpin, *p_Wq1, *p_Wq2, *p_Wff1, *p_bpin, *p_bq1, *p_bq2, *p_bff1;
    cudaGetSymbolAddress((void**)&p_h,    d_h);
    cudaGetSymbolAddress((void**)&p_hhat, d_hhat);
    cudaGetSymbolAddress((void**)&p_q1,   d_q1);
    cudaGetSymbolAddress((void**)&p_k1,   d_k1);
    cudaGetSymbolAddress((void**)&p_v1,   d_v1);
    cudaGetSymbolAddress((void**)&p_q2,   d_q2);
    cudaGetSymbolAddress((void**)&p_k2,   d_k2);
    cudaGetSymbolAddress((void**)&p_v2,   d_v2);
    cudaGetSymbolAddress((void**)&p_f1,   d_f1);
    cudaGetSymbolAddress((void**)&p_ffo,  d_ffo);
    cudaGetSymbolAddress((void**)&p_acc,  d_acc);
    cudaGetSymbolAddress((void**)&p_Opart,d_Opart);
    cudaGetSymbolAddress((void**)&p_ML,   d_ML);
    cudaGetSymbolAddress((void**)&p_Wpin, d_Wpin);
    cudaGetSymbolAddress((void**)&p_Wq1,  d_Wq1);
    cudaGetSymbolAddress((void**)&p_Wq2,  d_Wq2);
    cudaGetSymbolAddress((void**)&p_Wff1, d_Wff1);
    cudaGetSymbolAddress((void**)&p_bpin, d_bpin);
    cudaGetSymbolAddress((void**)&p_bq1,  d_bq1);
    cudaGetSymbolAddress((void**)&p_bq2,  d_bq2);
    cudaGetSymbolAddress((void**)&p_bff1, d_bff1);

    // 1. fold affine params
    prep_kernel<<<4, 256>>>(bn_g, bn_b, bn_m, bn_v,
                            ln1_g, ln1_b, ln2_g, ln2_b, ln3_g, ln3_b,
                            pin_w, pin_b, q_w, q_b, ff1_w, ff1_b);

    auto mkop = [](const float* A, const float* W, const float* bias,
                   const float* resid, float* o, int N, int K, int mode, int start) {
        GOp g; g.A = A; g.W = W; g.bias = bias; g.resid = resid;
        g.out = o; g.N = N; g.K = K; g.mode = mode; g.tileStart = start;
        return g;
    };
    const int MT = NTOK / 32;   // 108

    // 2. pin: h = relu(x @ Wpin + bpin)
    {
        GBatch P = {};
        P.op[0] = mkop(x, p_Wpin, p_bpin, nullptr, p_h, 256, 256, 1, 0);
        P.nops = 1;
        gemmB<<<MT*4, 128>>>(P);
    }

    // 3. hhat
    lnorm_kernel<<<NTOK, 256>>>(p_h, p_hhat);

    // 4. all projections + ff1 in one launch
    {
        GBatch P = {};
        P.op[0] = mkop(p_hhat,  p_Wq1,  p_bq1,  nullptr, p_q1, 256,  256, 0, 0);
        P.op[1] = mkop(p_h,     k_w,    k_b,    nullptr, p_k1, 256,  256, 0, MT*4);
        P.op[2] = mkop(p_h,     v_w,    v_b,    nullptr, p_v1, 256,  256, 0, MT*8);
        P.op[3] = mkop(p_hhat,  p_Wq2,  p_bq2,  nullptr, p_q2, 256,  256, 0, MT*12);
        P.op[4] = mkop(context, k_w,    k_b,    nullptr, p_k2, 256,  256, 0, MT*16);
        P.op[5] = mkop(context, v_w,    v_b,    nullptr, p_v2, 256,  256, 0, MT*20);
        P.op[6] = mkop(p_hhat,  p_Wff1, p_bff1, nullptr, p_f1, 1024, 256, 1, MT*24);
        P.nops = 7;
        gemmB<<<MT*40, 128>>>(P);   // 24 + 16 tiles-of-64 columns
    }

    // 5. both attentions, split-K
    {
        dim3 ga(L_/64, H_*SPLITS, B_*2);   // (27, 48, 4)
        attn_split<<<ga, 64>>>(p_q1, p_k1, p_v1, p_q2, p_k2, p_v2, p_Opart, p_ML);
    }

    // 6. ff2
    {
        GBatch P = {};
        P.op[0] = mkop(p_f1, ff2_w, ff2_b, nullptr, p_ffo, 256, 1024, 0, 0);
        P.nops = 1;
        gemmB<<<MT*4, 128>>>(P);
    }

    // 7. combine splits + h + ffo -> acc
    combine_kernel<<<NTOK, 256>>>(p_Opart, p_ML, p_h, p_ffo, p_acc);

    // 8. out = relu(acc @ pout_w + pout_b) + x
    {
        GBatch P = {};
        P.op[0] = mkop(p_acc, pout_w, pout_b, x, out, 256, 256, 2, 0);
        P.nops = 1;
        gemmB<<<MT*4, 128>>>(P);
    }
}

// round 3
// speedup vs baseline: 1.1869x; 1.0565x over previous
#include <cuda_runtime.h>
#include <math.h>

typedef unsigned long long ull;

#define B_    2
#define L_    1728
#define NTOK  3456
#define C_    256
#define U_    256
#define H_    8
#define HD    32
#define FF_   1024
#define EPS_  1e-3f
#define SPLITS 6
#define KTILE 16
#define NT_PER_SPLIT 18   /* 18 tiles of 16 keys = 288 keys per split */

// ---------------- packed fp32x2 helpers ------------------------------------
__device__ __forceinline__ ull pk(float lo, float hi) {
    ull r; asm("mov.b64 %0,{%1,%2};" : "=l"(r) : "f"(lo), "f"(hi)); return r;
}
__device__ __forceinline__ void upk(ull v, float& lo, float& hi) {
    asm("mov.b64 {%0,%1},%2;" : "=f"(lo), "=f"(hi) : "l"(v));
}
__device__ __forceinline__ ull fma2(ull a, ull b, ull c) {
    ull d; asm("fma.rn.f32x2 %0,%1,%2,%3;" : "=l"(d) : "l"(a), "l"(b), "l"(c)); return d;
}
__device__ __forceinline__ ull mul2(ull a, ull b) {
    ull d; asm("mul.rn.f32x2 %0,%1,%2;" : "=l"(d) : "l"(a), "l"(b)); return d;
}

// ---------------- scratch ---------------------------------------------------
__device__ float d_h   [NTOK*U_];
__device__ float d_hhat[NTOK*U_];
__device__ float d_q1  [NTOK*U_];
__device__ float d_k1  [NTOK*U_];
__device__ float d_v1  [NTOK*U_];
__device__ float d_q2  [NTOK*U_];
__device__ float d_k2  [NTOK*U_];
__device__ float d_v2  [NTOK*U_];
__device__ float d_f1  [NTOK*FF_];
__device__ float d_ffo [NTOK*U_];
__device__ float d_acc [NTOK*U_];
__device__ float d_Opart[2*B_*H_*SPLITS*L_*32];
__device__ float2 d_ML  [2*B_*H_*SPLITS*L_];

__device__ float d_Wpin[C_*U_];
__device__ float d_Wq1 [U_*U_];
__device__ float d_Wq2 [U_*U_];
__device__ float d_Wff1[U_*FF_];
__device__ float d_bpin[U_];
__device__ float d_bq1 [U_];
__device__ float d_bq2 [U_];
__device__ float d_bff1[FF_];

// ---------------- prep: fold BN into pin, LN affines into q/ff1 ------------
__global__ void prep_kernel(
    const float* __restrict__ bn_g, const float* __restrict__ bn_b,
    const float* __restrict__ bn_m, const float* __restrict__ bn_v,
    const float* __restrict__ ln1_g, const float* __restrict__ ln1_b,
    const float* __restrict__ ln2_g, const float* __restrict__ ln2_b,
    const float* __restrict__ ln3_g, const float* __restrict__ ln3_b,
    const float* __restrict__ pin_w, const float* __restrict__ pin_b,
    const float* __restrict__ q_w,  const float* __restrict__ q_b,
    const float* __restrict__ ff1_w, const float* __restrict__ ff1_b)
{
    int u = blockIdx.x * blockDim.x + threadIdx.x;   // 0..1023
    if (u < U_) {
        float accP = pin_b[u], accQ1 = q_b[u], accQ2 = q_b[u];
        for (int c = 0; c < C_; c++) {
            float sc = rsqrtf(bn_v[c] + EPS_) * bn_g[c];
            float sh = bn_b[c] - bn_m[c] * sc;
            float pw = pin_w[c*U_ + u];
            d_Wpin[c*U_ + u] = sc * pw;
            accP += sh * pw;
            float qw = q_w[c*U_ + u];
            d_Wq1[c*U_ + u] = ln1_g[c] * qw;  accQ1 += ln1_b[c] * qw;
            d_Wq2[c*U_ + u] = ln2_g[c] * qw;  accQ2 += ln2_b[c] * qw;
        }
        d_bpin[u] = accP; d_bq1[u] = accQ1; d_bq2[u] = accQ2;
    }
    {
        float accF = ff1_b[u];
        for (int c = 0; c < C_; c++) {
            float fw = ff1_w[c*FF_ + u];
            d_Wff1[c*FF_ + u] = ln3_g[c] * fw;
            accF += ln3_b[c] * fw;
        }
        d_bff1[u] = accF;
    }
}

// ---------------- batched GEMM: 32x128 tiles, 4x8/thread, f32x2 ------------
struct GOp {
    const float* A; const float* W; const float* bias; const float* resid;
    float* out; int N; int K; int mode; int tileStart;
};
struct GBatch { GOp op[8]; int nops; };

__global__ void __launch_bounds__(128) gemmB(GBatch P)
{
    __shared__ __align__(16) ull   As2[16][34];   // [k][m] duplicated pairs
    __shared__ __align__(16) float Ws [16][128];
    int bid = blockIdx.x;
    int sel = 0;
    #pragma unroll
    for (int i = 1; i < 8; i++)
        if (i < P.nops && bid >= P.op[i].tileStart) sel = i;
    GOp g = P.op[sel];

    int local = bid - g.tileStart;
    int ntn = g.N >> 7;                 // 128-col tiles
    int mt = local / ntn;
    int nt = local - mt * ntn;
    int m0 = mt * 32, n0 = nt * 128;
    int tid = threadIdx.x;
    int ty = tid >> 4;     // 0..7  -> rows ty*4..+3
    int tx = tid & 15;     // cols tx*8..+7

    ull acc2[4][4] = {};   // 4 rows x 8 cols (as 4 ull)

    for (int k0 = 0; k0 < g.K; k0 += 16) {
        {   // A tile 32x16 -> transposed, duplicated pairs
            int m = tid >> 2, kq = tid & 3;
            float4 t = *(const float4*)&g.A[(size_t)(m0 + m) * g.K + k0 + kq*4];
            As2[kq*4+0][m] = pk(t.x, t.x);
            As2[kq*4+1][m] = pk(t.y, t.y);
            As2[kq*4+2][m] = pk(t.z, t.z);
            As2[kq*4+3][m] = pk(t.w, t.w);
        }
        #pragma unroll
        for (int i = 0; i < 4; i++) {   // W tile 16x128 = 512 float4
            int v = tid + i * 128;
            int kk = v >> 5, nq = v & 31;
            *(float4*)&Ws[kk][nq*4] =
                *(const float4*)&g.W[(size_t)(k0 + kk) * g.N + n0 + nq*4];
        }
        __syncthreads();
        #pragma unroll
        for (int kk = 0; kk < 16; kk++) {
            ull a0 = As2[kk][ty*4+0], a1 = As2[kk][ty*4+1];
            ull a2 = As2[kk][ty*4+2], a3 = As2[kk][ty*4+3];
            const ull* wr = (const ull*)&Ws[kk][tx*8];
            ull w0 = wr[0], w1 = wr[1], w2 = wr[2], w3 = wr[3];
            acc2[0][0] = fma2(a0,w0,acc2[0][0]); acc2[0][1] = fma2(a0,w1,acc2[0][1]);
            acc2[0][2] = fma2(a0,w2,acc2[0][2]); acc2[0][3] = fma2(a0,w3,acc2[0][3]);
            acc2[1][0] = fma2(a1,w0,acc2[1][0]); acc2[1][1] = fma2(a1,w1,acc2[1][1]);
            acc2[1][2] = fma2(a1,w2,acc2[1][2]); acc2[1][3] = fma2(a1,w3,acc2[1][3]);
            acc2[2][0] = fma2(a2,w0,acc2[2][0]); acc2[2][1] = fma2(a2,w1,acc2[2][1]);
            acc2[2][2] = fma2(a2,w2,acc2[2][2]); acc2[2][3] = fma2(a2,w3,acc2[2][3]);
            acc2[3][0] = fma2(a3,w0,acc2[3][0]); acc2[3][1] = fma2(a3,w1,acc2[3][1]);
            acc2[3][2] = fma2(a3,w2,acc2[3][2]); acc2[3][3] = fma2(a3,w3,acc2[3][3]);
        }
        __syncthreads();
    }

    float4 b4a = *(const float4*)&g.bias[n0 + tx*8];
    float4 b4b = *(const float4*)&g.bias[n0 + tx*8 + 4];
    float bb[8] = {b4a.x,b4a.y,b4a.z,b4a.w,b4b.x,b4b.y,b4b.z,b4b.w};
    #pragma unroll
    for (int i = 0; i < 4; i++) {
        int mrow = m0 + ty*4 + i;
        float v[8];
        upk(acc2[i][0], v[0], v[1]);
        upk(acc2[i][1], v[2], v[3]);
        upk(acc2[i][2], v[4], v[5]);
        upk(acc2[i][3], v[6], v[7]);
        #pragma unroll
        for (int j = 0; j < 8; j++) {
            v[j] += bb[j];
            if (g.mode >= 1) v[j] = fmaxf(v[j], 0.f);
        }
        if (g.mode == 2) {
            const float* rr = &g.resid[(size_t)mrow * g.N + n0 + tx*8];
            float4 r0 = *(const float4*)&rr[0];
            float4 r1 = *(const float4*)&rr[4];
            v[0]+=r0.x; v[1]+=r0.y; v[2]+=r0.z; v[3]+=r0.w;
            v[4]+=r1.x; v[5]+=r1.y; v[6]+=r1.z; v[7]+=r1.w;
        }
        float* op = &g.out[(size_t)mrow * g.N + n0 + tx*8];
        *(float4*)&op[0] = make_float4(v[0],v[1],v[2],v[3]);
        *(float4*)&op[4] = make_float4(v[4],v[5],v[6],v[7]);
    }
}

// ---------------- LayerNorm (normalize only) --------------------------------
__global__ void __launch_bounds__(256) lnorm_kernel(const float* __restrict__ h,
                                                    float* __restrict__ hh)
{
    int row = blockIdx.x;
    int tid = threadIdx.x;
    float v = h[(size_t)row * 256 + tid];
    __shared__ float red[8];
    float s = v;
    #pragma unroll
    for (int o = 16; o > 0; o >>= 1) s += __shfl_xor_sync(0xffffffffu, s, o);
    if ((tid & 31) == 0) red[tid >> 5] = s;
    __syncthreads();
    float tot = 0.f;
    #pragma unroll
    for (int i = 0; i < 8; i++) tot += red[i];
    float mu = tot * (1.f / 256.f);
    float d = v - mu;
    float s2 = d * d;
    #pragma unroll
    for (int o = 16; o > 0; o >>= 1) s2 += __shfl_xor_sync(0xffffffffu, s2, o);
    __syncthreads();
    if ((tid & 31) == 0) red[tid >> 5] = s2;
    __syncthreads();
    float tot2 = 0.f;
    #pragma unroll
    for (int i = 0; i < 8; i++) tot2 += red[i];
    float var = tot2 * (1.f / 256.f);
    hh[(size_t)row * 256 + tid] = d * rsqrtf(var + EPS_);
}

// ---------------- split-K flash attention: 1 warp, 2 queries/thread --------
__global__ void __launch_bounds__(32) attn_split(
    const float* __restrict__ Q1, const float* __restrict__ K1, const float* __restrict__ V1,
    const float* __restrict__ Q2, const float* __restrict__ K2, const float* __restrict__ V2,
    float* __restrict__ Opart, float2* __restrict__ ML)
{
    __shared__ __align__(16) float Ks[KTILE][36];
    __shared__ __align__(16) float Vs[KTILE][36];
    int tid = threadIdx.x;                 // 0..31
    int br = blockIdx.z >> 1;
    int b  = blockIdx.z & 1;
    int hh = blockIdx.y / SPLITS;
    int sp = blockIdx.y - hh * SPLITS;
    int qa_row = blockIdx.x * 64 + tid;    // query A
    int qb_row = qa_row + 32;              // query B
    const float* Q  = br ? Q2 : Q1;
    const float* Kb = br ? K2 : K1;
    const float* Vb = br ? V2 : V1;
    const float scale = 0.0625f;           // UNITS^-0.5

    ull qa[16], qb[16], Oa[16], Ob[16];
    {
        const float* pa = Q + ((size_t)(b * L_) + qa_row) * U_ + hh * HD;
        const float* pb = Q + ((size_t)(b * L_) + qb_row) * U_ + hh * HD;
        #pragma unroll
        for (int d = 0; d < 32; d += 4) {
            float4 ta = *(const float4*)&pa[d];
            float4 tb = *(const float4*)&pb[d];
            qa[d/2]   = pk(ta.x*scale, ta.y*scale);
            qa[d/2+1] = pk(ta.z*scale, ta.w*scale);
            qb[d/2]   = pk(tb.x*scale, tb.y*scale);
            qb[d/2+1] = pk(tb.z*scale, tb.w*scale);
        }
    }
    #pragma unroll
    for (int i = 0; i < 16; i++) { Oa[i] = 0ull; Ob[i] = 0ull; }
    float ma = -1e30f, la = 0.f, mb = -1e30f, lb = 0.f;

    for (int t0 = 0; t0 < NT_PER_SPLIT; t0++) {
        int kt = (sp * NT_PER_SPLIT + t0) * KTILE;
        #pragma unroll
        for (int i = 0; i < 4; i++) {      // 16x32 K + V: 128 f4 each, 4/thread
            int v = tid + i * 32;
            int j = v >> 3, dq = v & 7;
            size_t go = (size_t)(b * L_ + kt + j) * U_ + hh * HD + dq * 4;
            *(float4*)&Ks[j][dq*4] = *(const float4*)&Kb[go];
            *(float4*)&Vs[j][dq*4] = *(const float4*)&Vb[go];
        }
        __syncwarp();

        float sa[KTILE], sb[KTILE];
        #pragma unroll
        for (int j = 0; j < KTILE; j++) {
            const ull* kr = (const ull*)&Ks[j][0];
            ull aa = 0ull, ab = 0ull;
            #pragma unroll
            for (int d2 = 0; d2 < 16; d2++) {
                ull k2 = kr[d2];
                aa = fma2(qa[d2], k2, aa);
                ab = fma2(qb[d2], k2, ab);
            }
            float lo, hi;
            upk(aa, lo, hi); sa[j] = lo + hi;
            upk(ab, lo, hi); sb[j] = lo + hi;
        }
        float tma = ma, tmb = mb;
        #pragma unroll
        for (int j = 0; j < KTILE; j++) {
            tma = fmaxf(tma, sa[j]);
            tmb = fmaxf(tmb, sb[j]);
        }
        float ca = __expf(ma - tma), cb = __expf(mb - tmb);
        la *= ca; lb *= cb;
        ull ca2 = pk(ca, ca), cb2 = pk(cb, cb);
        #pragma unroll
        for (int d2 = 0; d2 < 16; d2++) {
            Oa[d2] = mul2(Oa[d2], ca2);
            Ob[d2] = mul2(Ob[d2], cb2);
        }
        #pragma unroll
        for (int j = 0; j < KTILE; j++) {
            float pa = __expf(sa[j] - tma);
            float pb = __expf(sb[j] - tmb);
            la += pa; lb += pb;
            ull pa2 = pk(pa, pa), pb2 = pk(pb, pb);
            const ull* vr = (const ull*)&Vs[j][0];
            #pragma unroll
            for (int d2 = 0; d2 < 16; d2++) {
                ull v2 = vr[d2];
                Oa[d2] = fma2(pa2, v2, Oa[d2]);
                Ob[d2] = fma2(pb2, v2, Ob[d2]);
            }
        }
        ma = tma; mb = tmb;
        __syncwarp();
    }

    size_t hb = ((size_t)(((br*B_ + b)*H_ + hh)*SPLITS + sp)) * L_;
    {
        size_t oa = hb + qa_row;
        ull* op = (ull*)(Opart + oa * 32);
        #pragma unroll
        for (int d2 = 0; d2 < 16; d2++) op[d2] = Oa[d2];
        ML[oa] = make_float2(ma, la);
    }
    {
        size_t ob = hb + qb_row;
        ull* op = (ull*)(Opart + ob * 32);
        #pragma unroll
        for (int d2 = 0; d2 < 16; d2++) op[d2] = Ob[d2];
        ML[ob] = make_float2(mb, lb);
    }
}

// ---------------- combine splits + sum all branches into acc ----------------
__global__ void __launch_bounds__(256) combine_kernel(
    const float* __restrict__ Opart, const float2* __restrict__ ML,
    const float* __restrict__ h, const float* __restrict__ ffo,
    float* __restrict__ acc)
{
    int tok = blockIdx.x;
    int u = threadIdx.x;
    int b = tok / L_, l = tok - b * L_;
    int hh = u >> 5, d = u & 31;
    float res = 0.f;
    #pragma unroll
    for (int br = 0; br < 2; br++) {
        int base = ((br*B_ + b)*H_ + hh) * SPLITS;
        float2 ml[SPLITS];
        float m = -1e30f;
        #pragma unroll
        for (int sp = 0; sp < SPLITS; sp++) {
            ml[sp] = ML[(size_t)(base + sp) * L_ + l];
            m = fmaxf(m, ml[sp].x);
        }
        float Osum = 0.f, lsum = 0.f;
        #pragma unroll
        for (int sp = 0; sp < SPLITS; sp++) {
            float w = __expf(ml[sp].x - m);
            lsum += w * ml[sp].y;
            Osum += w * Opart[((size_t)(base + sp) * L_ + l) * 32 + d];
        }
        res += Osum / lsum;
    }
    size_t i = (size_t)tok * 256 + u;
    acc[i] = h[i] + ffo[i] + res;
}

// ---------------- launch -----------------------------------------------------
extern "C" void kernel_launch(void* const* d_in, const int* in_sizes, int n_in,
                              void* d_out, int out_size)
{
    const float* x       = (const float*)d_in[0];
    const float* context = (const float*)d_in[1];
    const float* bn_g = (const float*)d_in[2];
    const float* bn_b = (const float*)d_in[3];
    const float* bn_m = (const float*)d_in[4];
    const float* bn_v = (const float*)d_in[5];
    const float* ln1_g = (const float*)d_in[6];
    const float* ln1_b = (const float*)d_in[7];
    const float* ln2_g = (const float*)d_in[8];
    const float* ln2_b = (const float*)d_in[9];
    const float* ln3_g = (const float*)d_in[10];
    const float* ln3_b = (const float*)d_in[11];
    const float* pin_w = (const float*)d_in[12];
    const float* pin_b = (const float*)d_in[13];
    const float* q_w   = (const float*)d_in[14];
    const float* q_b   = (const float*)d_in[15];
    const float* k_w   = (const float*)d_in[16];
    const float* k_b   = (const float*)d_in[17];
    const float* v_w   = (const float*)d_in[18];
    const float* v_b   = (const float*)d_in[19];
    const float* ff1_w = (const float*)d_in[20];
    const float* ff1_b = (const float*)d_in[21];
    const float* ff2_w = (const float*)d_in[22];
    const float* ff2_b = (const float*)d_in[23];
    const float* pout_w = (const float*)d_in[24];
    const float* pout_b = (const float*)d_in[25];
    float* out = (float*)d_out;

    float *p_h, *p_hhat, *p_q1, *p_k1, *p_v1, *p_q2, *p_k2, *p_v2;
    float *p_f1, *p_ffo, *p_acc, *p_Opart;
    float2* p_ML;
    float *p_Wpin, *p_Wq1, *p_Wq2, *p_Wff1, *p_bpin, *p_bq1, *p_bq2, *p_bff1;
    cudaGetSymbolAddress((void**)&p_h,    d_h);
    cudaGetSymbolAddress((void**)&p_hhat, d_hhat);
    cudaGetSymbolAddress((void**)&p_q1,   d_q1);
    cudaGetSymbolAddress((void**)&p_k1,   d_k1);
    cudaGetSymbolAddress((void**)&p_v1,   d_v1);
    cudaGetSymbolAddress((void**)&p_q2,   d_q2);
    cudaGetSymbolAddress((void**)&p_k2,   d_k2);
    cudaGetSymbolAddress((void**)&p_v2,   d_v2);
    cudaGetSymbolAddress((void**)&p_f1,   d_f1);
    cudaGetSymbolAddress((void**)&p_ffo,  d_ffo);
    cudaGetSymbolAddress((void**)&p_acc,  d_acc);
    cudaGetSymbolAddress((void**)&p_Opart,d_Opart);
    cudaGetSymbolAddress((void**)&p_ML,   d_ML);
    cudaGetSymbolAddress((void**)&p_Wpin, d_Wpin);
    cudaGetSymbolAddress((void**)&p_Wq1,  d_Wq1);
    cudaGetSymbolAddress((void**)&p_Wq2,  d_Wq2);
    cudaGetSymbolAddress((void**)&p_Wff1, d_Wff1);
    cudaGetSymbolAddress((void**)&p_bpin, d_bpin);
    cudaGetSymbolAddress((void**)&p_bq1,  d_bq1);
    cudaGetSymbolAddress((void**)&p_bq2,  d_bq2);
    cudaGetSymbolAddress((void**)&p_bff1, d_bff1);

    // 1. fold affine params
    prep_kernel<<<4, 256>>>(bn_g, bn_b, bn_m, bn_v,
                            ln1_g, ln1_b, ln2_g, ln2_b, ln3_g, ln3_b,
                            pin_w, pin_b, q_w, q_b, ff1_w, ff1_b);

    auto mkop = [](const float* A, const float* W, const float* bias,
                   const float* resid, float* o, int N, int K, int mode, int start) {
        GOp g; g.A = A; g.W = W; g.bias = bias; g.resid = resid;
        g.out = o; g.N = N; g.K = K; g.mode = mode; g.tileStart = start;
        return g;
    };
    const int MT = NTOK / 32;   // 108 row tiles; 256 cols -> 2 tiles, 1024 -> 8

    // 2. pin: h = relu(x @ Wpin + bpin)
    {
        GBatch P = {};
        P.op[0] = mkop(x, p_Wpin, p_bpin, nullptr, p_h, 256, 256, 1, 0);
        P.nops = 1;
        gemmB<<<MT*2, 128>>>(P);
    }

    // 3. hhat
    lnorm_kernel<<<NTOK, 256>>>(p_h, p_hhat);

    // 4. all projections + ff1 in one launch
    {
        GBatch P = {};
        P.op[0] = mkop(p_hhat,  p_Wq1,  p_bq1,  nullptr, p_q1, 256,  256, 0, 0);
        P.op[1] = mkop(p_h,     k_w,    k_b,    nullptr, p_k1, 256,  256, 0, MT*2);
        P.op[2] = mkop(p_h,     v_w,    v_b,    nullptr, p_v1, 256,  256, 0, MT*4);
        P.op[3] = mkop(p_hhat,  p_Wq2,  p_bq2,  nullptr, p_q2, 256,  256, 0, MT*6);
        P.op[4] = mkop(context, k_w,    k_b,    nullptr, p_k2, 256,  256, 0, MT*8);
        P.op[5] = mkop(context, v_w,    v_b,    nullptr, p_v2, 256,  256, 0, MT*10);
        P.op[6] = mkop(p_hhat,  p_Wff1, p_bff1, nullptr, p_f1, 1024, 256, 1, MT*12);
        P.nops = 7;
        gemmB<<<MT*20, 128>>>(P);   // 12 + 8 col-tiles of 128
    }

    // 5. both attentions, split-K, 2 queries/thread
    {
        dim3 ga(L_/64, H_*SPLITS, B_*2);   // (27, 48, 4)
        attn_split<<<ga, 32>>>(p_q1, p_k1, p_v1, p_q2, p_k2, p_v2, p_Opart, p_ML);
    }

    // 6. ff2
    {
        GBatch P = {};
        P.op[0] = mkop(p_f1, ff2_w, ff2_b, nullptr, p_ffo, 256, 1024, 0, 0);
        P.nops = 1;
        gemmB<<<MT*2, 128>>>(P);
    }

    // 7. combine splits + h + ffo -> acc
    combine_kernel<<<NTOK, 256>>>(p_Opart, p_ML, p_h, p_ffo, p_acc);

    // 8. out = relu(acc @ pout_w + pout_b) + x
    {
        GBatch P = {};
        P.op[0] = mkop(p_acc, pout_w, pout_b, x, out, 256, 256, 2, 0);
        P.nops = 1;
        gemmB<<<MT*2, 128>>>(P);
    }
}

// round 4
// speedup vs baseline: 1.4467x; 1.2189x over previous
#include <cuda_runtime.h>
#include <math.h>

typedef unsigned long long ull;
typedef unsigned int uint;

#define B_    2
#define L_    1728
#define NTOK  3456
#define C_    256
#define U_    256
#define H_    8
#define HD    32
#define FF_   1024
#define EPS_  1e-3f
#define SPLITS 6
#define KTILE 16
#define NT_PER_SPLIT 18

#define FRELU   1
#define FRESID  2
#define FPLANES 4

// ---------------- packed fp32x2 helpers (attention) -------------------------
__device__ __forceinline__ ull pk(float lo, float hi) {
    ull r; asm("mov.b64 %0,{%1,%2};" : "=l"(r) : "f"(lo), "f"(hi)); return r;
}
__device__ __forceinline__ void upk(ull v, float& lo, float& hi) {
    asm("mov.b64 {%0,%1},%2;" : "=f"(lo), "=f"(hi) : "l"(v));
}
__device__ __forceinline__ ull fma2(ull a, ull b, ull c) {
    ull d; asm("fma.rn.f32x2 %0,%1,%2,%3;" : "=l"(d) : "l"(a), "l"(b), "l"(c)); return d;
}
__device__ __forceinline__ ull mul2(ull a, ull b) {
    ull d; asm("mul.rn.f32x2 %0,%1,%2;" : "=l"(d) : "l"(a), "l"(b)); return d;
}

// ---------------- bf16 split helpers (explicit pack: LOW half = even elem) --
__device__ __forceinline__ uint bf16_of(float f) {
    unsigned short u; asm("cvt.rn.bf16.f32 %0,%1;" : "=h"(u) : "f"(f));
    return (uint)u;
}
__device__ __forceinline__ void split_pair(float f0, float f1, uint& hi, uint& lo) {
    uint h0 = bf16_of(f0), h1 = bf16_of(f1);
    hi = h0 | (h1 << 16);
    float r0 = f0 - __uint_as_float(h0 << 16);
    float r1 = f1 - __uint_as_float(h1 << 16);
    lo = bf16_of(r0) | (bf16_of(r1) << 16);
}

// ---------------- mma m16n8k16 bf16 -----------------------------------------
__device__ __forceinline__ void mma_bf16(float* c, uint a0, uint a1, uint a2, uint a3,
                                         uint b0, uint b1) {
    asm volatile("mma.sync.aligned.m16n8k16.row.col.f32.bf16.bf16.f32 "
                 "{%0,%1,%2,%3},{%4,%5,%6,%7},{%8,%9},{%0,%1,%2,%3};"
                 : "+f"(c[0]), "+f"(c[1]), "+f"(c[2]), "+f"(c[3])
                 : "r"(a0), "r"(a1), "r"(a2), "r"(a3), "r"(b0), "r"(b1));
}

// ---------------- scratch ---------------------------------------------------
__device__ float d_h   [NTOK*U_];
__device__ float d_hhat[NTOK*U_];
__device__ float d_q1  [NTOK*U_];
__device__ float d_k1  [NTOK*U_];
__device__ float d_v1  [NTOK*U_];
__device__ float d_q2  [NTOK*U_];
__device__ float d_k2  [NTOK*U_];
__device__ float d_v2  [NTOK*U_];
__device__ float d_f1  [NTOK*FF_];
__device__ float d_ffo [NTOK*U_];
__device__ float d_acc [NTOK*U_];
__device__ float d_Opart[2*B_*H_*SPLITS*L_*32];
__device__ float2 d_ML  [2*B_*H_*SPLITS*L_];

// activation planes ([M][K/2] packed bf16 pairs)
__device__ uint d_xhi [NTOK*128], d_xlo [NTOK*128];
__device__ uint d_cthi[NTOK*128], d_ctlo[NTOK*128];
__device__ uint d_hhi [NTOK*128], d_hlo [NTOK*128];
__device__ uint d_nhi [NTOK*128], d_nlo [NTOK*128];
__device__ uint d_f1hi[NTOK*512], d_f1lo[NTOK*512];
__device__ uint d_ahi [NTOK*128], d_alo [NTOK*128];

// weight planes (transposed: [N][K/2])
__device__ uint d_Wpin_h[256*128], d_Wpin_l[256*128];
__device__ uint d_Wq1_h [256*128], d_Wq1_l [256*128];
__device__ uint d_Wq2_h [256*128], d_Wq2_l [256*128];
__device__ uint d_Wk_h  [256*128], d_Wk_l  [256*128];
__device__ uint d_Wv_h  [256*128], d_Wv_l  [256*128];
__device__ uint d_Wpout_h[256*128], d_Wpout_l[256*128];
__device__ uint d_Wff1_h[1024*128], d_Wff1_l[1024*128];
__device__ uint d_Wff2_h[256*512],  d_Wff2_l[256*512];

__device__ float d_bpin[U_], d_bq1[U_], d_bq2[U_], d_bff1[FF_];

// ---------------- prep: fold affines, build transposed bf16 planes ----------
__global__ void prep_kernel(
    const float* __restrict__ bn_g, const float* __restrict__ bn_b,
    const float* __restrict__ bn_m, const float* __restrict__ bn_v,
    const float* __restrict__ ln1_g, const float* __restrict__ ln1_b,
    const float* __restrict__ ln2_g, const float* __restrict__ ln2_b,
    const float* __restrict__ ln3_g, const float* __restrict__ ln3_b,
    const float* __restrict__ pin_w, const float* __restrict__ pin_b,
    const float* __restrict__ q_w,  const float* __restrict__ q_b,
    const float* __restrict__ k_w,  const float* __restrict__ v_w,
    const float* __restrict__ ff1_w, const float* __restrict__ ff1_b,
    const float* __restrict__ ff2_w, const float* __restrict__ pout_w)
{
    int idx = blockIdx.x * blockDim.x + threadIdx.x;
    if (idx < 256) {                       // pin (fold bn)
        int u = idx; float accP = pin_b[u];
        for (int k2 = 0; k2 < 128; k2++) {
            float w[2];
            #pragma unroll
            for (int e = 0; e < 2; e++) {
                int k = 2*k2 + e;
                float sc = rsqrtf(bn_v[k] + EPS_) * bn_g[k];
                float sh = bn_b[k] - bn_m[k] * sc;
                float pw = pin_w[k*256 + u];
                w[e] = sc * pw;
                accP += sh * pw;
            }
            uint hi, lo; split_pair(w[0], w[1], hi, lo);
            d_Wpin_h[u*128 + k2] = hi; d_Wpin_l[u*128 + k2] = lo;
        }
        d_bpin[u] = accP;
    } else if (idx < 512) {                // q1 (fold ln1)
        int u = idx - 256; float acc = q_b[u];
        for (int k2 = 0; k2 < 128; k2++) {
            float w[2];
            #pragma unroll
            for (int e = 0; e < 2; e++) {
                int k = 2*k2 + e;
                float qw = q_w[k*256 + u];
                w[e] = ln1_g[k] * qw;
                acc += ln1_b[k] * qw;
            }
            uint hi, lo; split_pair(w[0], w[1], hi, lo);
            d_Wq1_h[u*128 + k2] = hi; d_Wq1_l[u*128 + k2] = lo;
        }
        d_bq1[u] = acc;
    } else if (idx < 768) {                // q2 (fold ln2)
        int u = idx - 512; float acc = q_b[u];
        for (int k2 = 0; k2 < 128; k2++) {
            float w[2];
            #pragma unroll
            for (int e = 0; e < 2; e++) {
                int k = 2*k2 + e;
                float qw = q_w[k*256 + u];
                w[e] = ln2_g[k] * qw;
                acc += ln2_b[k] * qw;
            }
            uint hi, lo; split_pair(w[0], w[1], hi, lo);
            d_Wq2_h[u*128 + k2] = hi; d_Wq2_l[u*128 + k2] = lo;
        }
        d_bq2[u] = acc;
    } else if (idx < 1024) {               // k
        int u = idx - 768;
        for (int k2 = 0; k2 < 128; k2++) {
            uint hi, lo;
            split_pair(k_w[(2*k2)*256 + u], k_w[(2*k2+1)*256 + u], hi, lo);
            d_Wk_h[u*128 + k2] = hi; d_Wk_l[u*128 + k2] = lo;
        }
    } else if (idx < 1280) {               // v
        int u = idx - 1024;
        for (int k2 = 0; k2 < 128; k2++) {
            uint hi, lo;
            split_pair(v_w[(2*k2)*256 + u], v_w[(2*k2+1)*256 + u], hi, lo);
            d_Wv_h[u*128 + k2] = hi; d_Wv_l[u*128 + k2] = lo;
        }
    } else if (idx < 1536) {               // pout
        int u = idx - 1280;
        for (int k2 = 0; k2 < 128; k2++) {
            uint hi, lo;
            split_pair(pout_w[(2*k2)*256 + u], pout_w[(2*k2+1)*256 + u], hi, lo);
            d_Wpout_h[u*128 + k2] = hi; d_Wpout_l[u*128 + k2] = lo;
        }
    } else if (idx < 1792) {               // ff2 (K=1024)
        int u = idx - 1536;
        for (int k2 = 0; k2 < 512; k2++) {
            uint hi, lo;
            split_pair(ff2_w[(2*k2)*256 + u], ff2_w[(2*k2+1)*256 + u], hi, lo);
            d_Wff2_h[u*512 + k2] = hi; d_Wff2_l[u*512 + k2] = lo;
        }
    } else if (idx < 2816) {               // ff1 (fold ln3), N=1024
        int u = idx - 1792; float acc = ff1_b[u];
        for (int k2 = 0; k2 < 128; k2++) {
            float w[2];
            #pragma unroll
            for (int e = 0; e < 2; e++) {
                int k = 2*k2 + e;
                float fw = ff1_w[k*1024 + u];
                w[e] = ln3_g[k] * fw;
                acc += ln3_b[k] * fw;
            }
            uint hi, lo; split_pair(w[0], w[1], hi, lo);
            d_Wff1_h[u*128 + k2] = hi; d_Wff1_l[u*128 + k2] = lo;
        }
        d_bff1[u] = acc;
    }
}

// ---------------- convert activation tensor to planes ----------------------
__global__ void cvt_planes(const float* __restrict__ a, uint* __restrict__ hi,
                           uint* __restrict__ lo, int nwords)
{
    int i = blockIdx.x * blockDim.x + threadIdx.x;
    if (i < nwords) {
        float2 f = ((const float2*)a)[i];
        uint h, l; split_pair(f.x, f.y, h, l);
        hi[i] = h; lo[i] = l;
    }
}

// ---------------- tensor-core batched GEMM (bf16x3) -------------------------
struct GOp {
    const uint* Ahi; const uint* Alo;     // [M][K/2]
    const uint* Whi; const uint* Wlo;     // [N][K/2]
    const float* bias; const float* resid;
    float* out; uint* Ohi; uint* Olo;
    int N; int K; int flags; int tileStart;
};
struct GBatch { GOp op[8]; int nops; };

__global__ void __launch_bounds__(128) gemmT(GBatch P)
{
    __shared__ uint As_hi[64][12], As_lo[64][12];
    __shared__ uint Ws_hi[64][12], Ws_lo[64][12];

    int bid = blockIdx.x;
    int sel = 0;
    #pragma unroll
    for (int i = 1; i < 8; i++)
        if (i < P.nops && bid >= P.op[i].tileStart) sel = i;
    GOp g = P.op[sel];

    int local = bid - g.tileStart;
    int ntn = g.N >> 6;
    int mt = local / ntn;
    int nt = local - mt * ntn;
    int m0 = mt * 64, n0 = nt * 64;
    int tid = threadIdx.x;
    int warp = tid >> 5, lane = tid & 31;
    int gq = lane >> 2, t = lane & 3;
    int K2 = g.K >> 1;

    float acc[8][4];
    #pragma unroll
    for (int j = 0; j < 8; j++)
        #pragma unroll
        for (int i = 0; i < 4; i++) acc[j][i] = 0.f;

    int frow = tid >> 1;            // fill row 0..63
    int fhf  = (tid & 1) * 4;       // word offset 0 or 4

    for (int k16 = 0; k16 < g.K; k16 += 16) {
        int k2o = k16 >> 1;
        {
            const uint4 ah = *(const uint4*)&g.Ahi[(size_t)(m0+frow)*K2 + k2o + fhf];
            const uint4 al = *(const uint4*)&g.Alo[(size_t)(m0+frow)*K2 + k2o + fhf];
            const uint4 wh = *(const uint4*)&g.Whi[(size_t)(n0+frow)*K2 + k2o + fhf];
            const uint4 wl = *(const uint4*)&g.Wlo[(size_t)(n0+frow)*K2 + k2o + fhf];
            *(uint4*)&As_hi[frow][fhf] = ah;
            *(uint4*)&As_lo[frow][fhf] = al;
            *(uint4*)&Ws_hi[frow][fhf] = wh;
            *(uint4*)&Ws_lo[frow][fhf] = wl;
        }
        __syncthreads();

        int rs = warp * 16;
        uint a0h = As_hi[rs+gq  ][t  ], a1h = As_hi[rs+gq+8][t  ];
        uint a2h = As_hi[rs+gq  ][t+4], a3h = As_hi[rs+gq+8][t+4];
        uint a0l = As_lo[rs+gq  ][t  ], a1l = As_lo[rs+gq+8][t  ];
        uint a2l = As_lo[rs+gq  ][t+4], a3l = As_lo[rs+gq+8][t+4];

        #pragma unroll
        for (int j = 0; j < 8; j++) {
            int n = j*8 + gq;
            uint b0h = Ws_hi[n][t], b1h = Ws_hi[n][t+4];
            uint b0l = Ws_lo[n][t], b1l = Ws_lo[n][t+4];
            mma_bf16(acc[j], a0h, a1h, a2h, a3h, b0h, b1h);
            mma_bf16(acc[j], a0h, a1h, a2h, a3h, b0l, b1l);
            mma_bf16(acc[j], a0l, a1l, a2l, a3l, b0h, b1h);
        }
        __syncthreads();
    }

    // epilogue
    int K2o = g.N >> 1;
    int r0 = m0 + warp*16 + gq;
    int r1 = r0 + 8;
    #pragma unroll
    for (int j = 0; j < 8; j++) {
        int c0 = n0 + j*8 + 2*t;
        float b0 = g.bias[c0], b1 = g.bias[c0+1];
        float v00 = acc[j][0] + b0, v01 = acc[j][1] + b1;
        float v10 = acc[j][2] + b0, v11 = acc[j][3] + b1;
        if (g.flags & FRELU) {
            v00 = fmaxf(v00, 0.f); v01 = fmaxf(v01, 0.f);
            v10 = fmaxf(v10, 0.f); v11 = fmaxf(v11, 0.f);
        }
        if (g.flags & FRESID) {
            float2 ra = *(const float2*)&g.resid[(size_t)r0*g.N + c0];
            float2 rb = *(const float2*)&g.resid[(size_t)r1*g.N + c0];
            v00 += ra.x; v01 += ra.y; v10 += rb.x; v11 += rb.y;
        }
        *(float2*)&g.out[(size_t)r0*g.N + c0] = make_float2(v00, v01);
        *(float2*)&g.out[(size_t)r1*g.N + c0] = make_float2(v10, v11);
        if (g.flags & FPLANES) {
            uint h, l;
            split_pair(v00, v01, h, l);
            g.Ohi[(size_t)r0*K2o + (c0>>1)] = h; g.Olo[(size_t)r0*K2o + (c0>>1)] = l;
            split_pair(v10, v11, h, l);
            g.Ohi[(size_t)r1*K2o + (c0>>1)] = h; g.Olo[(size_t)r1*K2o + (c0>>1)] = l;
        }
    }
}

// ---------------- LayerNorm (normalize only) + planes -----------------------
__global__ void __launch_bounds__(256) lnorm_kernel(const float* __restrict__ h,
                                                    float* __restrict__ hh,
                                                    uint* __restrict__ nhi,
                                                    uint* __restrict__ nlo)
{
    int row = blockIdx.x;
    int tid = threadIdx.x;
    float v = h[(size_t)row * 256 + tid];
    __shared__ float red[8];
    float s = v;
    #pragma unroll
    for (int o = 16; o > 0; o >>= 1) s += __shfl_xor_sync(0xffffffffu, s, o);
    if ((tid & 31) == 0) red[tid >> 5] = s;
    __syncthreads();
    float tot = 0.f;
    #pragma unroll
    for (int i = 0; i < 8; i++) tot += red[i];
    float mu = tot * (1.f / 256.f);
    float d = v - mu;
    float s2 = d * d;
    #pragma unroll
    for (int o = 16; o > 0; o >>= 1) s2 += __shfl_xor_sync(0xffffffffu, s2, o);
    __syncthreads();
    if ((tid & 31) == 0) red[tid >> 5] = s2;
    __syncthreads();
    float tot2 = 0.f;
    #pragma unroll
    for (int i = 0; i < 8; i++) tot2 += red[i];
    float var = tot2 * (1.f / 256.f);
    float o = d * rsqrtf(var + EPS_);
    hh[(size_t)row * 256 + tid] = o;
    float pn = __shfl_xor_sync(0xffffffffu, o, 1);
    if (!(tid & 1)) {
        uint hi, lo; split_pair(o, pn, hi, lo);
        nhi[(size_t)row * 128 + (tid >> 1)] = hi;
        nlo[(size_t)row * 128 + (tid >> 1)] = lo;
    }
}

// ---------------- split-K flash attention: 1 warp, 2 queries/thread --------
__global__ void __launch_bounds__(32) attn_split(
    const float* __restrict__ Q1, const float* __restrict__ K1, const float* __restrict__ V1,
    const float* __restrict__ Q2, const float* __restrict__ K2, const float* __restrict__ V2,
    float* __restrict__ Opart, float2* __restrict__ ML)
{
    __shared__ __align__(16) float Ks[KTILE][36];
    __shared__ __align__(16) float Vs[KTILE][36];
    int tid = threadIdx.x;
    int br = blockIdx.z >> 1;
    int b  = blockIdx.z & 1;
    int hh = blockIdx.y / SPLITS;
    int sp = blockIdx.y - hh * SPLITS;
    int qa_row = blockIdx.x * 64 + tid;
    int qb_row = qa_row + 32;
    const float* Q  = br ? Q2 : Q1;
    const float* Kb = br ? K2 : K1;
    const float* Vb = br ? V2 : V1;
    const float scale = 0.0625f;

    ull qa[16], qb[16], Oa[16], Ob[16];
    {
        const float* pa = Q + ((size_t)(b * L_) + qa_row) * U_ + hh * HD;
        const float* pb = Q + ((size_t)(b * L_) + qb_row) * U_ + hh * HD;
        #pragma unroll
        for (int d = 0; d < 32; d += 4) {
            float4 ta = *(const float4*)&pa[d];
            float4 tb = *(const float4*)&pb[d];
            qa[d/2]   = pk(ta.x*scale, ta.y*scale);
            qa[d/2+1] = pk(ta.z*scale, ta.w*scale);
            qb[d/2]   = pk(tb.x*scale, tb.y*scale);
            qb[d/2+1] = pk(tb.z*scale, tb.w*scale);
        }
    }
    #pragma unroll
    for (int i = 0; i < 16; i++) { Oa[i] = 0ull; Ob[i] = 0ull; }
    float ma = -1e30f, la = 0.f, mb = -1e30f, lb = 0.f;

    for (int t0 = 0; t0 < NT_PER_SPLIT; t0++) {
        int kt = (sp * NT_PER_SPLIT + t0) * KTILE;
        #pragma unroll
        for (int i = 0; i < 4; i++) {
            int v = tid + i * 32;
            int j = v >> 3, dq = v & 7;
            size_t go = (size_t)(b * L_ + kt + j) * U_ + hh * HD + dq * 4;
            *(float4*)&Ks[j][dq*4] = *(const float4*)&Kb[go];
            *(float4*)&Vs[j][dq*4] = *(const float4*)&Vb[go];
        }
        __syncwarp();

        float sa[KTILE], sb[KTILE];
        #pragma unroll
        for (int j = 0; j < KTILE; j++) {
            const ull* kr = (const ull*)&Ks[j][0];
            ull aa = 0ull, ab = 0ull;
            #pragma unroll
            for (int d2 = 0; d2 < 16; d2++) {
                ull k2 = kr[d2];
                aa = fma2(qa[d2], k2, aa);
                ab = fma2(qb[d2], k2, ab);
            }
            float lo, hi;
            upk(aa, lo, hi); sa[j] = lo + hi;
            upk(ab, lo, hi); sb[j] = lo + hi;
        }
        float tma = ma, tmb = mb;
        #pragma unroll
        for (int j = 0; j < KTILE; j++) {
            tma = fmaxf(tma, sa[j]);
            tmb = fmaxf(tmb, sb[j]);
        }
        float ca = __expf(ma - tma), cb = __expf(mb - tmb);
        la *= ca; lb *= cb;
        ull ca2 = pk(ca, ca), cb2 = pk(cb, cb);
        #pragma unroll
        for (int d2 = 0; d2 < 16; d2++) {
            Oa[d2] = mul2(Oa[d2], ca2);
            Ob[d2] = mul2(Ob[d2], cb2);
        }
        #pragma unroll
        for (int j = 0; j < KTILE; j++) {
            float pa = __expf(sa[j] - tma);
            float pb = __expf(sb[j] - tmb);
            la += pa; lb += pb;
            ull pa2 = pk(pa, pa), pb2 = pk(pb, pb);
            const ull* vr = (const ull*)&Vs[j][0];
            #pragma unroll
            for (int d2 = 0; d2 < 16; d2++) {
                ull v2 = vr[d2];
                Oa[d2] = fma2(pa2, v2, Oa[d2]);
                Ob[d2] = fma2(pb2, v2, Ob[d2]);
            }
        }
        ma = tma; mb = tmb;
        __syncwarp();
    }

    size_t hb = ((size_t)(((br*B_ + b)*H_ + hh)*SPLITS + sp)) * L_;
    {
        size_t oa = hb + qa_row;
        ull* op = (ull*)(Opart + oa * 32);
        #pragma unroll
        for (int d2 = 0; d2 < 16; d2++) op[d2] = Oa[d2];
        ML[oa] = make_float2(ma, la);
    }
    {
        size_t ob = hb + qb_row;
        ull* op = (ull*)(Opart + ob * 32);
        #pragma unroll
        for (int d2 = 0; d2 < 16; d2++) op[d2] = Ob[d2];
        ML[ob] = make_float2(mb, lb);
    }
}

// ---------------- combine splits + branches -> acc (+planes) ----------------
__global__ void __launch_bounds__(256) combine_kernel(
    const float* __restrict__ Opart, const float2* __restrict__ ML,
    const float* __restrict__ h, const float* __restrict__ ffo,
    float* __restrict__ acc, uint* __restrict__ ahi, uint* __restrict__ alo)
{
    int tok = blockIdx.x;
    int u = threadIdx.x;
    int b = tok / L_, l = tok - b * L_;
    int hh = u >> 5, d = u & 31;
    float res = 0.f;
    #pragma unroll
    for (int br = 0; br < 2; br++) {
        int base = ((br*B_ + b)*H_ + hh) * SPLITS;
        float2 ml[SPLITS];
        float m = -1e30f;
        #pragma unroll
        for (int sp = 0; sp < SPLITS; sp++) {
            ml[sp] = ML[(size_t)(base + sp) * L_ + l];
            m = fmaxf(m, ml[sp].x);
        }
        float Osum = 0.f, lsum = 0.f;
        #pragma unroll
        for (int sp = 0; sp < SPLITS; sp++) {
            float w = __expf(ml[sp].x - m);
            lsum += w * ml[sp].y;
            Osum += w * Opart[((size_t)(base + sp) * L_ + l) * 32 + d];
        }
        res += Osum / lsum;
    }
    size_t i = (size_t)tok * 256 + u;
    float o = h[i] + ffo[i] + res;
    acc[i] = o;
    float pn = __shfl_xor_sync(0xffffffffu, o, 1);
    if (!(u & 1)) {
        uint hi, lo; split_pair(o, pn, hi, lo);
        ahi[(size_t)tok * 128 + (u >> 1)] = hi;
        alo[(size_t)tok * 128 + (u >> 1)] = lo;
    }
}

// ---------------- launch -----------------------------------------------------
extern "C" void kernel_launch(void* const* d_in, const int* in_sizes, int n_in,
                              void* d_out, int out_size)
{
    const float* x       = (const float*)d_in[0];
    const float* context = (const float*)d_in[1];
    const float* bn_g = (const float*)d_in[2];
    const float* bn_b = (const float*)d_in[3];
    const float* bn_m = (const float*)d_in[4];
    const float* bn_v = (const float*)d_in[5];
    const float* ln1_g = (const float*)d_in[6];
    const float* ln1_b = (const float*)d_in[7];
    const float* ln2_g = (const float*)d_in[8];
    const float* ln2_b = (const float*)d_in[9];
    const float* ln3_g = (const float*)d_in[10];
    const float* ln3_b = (const float*)d_in[11];
    const float* pin_w = (const float*)d_in[12];
    const float* pin_b = (const float*)d_in[13];
    const float* q_w   = (const float*)d_in[14];
    const float* q_b   = (const float*)d_in[15];
    const float* k_w   = (const float*)d_in[16];
    const float* k_b   = (const float*)d_in[17];
    const float* v_w   = (const float*)d_in[18];
    const float* v_b   = (const float*)d_in[19];
    const float* ff1_w = (const float*)d_in[20];
    const float* ff1_b = (const float*)d_in[21];
    const float* ff2_w = (const float*)d_in[22];
    const float* ff2_b = (const float*)d_in[23];
    const float* pout_w = (const float*)d_in[24];
    const float* pout_b = (const float*)d_in[25];
    float* out = (float*)d_out;

    float *p_h, *p_hhat, *p_q1, *p_k1, *p_v1, *p_q2, *p_k2, *p_v2;
    float *p_f1, *p_ffo, *p_acc, *p_Opart;
    float2* p_ML;
    uint *p_xhi, *p_xlo, *p_cthi, *p_ctlo, *p_hhi, *p_hlo, *p_nhi, *p_nlo;
    uint *p_f1hi, *p_f1lo, *p_ahi, *p_alo;
    uint *w_pin_h, *w_pin_l, *w_q1_h, *w_q1_l, *w_q2_h, *w_q2_l;
    uint *w_k_h, *w_k_l, *w_v_h, *w_v_l, *w_po_h, *w_po_l;
    uint *w_f1_h, *w_f1_l, *w_f2_h, *w_f2_l;
    float *p_bpin, *p_bq1, *p_bq2, *p_bff1;

    cudaGetSymbolAddress((void**)&p_h,    d_h);
    cudaGetSymbolAddress((void**)&p_hhat, d_hhat);
    cudaGetSymbolAddress((void**)&p_q1,   d_q1);
    cudaGetSymbolAddress((void**)&p_k1,   d_k1);
    cudaGetSymbolAddress((void**)&p_v1,   d_v1);
    cudaGetSymbolAddress((void**)&p_q2,   d_q2);
    cudaGetSymbolAddress((void**)&p_k2,   d_k2);
    cudaGetSymbolAddress((void**)&p_v2,   d_v2);
    cudaGetSymbolAddress((void**)&p_f1,   d_f1);
    cudaGetSymbolAddress((void**)&p_ffo,  d_ffo);
    cudaGetSymbolAddress((void**)&p_acc,  d_acc);
    cudaGetSymbolAddress((void**)&p_Opart,d_Opart);
    cudaGetSymbolAddress((void**)&p_ML,   d_ML);
    cudaGetSymbolAddress((void**)&p_xhi,  d_xhi);
    cudaGetSymbolAddress((void**)&p_xlo,  d_xlo);
    cudaGetSymbolAddress((void**)&p_cthi, d_cthi);
    cudaGetSymbolAddress((void**)&p_ctlo, d_ctlo);
    cudaGetSymbolAddress((void**)&p_hhi,  d_hhi);
    cudaGetSymbolAddress((void**)&p_hlo,  d_hlo);
    cudaGetSymbolAddress((void**)&p_nhi,  d_nhi);
    cudaGetSymbolAddress((void**)&p_nlo,  d_nlo);
    cudaGetSymbolAddress((void**)&p_f1hi, d_f1hi);
    cudaGetSymbolAddress((void**)&p_f1lo, d_f1lo);
    cudaGetSymbolAddress((void**)&p_ahi,  d_ahi);
    cudaGetSymbolAddress((void**)&p_alo,  d_alo);
    cudaGetSymbolAddress((void**)&w_pin_h, d_Wpin_h);
    cudaGetSymbolAddress((void**)&w_pin_l, d_Wpin_l);
    cudaGetSymbolAddress((void**)&w_q1_h,  d_Wq1_h);
    cudaGetSymbolAddress((void**)&w_q1_l,  d_Wq1_l);
    cudaGetSymbolAddress((void**)&w_q2_h,  d_Wq2_h);
    cudaGetSymbolAddress((void**)&w_q2_l,  d_Wq2_l);
    cudaGetSymbolAddress((void**)&w_k_h,   d_Wk_h);
    cudaGetSymbolAddress((void**)&w_k_l,   d_Wk_l);
    cudaGetSymbolAddress((void**)&w_v_h,   d_Wv_h);
    cudaGetSymbolAddress((void**)&w_v_l,   d_Wv_l);
    cudaGetSymbolAddress((void**)&w_po_h,  d_Wpout_h);
    cudaGetSymbolAddress((void**)&w_po_l,  d_Wpout_l);
    cudaGetSymbolAddress((void**)&w_f1_h,  d_Wff1_h);
    cudaGetSymbolAddress((void**)&w_f1_l,  d_Wff1_l);
    cudaGetSymbolAddress((void**)&w_f2_h,  d_Wff2_h);
    cudaGetSymbolAddress((void**)&w_f2_l,  d_Wff2_l);
    cudaGetSymbolAddress((void**)&p_bpin,  d_bpin);
    cudaGetSymbolAddress((void**)&p_bq1,   d_bq1);
    cudaGetSymbolAddress((void**)&p_bq2,   d_bq2);
    cudaGetSymbolAddress((void**)&p_bff1,  d_bff1);

    // 1. fold + convert weights
    prep_kernel<<<11, 256>>>(bn_g, bn_b, bn_m, bn_v,
                             ln1_g, ln1_b, ln2_g, ln2_b, ln3_g, ln3_b,
                             pin_w, pin_b, q_w, q_b, k_w, v_w,
                             ff1_w, ff1_b, ff2_w, pout_w);

    // 2. x / context planes
    {
        int nw = NTOK * 128;
        cvt_planes<<<(nw + 255) / 256, 256>>>(x, p_xhi, p_xlo, nw);
        cvt_planes<<<(nw + 255) / 256, 256>>>(context, p_cthi, p_ctlo, nw);
    }

    auto mkop = [](const uint* Ahi, const uint* Alo, const uint* Whi, const uint* Wlo,
                   const float* bias, const float* resid, float* o,
                   uint* Ohi, uint* Olo, int N, int K, int flags, int start) {
        GOp g; g.Ahi = Ahi; g.Alo = Alo; g.Whi = Whi; g.Wlo = Wlo;
        g.bias = bias; g.resid = resid; g.out = o; g.Ohi = Ohi; g.Olo = Olo;
        g.N = N; g.K = K; g.flags = flags; g.tileStart = start;
        return g;
    };
    const int RT = NTOK / 64;          // 54 row tiles
    const int T256 = RT * 4;           // 216 tiles for N=256

    // 3. pin: h = relu(x @ Wpin + bpin), emit h planes
    {
        GBatch P = {};
        P.op[0] = mkop(p_xhi, p_xlo, w_pin_h, w_pin_l, p_bpin, nullptr,
                       p_h, p_hhi, p_hlo, 256, 256, FRELU | FPLANES, 0);
        P.nops = 1;
        gemmT<<<T256, 128>>>(P);
    }

    // 4. hhat (+planes)
    lnorm_kernel<<<NTOK, 256>>>(p_h, p_hhat, p_nhi, p_nlo);

    // 5. projections + ff1 in one launch
    {
        GBatch P = {};
        P.op[0] = mkop(p_nhi, p_nlo, w_q1_h, w_q1_l, p_bq1, nullptr,
                       p_q1, nullptr, nullptr, 256, 256, 0, 0);
        P.op[1] = mkop(p_hhi, p_hlo, w_k_h, w_k_l, k_b, nullptr,
                       p_k1, nullptr, nullptr, 256, 256, 0, T256);
        P.op[2] = mkop(p_hhi, p_hlo, w_v_h, w_v_l, v_b, nullptr,
                       p_v1, nullptr, nullptr, 256, 256, 0, T256*2);
        P.op[3] = mkop(p_nhi, p_nlo, w_q2_h, w_q2_l, p_bq2, nullptr,
                       p_q2, nullptr, nullptr, 256, 256, 0, T256*3);
        P.op[4] = mkop(p_cthi, p_ctlo, w_k_h, w_k_l, k_b, nullptr,
                       p_k2, nullptr, nullptr, 256, 256, 0, T256*4);
        P.op[5] = mkop(p_cthi, p_ctlo, w_v_h, w_v_l, v_b, nullptr,
                       p_v2, nullptr, nullptr, 256, 256, 0, T256*5);
        P.op[6] = mkop(p_nhi, p_nlo, w_f1_h, w_f1_l, p_bff1, nullptr,
                       p_f1, p_f1hi, p_f1lo, 1024, 256, FRELU | FPLANES, T256*6);
        P.nops = 7;
        gemmT<<<T256*6 + RT*16, 128>>>(P);   // 1296 + 864 = 2160
    }

    // 6. attention (both branches, split-K)
    {
        dim3 ga(L_/64, H_*SPLITS, B_*2);
        attn_split<<<ga, 32>>>(p_q1, p_k1, p_v1, p_q2, p_k2, p_v2, p_Opart, p_ML);
    }

    // 7. ff2
    {
        GBatch P = {};
        P.op[0] = mkop(p_f1hi, p_f1lo, w_f2_h, w_f2_l, ff2_b, nullptr,
                       p_ffo, nullptr, nullptr, 256, 1024, 0, 0);
        P.nops = 1;
        gemmT<<<T256, 128>>>(P);
    }

    // 8. combine -> acc (+planes)
    combine_kernel<<<NTOK, 256>>>(p_Opart, p_ML, p_h, p_ffo, p_acc, p_ahi, p_alo);

    // 9. out = relu(acc @ pout + b) + x
    {
        GBatch P = {};
        P.op[0] = mkop(p_ahi, p_alo, w_po_h, w_po_l, pout_b, x,
                       out, nullptr, nullptr, 256, 256, FRELU | FRESID, 0);
        P.nops = 1;
        gemmT<<<T256, 128>>>(P);
    }
}

// round 6
// speedup vs baseline: 1.8122x; 1.2526x over previous
#include <cuda_runtime.h>
#include <math.h>

typedef unsigned long long ull;
typedef unsigned int uint;

#define B_    2
#define L_    1728
#define NTOK  3456
#define C_    256
#define U_    256
#define H_    8
#define HD    32
#define FF_   1024
#define EPS_  1e-3f
#define NKT   27          /* 27 key tiles of 64 */

#define FRELU   1
#define FRESID  2
#define FPLANES 4
#define FOUT    8

// ---------------- bf16 split helpers ---------------------------------------
__device__ __forceinline__ uint bf16_of(float f) {
    unsigned short u; asm("cvt.rn.bf16.f32 %0,%1;" : "=h"(u) : "f"(f));
    return (uint)u;
}
__device__ __forceinline__ void split_pair(float f0, float f1, uint& hi, uint& lo) {
    uint h0 = bf16_of(f0), h1 = bf16_of(f1);
    hi = h0 | (h1 << 16);
    float r0 = f0 - __uint_as_float(h0 << 16);
    float r1 = f1 - __uint_as_float(h1 << 16);
    lo = bf16_of(r0) | (bf16_of(r1) << 16);
}

// ---------------- mma m16n8k16 bf16 -----------------------------------------
__device__ __forceinline__ void mma_bf16(float* c, uint a0, uint a1, uint a2, uint a3,
                                         uint b0, uint b1) {
    asm volatile("mma.sync.aligned.m16n8k16.row.col.f32.bf16.bf16.f32 "
                 "{%0,%1,%2,%3},{%4,%5,%6,%7},{%8,%9},{%0,%1,%2,%3};"
                 : "+f"(c[0]), "+f"(c[1]), "+f"(c[2]), "+f"(c[3])
                 : "r"(a0), "r"(a1), "r"(a2), "r"(a3), "r"(b0), "r"(b1));
}

// ---------------- scratch ---------------------------------------------------
__device__ float d_h   [NTOK*U_];
__device__ float d_v1  [NTOK*U_];
__device__ float d_v2  [NTOK*U_];
__device__ float d_ffo [NTOK*U_];
__device__ float d_acc [NTOK*U_];
__device__ float d_O1  [NTOK*U_];
__device__ float d_O2  [NTOK*U_];

// activation planes ([M][K/2] packed bf16 pairs)
__device__ uint d_xhi [NTOK*128], d_xlo [NTOK*128];
__device__ uint d_cthi[NTOK*128], d_ctlo[NTOK*128];
__device__ uint d_hhi [NTOK*128], d_hlo [NTOK*128];
__device__ uint d_nhi [NTOK*128], d_nlo [NTOK*128];
__device__ uint d_f1hi[NTOK*512], d_f1lo[NTOK*512];
__device__ uint d_ahi [NTOK*128], d_alo [NTOK*128];
__device__ uint d_q1hi[NTOK*128], d_q1lo[NTOK*128];
__device__ uint d_k1hi[NTOK*128], d_k1lo[NTOK*128];
__device__ uint d_q2hi[NTOK*128], d_q2lo[NTOK*128];
__device__ uint d_k2hi[NTOK*128], d_k2lo[NTOK*128];
// V transposed planes: [group=br*2b*8h (32)][hd=32][864 key-pair words]
__device__ uint d_vthi[32*32*864], d_vtlo[32*32*864];

// weight planes (transposed: [N][K/2])
__device__ uint d_Wpin_h[256*128], d_Wpin_l[256*128];
__device__ uint d_Wq1_h [256*128], d_Wq1_l [256*128];
__device__ uint d_Wq2_h [256*128], d_Wq2_l [256*128];
__device__ uint d_Wk_h  [256*128], d_Wk_l  [256*128];
__device__ uint d_Wv_h  [256*128], d_Wv_l  [256*128];
__device__ uint d_Wpout_h[256*128], d_Wpout_l[256*128];
__device__ uint d_Wff1_h[1024*128], d_Wff1_l[1024*128];
__device__ uint d_Wff2_h[256*512],  d_Wff2_l[256*512];

__device__ float d_bpin[U_], d_bq1[U_], d_bq2[U_], d_bff1[FF_];

// ---------------- prep: fold affines, build transposed bf16 planes ----------
__global__ void prep_kernel(
    const float* __restrict__ bn_g, const float* __restrict__ bn_b,
    const float* __restrict__ bn_m, const float* __restrict__ bn_v,
    const float* __restrict__ ln1_g, const float* __restrict__ ln1_b,
    const float* __restrict__ ln2_g, const float* __restrict__ ln2_b,
    const float* __restrict__ ln3_g, const float* __restrict__ ln3_b,
    const float* __restrict__ pin_w, const float* __restrict__ pin_b,
    const float* __restrict__ q_w,  const float* __restrict__ q_b,
    const float* __restrict__ k_w,  const float* __restrict__ v_w,
    const float* __restrict__ ff1_w, const float* __restrict__ ff1_b,
    const float* __restrict__ ff2_w, const float* __restrict__ pout_w)
{
    int idx = blockIdx.x * blockDim.x + threadIdx.x;
    if (idx < 256) {
        int u = idx; float accP = pin_b[u];
        for (int k2 = 0; k2 < 128; k2++) {
            float w[2];
            #pragma unroll
            for (int e = 0; e < 2; e++) {
                int k = 2*k2 + e;
                float sc = rsqrtf(bn_v[k] + EPS_) * bn_g[k];
                float sh = bn_b[k] - bn_m[k] * sc;
                float pw = pin_w[k*256 + u];
                w[e] = sc * pw;
                accP += sh * pw;
            }
            uint hi, lo; split_pair(w[0], w[1], hi, lo);
            d_Wpin_h[u*128 + k2] = hi; d_Wpin_l[u*128 + k2] = lo;
        }
        d_bpin[u] = accP;
    } else if (idx < 512) {
        int u = idx - 256; float acc = q_b[u];
        for (int k2 = 0; k2 < 128; k2++) {
            float w[2];
            #pragma unroll
            for (int e = 0; e < 2; e++) {
                int k = 2*k2 + e;
                float qw = q_w[k*256 + u];
                w[e] = ln1_g[k] * qw;
                acc += ln1_b[k] * qw;
            }
            uint hi, lo; split_pair(w[0], w[1], hi, lo);
            d_Wq1_h[u*128 + k2] = hi; d_Wq1_l[u*128 + k2] = lo;
        }
        d_bq1[u] = acc;
    } else if (idx < 768) {
        int u = idx - 512; float acc = q_b[u];
        for (int k2 = 0; k2 < 128; k2++) {
            float w[2];
            #pragma unroll
            for (int e = 0; e < 2; e++) {
                int k = 2*k2 + e;
                float qw = q_w[k*256 + u];
                w[e] = ln2_g[k] * qw;
                acc += ln2_b[k] * qw;
            }
            uint hi, lo; split_pair(w[0], w[1], hi, lo);
            d_Wq2_h[u*128 + k2] = hi; d_Wq2_l[u*128 + k2] = lo;
        }
        d_bq2[u] = acc;
    } else if (idx < 1024) {
        int u = idx - 768;
        for (int k2 = 0; k2 < 128; k2++) {
            uint hi, lo;
            split_pair(k_w[(2*k2)*256 + u], k_w[(2*k2+1)*256 + u], hi, lo);
            d_Wk_h[u*128 + k2] = hi; d_Wk_l[u*128 + k2] = lo;
        }
    } else if (idx < 1280) {
        int u = idx - 1024;
        for (int k2 = 0; k2 < 128; k2++) {
            uint hi, lo;
            split_pair(v_w[(2*k2)*256 + u], v_w[(2*k2+1)*256 + u], hi, lo);
            d_Wv_h[u*128 + k2] = hi; d_Wv_l[u*128 + k2] = lo;
        }
    } else if (idx < 1536) {
        int u = idx - 1280;
        for (int k2 = 0; k2 < 128; k2++) {
            uint hi, lo;
            split_pair(pout_w[(2*k2)*256 + u], pout_w[(2*k2+1)*256 + u], hi, lo);
            d_Wpout_h[u*128 + k2] = hi; d_Wpout_l[u*128 + k2] = lo;
        }
    } else if (idx < 1792) {
        int u = idx - 1536;
        for (int k2 = 0; k2 < 512; k2++) {
            uint hi, lo;
            split_pair(ff2_w[(2*k2)*256 + u], ff2_w[(2*k2+1)*256 + u], hi, lo);
            d_Wff2_h[u*512 + k2] = hi; d_Wff2_l[u*512 + k2] = lo;
        }
    } else if (idx < 2816) {
        int u = idx - 1792; float acc = ff1_b[u];
        for (int k2 = 0; k2 < 128; k2++) {
            float w[2];
            #pragma unroll
            for (int e = 0; e < 2; e++) {
                int k = 2*k2 + e;
                float fw = ff1_w[k*1024 + u];
                w[e] = ln3_g[k] * fw;
                acc += ln3_b[k] * fw;
            }
            uint hi, lo; split_pair(w[0], w[1], hi, lo);
            d_Wff1_h[u*128 + k2] = hi; d_Wff1_l[u*128 + k2] = lo;
        }
        d_bff1[u] = acc;
    }
}

// ---------------- convert activation tensor to planes ----------------------
__global__ void cvt_planes(const float* __restrict__ a, uint* __restrict__ hi,
                           uint* __restrict__ lo, int nwords)
{
    int i = blockIdx.x * blockDim.x + threadIdx.x;
    if (i < nwords) {
        float2 f = ((const float2*)a)[i];
        uint h, l; split_pair(f.x, f.y, h, l);
        hi[i] = h; lo[i] = l;
    }
}

// ---------------- tensor-core batched GEMM (bf16x3) -------------------------
struct GOp {
    const uint* Ahi; const uint* Alo;
    const uint* Whi; const uint* Wlo;
    const float* bias; const float* resid;
    float* out; uint* Ohi; uint* Olo;
    int N; int K; int flags; int tileStart;
};
struct GBatch { GOp op[8]; int nops; };

__global__ void __launch_bounds__(128) gemmT(GBatch P)
{
    __shared__ uint As_hi[64][12], As_lo[64][12];
    __shared__ uint Ws_hi[64][12], Ws_lo[64][12];

    int bid = blockIdx.x;
    int sel = 0;
    #pragma unroll
    for (int i = 1; i < 8; i++)
        if (i < P.nops && bid >= P.op[i].tileStart) sel = i;
    GOp g = P.op[sel];

    int local = bid - g.tileStart;
    int ntn = g.N >> 6;
    int mt = local / ntn;
    int nt = local - mt * ntn;
    int m0 = mt * 64, n0 = nt * 64;
    int tid = threadIdx.x;
    int warp = tid >> 5, lane = tid & 31;
    int gq = lane >> 2, t = lane & 3;
    int K2 = g.K >> 1;

    float acc[8][4];
    #pragma unroll
    for (int j = 0; j < 8; j++)
        #pragma unroll
        for (int i = 0; i < 4; i++) acc[j][i] = 0.f;

    int frow = tid >> 1;
    int fhf  = (tid & 1) * 4;

    for (int k16 = 0; k16 < g.K; k16 += 16) {
        int k2o = k16 >> 1;
        {
            const uint4 ah = *(const uint4*)&g.Ahi[(size_t)(m0+frow)*K2 + k2o + fhf];
            const uint4 al = *(const uint4*)&g.Alo[(size_t)(m0+frow)*K2 + k2o + fhf];
            const uint4 wh = *(const uint4*)&g.Whi[(size_t)(n0+frow)*K2 + k2o + fhf];
            const uint4 wl = *(const uint4*)&g.Wlo[(size_t)(n0+frow)*K2 + k2o + fhf];
            *(uint4*)&As_hi[frow][fhf] = ah;
            *(uint4*)&As_lo[frow][fhf] = al;
            *(uint4*)&Ws_hi[frow][fhf] = wh;
            *(uint4*)&Ws_lo[frow][fhf] = wl;
        }
        __syncthreads();

        int rs = warp * 16;
        uint a0h = As_hi[rs+gq  ][t  ], a1h = As_hi[rs+gq+8][t  ];
        uint a2h = As_hi[rs+gq  ][t+4], a3h = As_hi[rs+gq+8][t+4];
        uint a0l = As_lo[rs+gq  ][t  ], a1l = As_lo[rs+gq+8][t  ];
        uint a2l = As_lo[rs+gq  ][t+4], a3l = As_lo[rs+gq+8][t+4];

        #pragma unroll
        for (int j = 0; j < 8; j++) {
            int n = j*8 + gq;
            uint b0h = Ws_hi[n][t], b1h = Ws_hi[n][t+4];
            uint b0l = Ws_lo[n][t], b1l = Ws_lo[n][t+4];
            mma_bf16(acc[j], a0h, a1h, a2h, a3h, b0h, b1h);
            mma_bf16(acc[j], a0h, a1h, a2h, a3h, b0l, b1l);
            mma_bf16(acc[j], a0l, a1l, a2l, a3l, b0h, b1h);
        }
        __syncthreads();
    }

    int K2o = g.N >> 1;
    int r0 = m0 + warp*16 + gq;
    int r1 = r0 + 8;
    #pragma unroll
    for (int j = 0; j < 8; j++) {
        int c0 = n0 + j*8 + 2*t;
        float b0 = g.bias[c0], b1 = g.bias[c0+1];
        float v00 = acc[j][0] + b0, v01 = acc[j][1] + b1;
        float v10 = acc[j][2] + b0, v11 = acc[j][3] + b1;
        if (g.flags & FRELU) {
            v00 = fmaxf(v00, 0.f); v01 = fmaxf(v01, 0.f);
            v10 = fmaxf(v10, 0.f); v11 = fmaxf(v11, 0.f);
        }
        if (g.flags & FRESID) {
            float2 ra = *(const float2*)&g.resid[(size_t)r0*g.N + c0];
            float2 rb = *(const float2*)&g.resid[(size_t)r1*g.N + c0];
            v00 += ra.x; v01 += ra.y; v10 += rb.x; v11 += rb.y;
        }
        if (g.flags & FOUT) {
            *(float2*)&g.out[(size_t)r0*g.N + c0] = make_float2(v00, v01);
            *(float2*)&g.out[(size_t)r1*g.N + c0] = make_float2(v10, v11);
        }
        if (g.flags & FPLANES) {
            uint h, l;
            split_pair(v00, v01, h, l);
            g.Ohi[(size_t)r0*K2o + (c0>>1)] = h; g.Olo[(size_t)r0*K2o + (c0>>1)] = l;
            split_pair(v10, v11, h, l);
            g.Ohi[(size_t)r1*K2o + (c0>>1)] = h; g.Olo[(size_t)r1*K2o + (c0>>1)] = l;
        }
    }
}

// ---------------- LayerNorm (normalize only) -> planes ----------------------
__global__ void __launch_bounds__(256) lnorm_kernel(const float* __restrict__ h,
                                                    uint* __restrict__ nhi,
                                                    uint* __restrict__ nlo)
{
    int row = blockIdx.x;
    int tid = threadIdx.x;
    float v = h[(size_t)row * 256 + tid];
    __shared__ float red[8];
    float s = v;
    #pragma unroll
    for (int o = 16; o > 0; o >>= 1) s += __shfl_xor_sync(0xffffffffu, s, o);
    if ((tid & 31) == 0) red[tid >> 5] = s;
    __syncthreads();
    float tot = 0.f;
    #pragma unroll
    for (int i = 0; i < 8; i++) tot += red[i];
    float mu = tot * (1.f / 256.f);
    float d = v - mu;
    float s2 = d * d;
    #pragma unroll
    for (int o = 16; o > 0; o >>= 1) s2 += __shfl_xor_sync(0xffffffffu, s2, o);
    __syncthreads();
    if ((tid & 31) == 0) red[tid >> 5] = s2;
    __syncthreads();
    float tot2 = 0.f;
    #pragma unroll
    for (int i = 0; i < 8; i++) tot2 += red[i];
    float var = tot2 * (1.f / 256.f);
    float o = d * rsqrtf(var + EPS_);
    float pn = __shfl_xor_sync(0xffffffffu, o, 1);
    if (!(tid & 1)) {
        uint hi, lo; split_pair(o, pn, hi, lo);
        nhi[(size_t)row * 128 + (tid >> 1)] = hi;
        nlo[(size_t)row * 128 + (tid >> 1)] = lo;
    }
}

// ---------------- V transpose into packed key-pair planes -------------------
__global__ void __launch_bounds__(128) vplanes_T(
    const float* __restrict__ V1, const float* __restrict__ V2,
    uint* __restrict__ vthi, uint* __restrict__ vtlo)
{
    __shared__ float Vs[64][33];
    int tid = threadIdx.x;
    int kt = blockIdx.x;            // key tile 0..26
    int head = blockIdx.y;
    int br = blockIdx.z >> 1, b = blockIdx.z & 1;
    const float* V = br ? V2 : V1;
    #pragma unroll
    for (int i = 0; i < 4; i++) {
        int idx = tid + i * 128;
        int key = idx >> 3, f4 = (idx & 7) * 4;
        const float* p = &V[(size_t)(b * L_ + kt * 64 + key) * 256 + head * 32 + f4];
        float4 t4 = *(const float4*)p;
        Vs[key][f4] = t4.x; Vs[key][f4+1] = t4.y;
        Vs[key][f4+2] = t4.z; Vs[key][f4+3] = t4.w;
    }
    __syncthreads();
    int g = (br * 2 + b) * 8 + head;
    #pragma unroll
    for (int i = 0; i < 8; i++) {
        int widx = tid + i * 128;
        int d = widx >> 5, kp = widx & 31;
        uint hi, lo;
        split_pair(Vs[2*kp][d], Vs[2*kp+1][d], hi, lo);
        size_t o = ((size_t)g * 32 + d) * 864 + kt * 32 + kp;
        vthi[o] = hi; vtlo[o] = lo;
    }
}

// ---------------- tensor-core flash attention -------------------------------
// block: 128 thr (4 warps), 64 queries, full 1728 keys, one (br,b,head).
__global__ void __launch_bounds__(128) attn_mma(
    const uint* __restrict__ Q1hi, const uint* __restrict__ Q1lo,
    const uint* __restrict__ K1hi, const uint* __restrict__ K1lo,
    const uint* __restrict__ Q2hi, const uint* __restrict__ Q2lo,
    const uint* __restrict__ K2hi, const uint* __restrict__ K2lo,
    const uint* __restrict__ VThi, const uint* __restrict__ VTlo,
    float* __restrict__ O1, float* __restrict__ O2)
{
    __shared__ uint Khi[64][20], Klo[64][20];
    __shared__ uint Vhi[32][36], Vlo[32][36];

    int tid = threadIdx.x, warp = tid >> 5, lane = tid & 31;
    int gq = lane >> 2, t = lane & 3;
    int qt = blockIdx.x, head = blockIdx.y;
    int br = blockIdx.z >> 1, b = blockIdx.z & 1;
    const uint* Qhi = br ? Q2hi : Q1hi;
    const uint* Qlo = br ? Q2lo : Q1lo;
    const uint* KhG = br ? K2hi : K1hi;
    const uint* KlG = br ? K2lo : K1lo;
    float* Ob = br ? O2 : O1;
    const float scale = 0.0625f;

    int r0 = qt * 64 + warp * 16 + gq;
    int r1 = r0 + 8;

    uint qh[2][4], ql[2][4];
    {
        size_t q0 = (size_t)(b * L_ + r0) * 128 + head * 16;
        size_t q1 = (size_t)(b * L_ + r1) * 128 + head * 16;
        #pragma unroll
        for (int ks = 0; ks < 2; ks++) {
            qh[ks][0] = Qhi[q0 + ks*8 + t];     qh[ks][1] = Qhi[q1 + ks*8 + t];
            qh[ks][2] = Qhi[q0 + ks*8 + t + 4]; qh[ks][3] = Qhi[q1 + ks*8 + t + 4];
            ql[ks][0] = Qlo[q0 + ks*8 + t];     ql[ks][1] = Qlo[q1 + ks*8 + t];
            ql[ks][2] = Qlo[q0 + ks*8 + t + 4]; ql[ks][3] = Qlo[q1 + ks*8 + t + 4];
        }
    }

    float Oacc[4][4];
    #pragma unroll
    for (int j = 0; j < 4; j++)
        #pragma unroll
        for (int i = 0; i < 4; i++) Oacc[j][i] = 0.f;
    float m0r = -1e30f, m1r = -1e30f, l0r = 0.f, l1r = 0.f;

    int vg = (br * 2 + b) * 8 + head;

    for (int kt = 0; kt < NKT; kt++) {
        {   // K tile: 64 keys x 16 words per plane
            int key = tid >> 1;
            int w4  = (tid & 1) * 8;
            size_t go = (size_t)(b * L_ + kt * 64 + key) * 128 + head * 16 + w4;
            *(uint4*)&Khi[key][w4]     = *(const uint4*)&KhG[go];
            *(uint4*)&Khi[key][w4 + 4] = *(const uint4*)&KhG[go + 4];
            *(uint4*)&Klo[key][w4]     = *(const uint4*)&KlG[go];
            *(uint4*)&Klo[key][w4 + 4] = *(const uint4*)&KlG[go + 4];
        }
        {   // Vt tile: 32 hd x 32 key-pair words per plane
            int d = tid >> 2;
            int w4 = (tid & 3) * 8;
            size_t go = ((size_t)vg * 32 + d) * 864 + kt * 32 + w4;
            *(uint4*)&Vhi[d][w4]     = *(const uint4*)&VThi[go];
            *(uint4*)&Vhi[d][w4 + 4] = *(const uint4*)&VThi[go + 4];
            *(uint4*)&Vlo[d][w4]     = *(const uint4*)&VTlo[go];
            *(uint4*)&Vlo[d][w4 + 4] = *(const uint4*)&VTlo[go + 4];
        }
        __syncthreads();

        // S = Q K^T (64x64 per block; this warp: rows r0/r1, 64 cols)
        float s[8][4];
        #pragma unroll
        for (int j = 0; j < 8; j++) {
            s[j][0] = s[j][1] = s[j][2] = s[j][3] = 0.f;
            int n = j * 8 + gq;
            #pragma unroll
            for (int ks = 0; ks < 2; ks++) {
                uint b0h = Khi[n][ks*8 + t], b1h = Khi[n][ks*8 + t + 4];
                uint b0l = Klo[n][ks*8 + t], b1l = Klo[n][ks*8 + t + 4];
                mma_bf16(s[j], qh[ks][0], qh[ks][1], qh[ks][2], qh[ks][3], b0h, b1h);
                mma_bf16(s[j], qh[ks][0], qh[ks][1], qh[ks][2], qh[ks][3], b0l, b1l);
                mma_bf16(s[j], ql[ks][0], ql[ks][1], ql[ks][2], ql[ks][3], b0h, b1h);
            }
            s[j][0] *= scale; s[j][1] *= scale;
            s[j][2] *= scale; s[j][3] *= scale;
        }

        // online softmax
        float mx0 = -1e30f, mx1 = -1e30f;
        #pragma unroll
        for (int j = 0; j < 8; j++) {
            mx0 = fmaxf(mx0, fmaxf(s[j][0], s[j][1]));
            mx1 = fmaxf(mx1, fmaxf(s[j][2], s[j][3]));
        }
        mx0 = fmaxf(mx0, __shfl_xor_sync(0xffffffffu, mx0, 1));
        mx0 = fmaxf(mx0, __shfl_xor_sync(0xffffffffu, mx0, 2));
        mx1 = fmaxf(mx1, __shfl_xor_sync(0xffffffffu, mx1, 1));
        mx1 = fmaxf(mx1, __shfl_xor_sync(0xffffffffu, mx1, 2));
        float nm0 = fmaxf(m0r, mx0), nm1 = fmaxf(m1r, mx1);
        float c0 = __expf(m0r - nm0), c1 = __expf(m1r - nm1);

        float ls0 = 0.f, ls1 = 0.f;
        #pragma unroll
        for (int j = 0; j < 8; j++) {
            s[j][0] = __expf(s[j][0] - nm0); ls0 += s[j][0];
            s[j][1] = __expf(s[j][1] - nm0); ls0 += s[j][1];
            s[j][2] = __expf(s[j][2] - nm1); ls1 += s[j][2];
            s[j][3] = __expf(s[j][3] - nm1); ls1 += s[j][3];
        }
        ls0 += __shfl_xor_sync(0xffffffffu, ls0, 1);
        ls0 += __shfl_xor_sync(0xffffffffu, ls0, 2);
        ls1 += __shfl_xor_sync(0xffffffffu, ls1, 1);
        ls1 += __shfl_xor_sync(0xffffffffu, ls1, 2);
        l0r = l0r * c0 + ls0;
        l1r = l1r * c1 + ls1;
        m0r = nm0; m1r = nm1;

        #pragma unroll
        for (int jn = 0; jn < 4; jn++) {
            Oacc[jn][0] *= c0; Oacc[jn][1] *= c0;
            Oacc[jn][2] *= c1; Oacc[jn][3] *= c1;
        }

        // P -> bf16x2 A fragments
        uint ph[4][4], pl[4][4];
        #pragma unroll
        for (int ks = 0; ks < 4; ks++) {
            split_pair(s[2*ks  ][0], s[2*ks  ][1], ph[ks][0], pl[ks][0]);
            split_pair(s[2*ks  ][2], s[2*ks  ][3], ph[ks][1], pl[ks][1]);
            split_pair(s[2*ks+1][0], s[2*ks+1][1], ph[ks][2], pl[ks][2]);
            split_pair(s[2*ks+1][2], s[2*ks+1][3], ph[ks][3], pl[ks][3]);
        }

        // O += P V
        #pragma unroll
        for (int jn = 0; jn < 4; jn++) {
            int n = jn * 8 + gq;
            #pragma unroll
            for (int ks = 0; ks < 4; ks++) {
                uint b0h = Vhi[n][ks*8 + t], b1h = Vhi[n][ks*8 + t + 4];
                uint b0l = Vlo[n][ks*8 + t], b1l = Vlo[n][ks*8 + t + 4];
                mma_bf16(Oacc[jn], ph[ks][0], ph[ks][1], ph[ks][2], ph[ks][3], b0h, b1h);
                mma_bf16(Oacc[jn], ph[ks][0], ph[ks][1], ph[ks][2], ph[ks][3], b0l, b1l);
                mma_bf16(Oacc[jn], pl[ks][0], pl[ks][1], pl[ks][2], pl[ks][3], b0h, b1h);
            }
        }
        __syncthreads();
    }

    float inv0 = 1.f / l0r, inv1 = 1.f / l1r;
    #pragma unroll
    for (int jn = 0; jn < 4; jn++) {
        int col = head * 32 + jn * 8 + 2 * t;
        *(float2*)&Ob[(size_t)(b * L_ + r0) * 256 + col] =
            make_float2(Oacc[jn][0] * inv0, Oacc[jn][1] * inv0);
        *(float2*)&Ob[(size_t)(b * L_ + r1) * 256 + col] =
            make_float2(Oacc[jn][2] * inv1, Oacc[jn][3] * inv1);
    }
}

// ---------------- combine: acc = h + ffo + O1 + O2 (+planes) ----------------
__global__ void __launch_bounds__(256) combine_kernel(
    const float* __restrict__ O1, const float* __restrict__ O2,
    const float* __restrict__ h, const float* __restrict__ ffo,
    float* __restrict__ acc, uint* __restrict__ ahi, uint* __restrict__ alo)
{
    int tok = blockIdx.x;
    int u = threadIdx.x;
    size_t i = (size_t)tok * 256 + u;
    float o = h[i] + ffo[i] + O1[i] + O2[i];
    acc[i] = o;
    float pn = __shfl_xor_sync(0xffffffffu, o, 1);
    if (!(u & 1)) {
        uint hi, lo; split_pair(o, pn, hi, lo);
        ahi[(size_t)tok * 128 + (u >> 1)] = hi;
        alo[(size_t)tok * 128 + (u >> 1)] = lo;
    }
}

// ---------------- launch -----------------------------------------------------
extern "C" void kernel_launch(void* const* d_in, const int* in_sizes, int n_in,
                              void* d_out, int out_size)
{
    const float* x       = (const float*)d_in[0];
    const float* context = (const float*)d_in[1];
    const float* bn_g = (const float*)d_in[2];
    const float* bn_b = (const float*)d_in[3];
    const float* bn_m = (const float*)d_in[4];
    const float* bn_v = (const float*)d_in[5];
    const float* ln1_g = (const float*)d_in[6];
    const float* ln1_b = (const float*)d_in[7];
    const float* ln2_g = (const float*)d_in[8];
    const float* ln2_b = (const float*)d_in[9];
    const float* ln3_g = (const float*)d_in[10];
    const float* ln3_b = (const float*)d_in[11];
    const float* pin_w = (const float*)d_in[12];
    const float* pin_b = (const float*)d_in[13];
    const float* q_w   = (const float*)d_in[14];
    const float* q_b   = (const float*)d_in[15];
    const float* k_w   = (const float*)d_in[16];
    const float* k_b   = (const float*)d_in[17];
    const float* v_w   = (const float*)d_in[18];
    const float* v_b   = (const float*)d_in[19];
    const float* ff1_w = (const float*)d_in[20];
    const float* ff1_b = (const float*)d_in[21];
    const float* ff2_w = (const float*)d_in[22];
    const float* ff2_b = (const float*)d_in[23];
    const float* pout_w = (const float*)d_in[24];
    const float* pout_b = (const float*)d_in[25];
    float* out = (float*)d_out;

    float *p_h, *p_v1, *p_v2, *p_ffo, *p_acc, *p_O1, *p_O2;
    uint *p_xhi, *p_xlo, *p_cthi, *p_ctlo, *p_hhi, *p_hlo, *p_nhi, *p_nlo;
    uint *p_f1hi, *p_f1lo, *p_ahi, *p_alo;
    uint *p_q1hi, *p_q1lo, *p_k1hi, *p_k1lo, *p_q2hi, *p_q2lo, *p_k2hi, *p_k2lo;
    uint *p_vthi, *p_vtlo;
    uint *w_pin_h, *w_pin_l, *w_q1_h, *w_q1_l, *w_q2_h, *w_q2_l;
    uint *w_k_h, *w_k_l, *w_v_h, *w_v_l, *w_po_h, *w_po_l;
    uint *w_f1_h, *w_f1_l, *w_f2_h, *w_f2_l;
    float *p_bpin, *p_bq1, *p_bq2, *p_bff1;

    cudaGetSymbolAddress((void**)&p_h,    d_h);
    cudaGetSymbolAddress((void**)&p_v1,   d_v1);
    cudaGetSymbolAddress((void**)&p_v2,   d_v2);
    cudaGetSymbolAddress((void**)&p_ffo,  d_ffo);
    cudaGetSymbolAddress((void**)&p_acc,  d_acc);
    cudaGetSymbolAddress((void**)&p_O1,   d_O1);
    cudaGetSymbolAddress((void**)&p_O2,   d_O2);
    cudaGetSymbolAddress((void**)&p_xhi,  d_xhi);
    cudaGetSymbolAddress((void**)&p_xlo,  d_xlo);
    cudaGetSymbolAddress((void**)&p_cthi, d_cthi);
    cudaGetSymbolAddress((void**)&p_ctlo, d_ctlo);
    cudaGetSymbolAddress((void**)&p_hhi,  d_hhi);
    cudaGetSymbolAddress((void**)&p_hlo,  d_hlo);
    cudaGetSymbolAddress((void**)&p_nhi,  d_nhi);
    cudaGetSymbolAddress((void**)&p_nlo,  d_nlo);
    cudaGetSymbolAddress((void**)&p_f1hi, d_f1hi);
    cudaGetSymbolAddress((void**)&p_f1lo, d_f1lo);
    cudaGetSymbolAddress((void**)&p_ahi,  d_ahi);
    cudaGetSymbolAddress((void**)&p_alo,  d_alo);
    cudaGetSymbolAddress((void**)&p_q1hi, d_q1hi);
    cudaGetSymbolAddress((void**)&p_q1lo, d_q1lo);
    cudaGetSymbolAddress((void**)&p_k1hi, d_k1hi);
    cudaGetSymbolAddress((void**)&p_k1lo, d_k1lo);
    cudaGetSymbolAddress((void**)&p_q2hi, d_q2hi);
    cudaGetSymbolAddress((void**)&p_q2lo, d_q2lo);
    cudaGetSymbolAddress((void**)&p_k2hi, d_k2hi);
    cudaGetSymbolAddress((void**)&p_k2lo, d_k2lo);
    cudaGetSymbolAddress((void**)&p_vthi, d_vthi);
    cudaGetSymbolAddress((void**)&p_vtlo, d_vtlo);
    cudaGetSymbolAddress((void**)&w_pin_h, d_Wpin_h);
    cudaGetSymbolAddress((void**)&w_pin_l, d_Wpin_l);
    cudaGetSymbolAddress((void**)&w_q1_h,  d_Wq1_h);
    cudaGetSymbolAddress((void**)&w_q1_l,  d_Wq1_l);
    cudaGetSymbolAddress((void**)&w_q2_h,  d_Wq2_h);
    cudaGetSymbolAddress((void**)&w_q2_l,  d_Wq2_l);
    cudaGetSymbolAddress((void**)&w_k_h,   d_Wk_h);
    cudaGetSymbolAddress((void**)&w_k_l,   d_Wk_l);
    cudaGetSymbolAddress((void**)&w_v_h,   d_Wv_h);
    cudaGetSymbolAddress((void**)&w_v_l,   d_Wv_l);
    cudaGetSymbolAddress((void**)&w_po_h,  d_Wpout_h);
    cudaGetSymbolAddress((void**)&w_po_l,  d_Wpout_l);
    cudaGetSymbolAddress((void**)&w_f1_h,  d_Wff1_h);
    cudaGetSymbolAddress((void**)&w_f1_l,  d_Wff1_l);
    cudaGetSymbolAddress((void**)&w_f2_h,  d_Wff2_h);
    cudaGetSymbolAddress((void**)&w_f2_l,  d_Wff2_l);
    cudaGetSymbolAddress((void**)&p_bpin,  d_bpin);
    cudaGetSymbolAddress((void**)&p_bq1,   d_bq1);
    cudaGetSymbolAddress((void**)&p_bq2,   d_bq2);
    cudaGetSymbolAddress((void**)&p_bff1,  d_bff1);

    // 1. fold + convert weights
    prep_kernel<<<11, 256>>>(bn_g, bn_b, bn_m, bn_v,
                             ln1_g, ln1_b, ln2_g, ln2_b, ln3_g, ln3_b,
                             pin_w, pin_b, q_w, q_b, k_w, v_w,
                             ff1_w, ff1_b, ff2_w, pout_w);

    // 2. x / context planes
    {
        int nw = NTOK * 128;
        cvt_planes<<<(nw + 255) / 256, 256>>>(x, p_xhi, p_xlo, nw);
        cvt_planes<<<(nw + 255) / 256, 256>>>(context, p_cthi, p_ctlo, nw);
    }

    auto mkop = [](const uint* Ahi, const uint* Alo, const uint* Whi, const uint* Wlo,
                   const float* bias, const float* resid, float* o,
                   uint* Ohi, uint* Olo, int N, int K, int flags, int start) {
        GOp g; g.Ahi = Ahi; g.Alo = Alo; g.Whi = Whi; g.Wlo = Wlo;
        g.bias = bias; g.resid = resid; g.out = o; g.Ohi = Ohi; g.Olo = Olo;
        g.N = N; g.K = K; g.flags = flags; g.tileStart = start;
        return g;
    };
    const int RT = NTOK / 64;          // 54
    const int T256 = RT * 4;           // 216

    // 3. pin: h = relu(x @ Wpin + bpin) -> fp32 + planes
    {
        GBatch P = {};
        P.op[0] = mkop(p_xhi, p_xlo, w_pin_h, w_pin_l, p_bpin, nullptr,
                       p_h, p_hhi, p_hlo, 256, 256, FOUT | FRELU | FPLANES, 0);
        P.nops = 1;
        gemmT<<<T256, 128>>>(P);
    }

    // 4. hhat planes
    lnorm_kernel<<<NTOK, 256>>>(p_h, p_nhi, p_nlo);

    // 5. projections + ff1
    {
        GBatch P = {};
        P.op[0] = mkop(p_nhi, p_nlo, w_q1_h, w_q1_l, p_bq1, nullptr,
                       nullptr, p_q1hi, p_q1lo, 256, 256, FPLANES, 0);
        P.op[1] = mkop(p_hhi, p_hlo, w_k_h, w_k_l, k_b, nullptr,
                       nullptr, p_k1hi, p_k1lo, 256, 256, FPLANES, T256);
        P.op[2] = mkop(p_hhi, p_hlo, w_v_h, w_v_l, v_b, nullptr,
                       p_v1, nullptr, nullptr, 256, 256, FOUT, T256*2);
        P.op[3] = mkop(p_nhi, p_nlo, w_q2_h, w_q2_l, p_bq2, nullptr,
                       nullptr, p_q2hi, p_q2lo, 256, 256, FPLANES, T256*3);
        P.op[4] = mkop(p_cthi, p_ctlo, w_k_h, w_k_l, k_b, nullptr,
                       nullptr, p_k2hi, p_k2lo, 256, 256, FPLANES, T256*4);
        P.op[5] = mkop(p_cthi, p_ctlo, w_v_h, w_v_l, v_b, nullptr,
                       p_v2, nullptr, nullptr, 256, 256, FOUT, T256*5);
        P.op[6] = mkop(p_nhi, p_nlo, w_f1_h, w_f1_l, p_bff1, nullptr,
                       nullptr, p_f1hi, p_f1lo, 1024, 256, FRELU | FPLANES, T256*6);
        P.nops = 7;
        gemmT<<<T256*6 + RT*16, 128>>>(P);
    }

    // 6. V transpose planes
    {
        dim3 gv(NKT, H_, 4);
        vplanes_T<<<gv, 128>>>(p_v1, p_v2, p_vthi, p_vtlo);
    }

    // 7. attention (tensor cores)
    {
        dim3 ga(NKT, H_, 4);   // 27 qtiles, 8 heads, br*2+b
        attn_mma<<<ga, 128>>>(p_q1hi, p_q1lo, p_k1hi, p_k1lo,
                              p_q2hi, p_q2lo, p_k2hi, p_k2lo,
                              p_vthi, p_vtlo, p_O1, p_O2);
    }

    // 8. ff2
    {
        GBatch P = {};
        P.op[0] = mkop(p_f1hi, p_f1lo, w_f2_h, w_f2_l, ff2_b, nullptr,
                       p_ffo, nullptr, nullptr, 256, 1024, FOUT, 0);
        P.nops = 1;
        gemmT<<<T256, 128>>>(P);
    }

    // 9. combine -> acc (+planes)
    combine_kernel<<<NTOK, 256>>>(p_O1, p_O2, p_h, p_ffo, p_acc, p_ahi, p_alo);

    // 10. out = relu(acc @ pout + b) + x
    {
        GBatch P = {};
        P.op[0] = mkop(p_ahi, p_alo, w_po_h, w_po_l, pout_b, x,
                       out, nullptr, nullptr, 256, 256, FOUT | FRELU | FRESID, 0);
        P.nops = 1;
        gemmT<<<T256, 128>>>(P);
    }
}

// round 7
// speedup vs baseline: 2.6410x; 1.4573x over previous
#include <cuda_runtime.h>
#include <math.h>

typedef unsigned long long ull;
typedef unsigned int uint;

#define B_    2
#define L_    1728
#define NTOK  3456
#define C_    256
#define U_    256
#define H_    8
#define HD    32
#define FF_   1024
#define EPS_  1e-3f
#define NKT   27          /* 27 key tiles of 64 */

#define FRELU   1
#define FRESID  2
#define FPLANES 4
#define FOUT    8

// ---------------- cp.async helpers ------------------------------------------
__device__ __forceinline__ void cp16(uint saddr, const void* gptr) {
    asm volatile("cp.async.cg.shared.global [%0], [%1], 16;" :: "r"(saddr), "l"(gptr));
}
__device__ __forceinline__ uint sa(const void* p) {
    return (uint)__cvta_generic_to_shared(p);
}
#define CP_COMMIT() asm volatile("cp.async.commit_group;")
#define CP_WAIT0()  asm volatile("cp.async.wait_group 0;")

// ---------------- bf16 split helpers ---------------------------------------
__device__ __forceinline__ uint bf16_of(float f) {
    unsigned short u; asm("cvt.rn.bf16.f32 %0,%1;" : "=h"(u) : "f"(f));
    return (uint)u;
}
__device__ __forceinline__ void split_pair(float f0, float f1, uint& hi, uint& lo) {
    uint h0 = bf16_of(f0), h1 = bf16_of(f1);
    hi = h0 | (h1 << 16);
    float r0 = f0 - __uint_as_float(h0 << 16);
    float r1 = f1 - __uint_as_float(h1 << 16);
    lo = bf16_of(r0) | (bf16_of(r1) << 16);
}

// ---------------- mma m16n8k16 bf16 -----------------------------------------
__device__ __forceinline__ void mma_bf16(float* c, uint a0, uint a1, uint a2, uint a3,
                                         uint b0, uint b1) {
    asm volatile("mma.sync.aligned.m16n8k16.row.col.f32.bf16.bf16.f32 "
                 "{%0,%1,%2,%3},{%4,%5,%6,%7},{%8,%9},{%0,%1,%2,%3};"
                 : "+f"(c[0]), "+f"(c[1]), "+f"(c[2]), "+f"(c[3])
                 : "r"(a0), "r"(a1), "r"(a2), "r"(a3), "r"(b0), "r"(b1));
}

// ---------------- scratch ---------------------------------------------------
__device__ float d_h   [NTOK*U_];
__device__ float d_v1  [NTOK*U_];
__device__ float d_v2  [NTOK*U_];
__device__ float d_ffo [NTOK*U_];
__device__ float d_acc [NTOK*U_];
__device__ float d_O1  [NTOK*U_];
__device__ float d_O2  [NTOK*U_];

// activation planes ([M][K/2] packed bf16 pairs)
__device__ uint d_xhi [NTOK*128], d_xlo [NTOK*128];
__device__ uint d_cthi[NTOK*128], d_ctlo[NTOK*128];
__device__ uint d_hhi [NTOK*128], d_hlo [NTOK*128];
__device__ uint d_nhi [NTOK*128], d_nlo [NTOK*128];
__device__ uint d_f1hi[NTOK*512], d_f1lo[NTOK*512];
__device__ uint d_ahi [NTOK*128], d_alo [NTOK*128];
__device__ uint d_q1hi[NTOK*128], d_q1lo[NTOK*128];
__device__ uint d_k1hi[NTOK*128], d_k1lo[NTOK*128];
__device__ uint d_q2hi[NTOK*128], d_q2lo[NTOK*128];
__device__ uint d_k2hi[NTOK*128], d_k2lo[NTOK*128];
// V transposed planes: [group=br*2b*8h (32)][hd=32][864 key-pair words]
__device__ uint d_vthi[32*32*864], d_vtlo[32*32*864];

// weight planes (transposed: [N][K/2])
__device__ uint d_Wpin_h[256*128], d_Wpin_l[256*128];
__device__ uint d_Wq1_h [256*128], d_Wq1_l [256*128];
__device__ uint d_Wq2_h [256*128], d_Wq2_l [256*128];
__device__ uint d_Wk_h  [256*128], d_Wk_l  [256*128];
__device__ uint d_Wv_h  [256*128], d_Wv_l  [256*128];
__device__ uint d_Wpout_h[256*128], d_Wpout_l[256*128];
__device__ uint d_Wff1_h[1024*128], d_Wff1_l[1024*128];
__device__ uint d_Wff2_h[256*512],  d_Wff2_l[256*512];

__device__ float d_bpin[U_], d_bq1[U_], d_bq2[U_], d_bff1[FF_];

// ---------------- prep weights: fully parallel (1 thread = 1 packed word) ---
__global__ void __launch_bounds__(256) prep_w(
    const float* __restrict__ bn_g, const float* __restrict__ bn_v,
    const float* __restrict__ ln1_g, const float* __restrict__ ln2_g,
    const float* __restrict__ ln3_g,
    const float* __restrict__ pin_w, const float* __restrict__ q_w,
    const float* __restrict__ k_w,  const float* __restrict__ v_w,
    const float* __restrict__ ff1_w, const float* __restrict__ ff2_w,
    const float* __restrict__ pout_w)
{
    int w = blockIdx.x * 256 + threadIdx.x;
    float w0, w1;
    uint *dh, *dl;
    size_t oidx;
    if (w < 196608) {                    // six 256x128 matrices
        int r = w >> 15;
        int idx = w & 32767;
        int u = idx >> 7, k2 = idx & 127;
        int k = k2 * 2;
        oidx = (size_t)u * 128 + k2;
        switch (r) {
        case 0: {
            float s0 = rsqrtf(bn_v[k] + EPS_) * bn_g[k];
            float s1 = rsqrtf(bn_v[k+1] + EPS_) * bn_g[k+1];
            w0 = s0 * pin_w[k*256 + u]; w1 = s1 * pin_w[(k+1)*256 + u];
            dh = d_Wpin_h; dl = d_Wpin_l; } break;
        case 1:
            w0 = ln1_g[k] * q_w[k*256 + u]; w1 = ln1_g[k+1] * q_w[(k+1)*256 + u];
            dh = d_Wq1_h; dl = d_Wq1_l; break;
        case 2:
            w0 = ln2_g[k] * q_w[k*256 + u]; w1 = ln2_g[k+1] * q_w[(k+1)*256 + u];
            dh = d_Wq2_h; dl = d_Wq2_l; break;
        case 3:
            w0 = k_w[k*256 + u]; w1 = k_w[(k+1)*256 + u];
            dh = d_Wk_h; dl = d_Wk_l; break;
        case 4:
            w0 = v_w[k*256 + u]; w1 = v_w[(k+1)*256 + u];
            dh = d_Wv_h; dl = d_Wv_l; break;
        default:
            w0 = pout_w[k*256 + u]; w1 = pout_w[(k+1)*256 + u];
            dh = d_Wpout_h; dl = d_Wpout_l; break;
        }
    } else if (w < 327680) {             // ff1: 1024 x 128
        int idx = w - 196608;
        int u = idx >> 7, k2 = idx & 127;
        int k = k2 * 2;
        oidx = (size_t)u * 128 + k2;
        w0 = ln3_g[k] * ff1_w[k*1024 + u]; w1 = ln3_g[k+1] * ff1_w[(k+1)*1024 + u];
        dh = d_Wff1_h; dl = d_Wff1_l;
    } else {                             // ff2: 256 x 512
        int idx = w - 327680;
        int u = idx >> 9, k2 = idx & 511;
        int k = k2 * 2;
        oidx = (size_t)u * 512 + k2;
        w0 = ff2_w[k*256 + u]; w1 = ff2_w[(k+1)*256 + u];
        dh = d_Wff2_h; dl = d_Wff2_l;
    }
    uint hi, lo; split_pair(w0, w1, hi, lo);
    dh[oidx] = hi; dl[oidx] = lo;
}

// ---------------- prep biases ------------------------------------------------
__global__ void __launch_bounds__(256) prep_bias(
    const float* __restrict__ bn_g, const float* __restrict__ bn_b,
    const float* __restrict__ bn_m, const float* __restrict__ bn_v,
    const float* __restrict__ ln1_b, const float* __restrict__ ln2_b,
    const float* __restrict__ ln3_b,
    const float* __restrict__ pin_w, const float* __restrict__ pin_b,
    const float* __restrict__ q_w,  const float* __restrict__ q_b,
    const float* __restrict__ ff1_w, const float* __restrict__ ff1_b)
{
    int idx = blockIdx.x * 256 + threadIdx.x;
    if (idx < 256) {
        int u = idx; float acc = pin_b[u];
        for (int k = 0; k < 256; k++) {
            float sc = rsqrtf(bn_v[k] + EPS_) * bn_g[k];
            float sh = bn_b[k] - bn_m[k] * sc;
            acc += sh * pin_w[k*256 + u];
        }
        d_bpin[u] = acc;
    } else if (idx < 512) {
        int u = idx - 256; float acc = q_b[u];
        for (int k = 0; k < 256; k++) acc += ln1_b[k] * q_w[k*256 + u];
        d_bq1[u] = acc;
    } else if (idx < 768) {
        int u = idx - 512; float acc = q_b[u];
        for (int k = 0; k < 256; k++) acc += ln2_b[k] * q_w[k*256 + u];
        d_bq2[u] = acc;
    } else if (idx < 1792) {
        int u = idx - 768; float acc = ff1_b[u];
        for (int k = 0; k < 256; k++) acc += ln3_b[k] * ff1_w[k*1024 + u];
        d_bff1[u] = acc;
    }
}

// ---------------- convert x / context to planes (fused) ---------------------
__global__ void cvt_planes2(const float* __restrict__ x, const float* __restrict__ ctx,
                            uint* __restrict__ xhi, uint* __restrict__ xlo,
                            uint* __restrict__ chi, uint* __restrict__ clo, int nwords)
{
    int i = blockIdx.x * blockDim.x + threadIdx.x;
    if (i < nwords) {
        const float* s = blockIdx.y ? ctx : x;
        uint* ph = blockIdx.y ? chi : xhi;
        uint* pl = blockIdx.y ? clo : xlo;
        float2 f = ((const float2*)s)[i];
        uint h, l; split_pair(f.x, f.y, h, l);
        ph[i] = h; pl[i] = l;
    }
}

// ---------------- tensor-core batched GEMM (bf16x3, cp.async pipelined) -----
struct GOp {
    const uint* Ahi; const uint* Alo;
    const uint* Whi; const uint* Wlo;
    const float* bias; const float* resid;
    float* out; uint* Ohi; uint* Olo;
    int N; int K; int flags; int tileStart;
};
struct GBatch { GOp op[8]; int nops; };

__global__ void __launch_bounds__(128) gemmT(GBatch P)
{
    __shared__ __align__(16) uint As_hi[2][64][12], As_lo[2][64][12];
    __shared__ __align__(16) uint Ws_hi[2][64][12], Ws_lo[2][64][12];

    int bid = blockIdx.x;
    int sel = 0;
    #pragma unroll
    for (int i = 1; i < 8; i++)
        if (i < P.nops && bid >= P.op[i].tileStart) sel = i;
    GOp g = P.op[sel];

    int local = bid - g.tileStart;
    int ntn = g.N >> 6;
    int mt = local / ntn;
    int nt = local - mt * ntn;
    int m0 = mt * 64, n0 = nt * 64;
    int tid = threadIdx.x;
    int warp = tid >> 5, lane = tid & 31;
    int gq = lane >> 2, t = lane & 3;
    int K2 = g.K >> 1;

    float acc[8][4];
    #pragma unroll
    for (int j = 0; j < 8; j++)
        #pragma unroll
        for (int i = 0; i < 4; i++) acc[j][i] = 0.f;

    int frow = tid >> 1;
    int fhf  = (tid & 1) * 4;
    const size_t abase = (size_t)(m0 + frow) * K2 + fhf;
    const size_t wbase = (size_t)(n0 + frow) * K2 + fhf;

    int nc = K2 >> 3;   // chunks of 8 words (k16)

    // prefetch chunk 0 -> buf 0
    cp16(sa(&As_hi[0][frow][fhf]), g.Ahi + abase);
    cp16(sa(&As_lo[0][frow][fhf]), g.Alo + abase);
    cp16(sa(&Ws_hi[0][frow][fhf]), g.Whi + wbase);
    cp16(sa(&Ws_lo[0][frow][fhf]), g.Wlo + wbase);
    CP_COMMIT();

    for (int c = 0; c < nc; c++) {
        CP_WAIT0();
        __syncthreads();
        if (c + 1 < nc) {
            int nb = (c + 1) & 1;
            size_t off = (size_t)(c + 1) * 8;
            cp16(sa(&As_hi[nb][frow][fhf]), g.Ahi + abase + off);
            cp16(sa(&As_lo[nb][frow][fhf]), g.Alo + abase + off);
            cp16(sa(&Ws_hi[nb][frow][fhf]), g.Whi + wbase + off);
            cp16(sa(&Ws_lo[nb][frow][fhf]), g.Wlo + wbase + off);
            CP_COMMIT();
        }
        int bb = c & 1;
        int rs = warp * 16;
        uint a0h = As_hi[bb][rs+gq  ][t  ], a1h = As_hi[bb][rs+gq+8][t  ];
        uint a2h = As_hi[bb][rs+gq  ][t+4], a3h = As_hi[bb][rs+gq+8][t+4];
        uint a0l = As_lo[bb][rs+gq  ][t  ], a1l = As_lo[bb][rs+gq+8][t  ];
        uint a2l = As_lo[bb][rs+gq  ][t+4], a3l = As_lo[bb][rs+gq+8][t+4];

        #pragma unroll
        for (int j = 0; j < 8; j++) {
            int n = j*8 + gq;
            uint b0h = Ws_hi[bb][n][t], b1h = Ws_hi[bb][n][t+4];
            uint b0l = Ws_lo[bb][n][t], b1l = Ws_lo[bb][n][t+4];
            mma_bf16(acc[j], a0h, a1h, a2h, a3h, b0h, b1h);
            mma_bf16(acc[j], a0h, a1h, a2h, a3h, b0l, b1l);
            mma_bf16(acc[j], a0l, a1l, a2l, a3l, b0h, b1h);
        }
    }

    int K2o = g.N >> 1;
    int r0 = m0 + warp*16 + gq;
    int r1 = r0 + 8;
    #pragma unroll
    for (int j = 0; j < 8; j++) {
        int c0 = n0 + j*8 + 2*t;
        float b0 = g.bias[c0], b1 = g.bias[c0+1];
        float v00 = acc[j][0] + b0, v01 = acc[j][1] + b1;
        float v10 = acc[j][2] + b0, v11 = acc[j][3] + b1;
        if (g.flags & FRELU) {
            v00 = fmaxf(v00, 0.f); v01 = fmaxf(v01, 0.f);
            v10 = fmaxf(v10, 0.f); v11 = fmaxf(v11, 0.f);
        }
        if (g.flags & FRESID) {
            float2 ra = *(const float2*)&g.resid[(size_t)r0*g.N + c0];
            float2 rb = *(const float2*)&g.resid[(size_t)r1*g.N + c0];
            v00 += ra.x; v01 += ra.y; v10 += rb.x; v11 += rb.y;
        }
        if (g.flags & FOUT) {
            *(float2*)&g.out[(size_t)r0*g.N + c0] = make_float2(v00, v01);
            *(float2*)&g.out[(size_t)r1*g.N + c0] = make_float2(v10, v11);
        }
        if (g.flags & FPLANES) {
            uint h, l;
            split_pair(v00, v01, h, l);
            g.Ohi[(size_t)r0*K2o + (c0>>1)] = h; g.Olo[(size_t)r0*K2o + (c0>>1)] = l;
            split_pair(v10, v11, h, l);
            g.Ohi[(size_t)r1*K2o + (c0>>1)] = h; g.Olo[(size_t)r1*K2o + (c0>>1)] = l;
        }
    }
}

// ---------------- LayerNorm (normalize only) -> planes ----------------------
__global__ void __launch_bounds__(256) lnorm_kernel(const float* __restrict__ h,
                                                    uint* __restrict__ nhi,
                                                    uint* __restrict__ nlo)
{
    int row = blockIdx.x;
    int tid = threadIdx.x;
    float v = h[(size_t)row * 256 + tid];
    __shared__ float red[8];
    float s = v;
    #pragma unroll
    for (int o = 16; o > 0; o >>= 1) s += __shfl_xor_sync(0xffffffffu, s, o);
    if ((tid & 31) == 0) red[tid >> 5] = s;
    __syncthreads();
    float tot = 0.f;
    #pragma unroll
    for (int i = 0; i < 8; i++) tot += red[i];
    float mu = tot * (1.f / 256.f);
    float d = v - mu;
    float s2 = d * d;
    #pragma unroll
    for (int o = 16; o > 0; o >>= 1) s2 += __shfl_xor_sync(0xffffffffu, s2, o);
    __syncthreads();
    if ((tid & 31) == 0) red[tid >> 5] = s2;
    __syncthreads();
    float tot2 = 0.f;
    #pragma unroll
    for (int i = 0; i < 8; i++) tot2 += red[i];
    float var = tot2 * (1.f / 256.f);
    float o = d * rsqrtf(var + EPS_);
    float pn = __shfl_xor_sync(0xffffffffu, o, 1);
    if (!(tid & 1)) {
        uint hi, lo; split_pair(o, pn, hi, lo);
        nhi[(size_t)row * 128 + (tid >> 1)] = hi;
        nlo[(size_t)row * 128 + (tid >> 1)] = lo;
    }
}

// ---------------- V transpose into packed key-pair planes -------------------
__global__ void __launch_bounds__(128) vplanes_T(
    const float* __restrict__ V1, const float* __restrict__ V2,
    uint* __restrict__ vthi, uint* __restrict__ vtlo)
{
    __shared__ float Vs[64][33];
    int tid = threadIdx.x;
    int kt = blockIdx.x;
    int head = blockIdx.y;
    int br = blockIdx.z >> 1, b = blockIdx.z & 1;
    const float* V = br ? V2 : V1;
    #pragma unroll
    for (int i = 0; i < 4; i++) {
        int idx = tid + i * 128;
        int key = idx >> 3, f4 = (idx & 7) * 4;
        const float* p = &V[(size_t)(b * L_ + kt * 64 + key) * 256 + head * 32 + f4];
        float4 t4 = *(const float4*)p;
        Vs[key][f4] = t4.x; Vs[key][f4+1] = t4.y;
        Vs[key][f4+2] = t4.z; Vs[key][f4+3] = t4.w;
    }
    __syncthreads();
    int g = (br * 2 + b) * 8 + head;
    #pragma unroll
    for (int i = 0; i < 8; i++) {
        int widx = tid + i * 128;
        int d = widx >> 5, kp = widx & 31;
        uint hi, lo;
        split_pair(Vs[2*kp][d], Vs[2*kp+1][d], hi, lo);
        size_t o = ((size_t)g * 32 + d) * 864 + kt * 32 + kp;
        vthi[o] = hi; vtlo[o] = lo;
    }
}

// ---------------- tensor-core flash attention (cp.async pipelined) ----------
__global__ void __launch_bounds__(128) attn_mma(
    const uint* __restrict__ Q1hi, const uint* __restrict__ Q1lo,
    const uint* __restrict__ K1hi, const uint* __restrict__ K1lo,
    const uint* __restrict__ Q2hi, const uint* __restrict__ Q2lo,
    const uint* __restrict__ K2hi, const uint* __restrict__ K2lo,
    const uint* __restrict__ VThi, const uint* __restrict__ VTlo,
    float* __restrict__ O1, float* __restrict__ O2)
{
    __shared__ __align__(16) uint Khi[2][64][20], Klo[2][64][20];
    __shared__ __align__(16) uint Vhi[2][32][36], Vlo[2][32][36];

    int tid = threadIdx.x, warp = tid >> 5, lane = tid & 31;
    int gq = lane >> 2, t = lane & 3;
    int qt = blockIdx.x, head = blockIdx.y;
    int br = blockIdx.z >> 1, b = blockIdx.z & 1;
    const uint* Qhi = br ? Q2hi : Q1hi;
    const uint* Qlo = br ? Q2lo : Q1lo;
    const uint* KhG = br ? K2hi : K1hi;
    const uint* KlG = br ? K2lo : K1lo;
    float* Ob = br ? O2 : O1;
    const float scale = 0.0625f;

    int vg = (br * 2 + b) * 8 + head;

    // fill-pattern indices
    int fkey = tid >> 1;
    int fkw  = (tid & 1) * 8;
    int fd   = tid >> 2;
    int fvw  = (tid & 3) * 8;
    const size_t kbase = (size_t)(b * L_ + fkey) * 128 + head * 16 + fkw;
    const size_t vbase = ((size_t)vg * 32 + fd) * 864 + fvw;

    // prefetch key tile 0
    {
        cp16(sa(&Khi[0][fkey][fkw]),   KhG + kbase);
        cp16(sa(&Khi[0][fkey][fkw+4]), KhG + kbase + 4);
        cp16(sa(&Klo[0][fkey][fkw]),   KlG + kbase);
        cp16(sa(&Klo[0][fkey][fkw+4]), KlG + kbase + 4);
        cp16(sa(&Vhi[0][fd][fvw]),     VThi + vbase);
        cp16(sa(&Vhi[0][fd][fvw+4]),   VThi + vbase + 4);
        cp16(sa(&Vlo[0][fd][fvw]),     VTlo + vbase);
        cp16(sa(&Vlo[0][fd][fvw+4]),   VTlo + vbase + 4);
        CP_COMMIT();
    }

    int r0 = qt * 64 + warp * 16 + gq;
    int r1 = r0 + 8;

    uint qh[2][4], ql[2][4];
    {
        size_t q0 = (size_t)(b * L_ + r0) * 128 + head * 16;
        size_t q1 = (size_t)(b * L_ + r1) * 128 + head * 16;
        #pragma unroll
        for (int ks = 0; ks < 2; ks++) {
            qh[ks][0] = Qhi[q0 + ks*8 + t];     qh[ks][1] = Qhi[q1 + ks*8 + t];
            qh[ks][2] = Qhi[q0 + ks*8 + t + 4]; qh[ks][3] = Qhi[q1 + ks*8 + t + 4];
            ql[ks][0] = Qlo[q0 + ks*8 + t];     ql[ks][1] = Qlo[q1 + ks*8 + t];
            ql[ks][2] = Qlo[q0 + ks*8 + t + 4]; ql[ks][3] = Qlo[q1 + ks*8 + t + 4];
        }
    }

    float Oacc[4][4];
    #pragma unroll
    for (int j = 0; j < 4; j++)
        #pragma unroll
        for (int i = 0; i < 4; i++) Oacc[j][i] = 0.f;
    float m0r = -1e30f, m1r = -1e30f, l0r = 0.f, l1r = 0.f;

    for (int kt = 0; kt < NKT; kt++) {
        CP_WAIT0();
        __syncthreads();
        if (kt + 1 < NKT) {
            int nb = (kt + 1) & 1;
            size_t ko = kbase + (size_t)(kt + 1) * 64 * 128;
            size_t vo = vbase + (size_t)(kt + 1) * 32;
            cp16(sa(&Khi[nb][fkey][fkw]),   KhG + ko);
            cp16(sa(&Khi[nb][fkey][fkw+4]), KhG + ko + 4);
            cp16(sa(&Klo[nb][fkey][fkw]),   KlG + ko);
            cp16(sa(&Klo[nb][fkey][fkw+4]), KlG + ko + 4);
            cp16(sa(&Vhi[nb][fd][fvw]),     VThi + vo);
            cp16(sa(&Vhi[nb][fd][fvw+4]),   VThi + vo + 4);
            cp16(sa(&Vlo[nb][fd][fvw]),     VTlo + vo);
            cp16(sa(&Vlo[nb][fd][fvw+4]),   VTlo + vo + 4);
            CP_COMMIT();
        }
        int bb = kt & 1;

        // S = Q K^T
        float s[8][4];
        #pragma unroll
        for (int j = 0; j < 8; j++) {
            s[j][0] = s[j][1] = s[j][2] = s[j][3] = 0.f;
            int n = j * 8 + gq;
            #pragma unroll
            for (int ks = 0; ks < 2; ks++) {
                uint b0h = Khi[bb][n][ks*8 + t], b1h = Khi[bb][n][ks*8 + t + 4];
                uint b0l = Klo[bb][n][ks*8 + t], b1l = Klo[bb][n][ks*8 + t + 4];
                mma_bf16(s[j], qh[ks][0], qh[ks][1], qh[ks][2], qh[ks][3], b0h, b1h);
                mma_bf16(s[j], qh[ks][0], qh[ks][1], qh[ks][2], qh[ks][3], b0l, b1l);
                mma_bf16(s[j], ql[ks][0], ql[ks][1], ql[ks][2], ql[ks][3], b0h, b1h);
            }
            s[j][0] *= scale; s[j][1] *= scale;
            s[j][2] *= scale; s[j][3] *= scale;
        }

        // online softmax
        float mx0 = -1e30f, mx1 = -1e30f;
        #pragma unroll
        for (int j = 0; j < 8; j++) {
            mx0 = fmaxf(mx0, fmaxf(s[j][0], s[j][1]));
            mx1 = fmaxf(mx1, fmaxf(s[j][2], s[j][3]));
        }
        mx0 = fmaxf(mx0, __shfl_xor_sync(0xffffffffu, mx0, 1));
        mx0 = fmaxf(mx0, __shfl_xor_sync(0xffffffffu, mx0, 2));
        mx1 = fmaxf(mx1, __shfl_xor_sync(0xffffffffu, mx1, 1));
        mx1 = fmaxf(mx1, __shfl_xor_sync(0xffffffffu, mx1, 2));
        float nm0 = fmaxf(m0r, mx0), nm1 = fmaxf(m1r, mx1);
        float c0 = __expf(m0r - nm0), c1 = __expf(m1r - nm1);

        float ls0 = 0.f, ls1 = 0.f;
        #pragma unroll
        for (int j = 0; j < 8; j++) {
            s[j][0] = __expf(s[j][0] - nm0); ls0 += s[j][0];
            s[j][1] = __expf(s[j][1] - nm0); ls0 += s[j][1];
            s[j][2] = __expf(s[j][2] - nm1); ls1 += s[j][2];
            s[j][3] = __expf(s[j][3] - nm1); ls1 += s[j][3];
        }
        ls0 += __shfl_xor_sync(0xffffffffu, ls0, 1);
        ls0 += __shfl_xor_sync(0xffffffffu, ls0, 2);
        ls1 += __shfl_xor_sync(0xffffffffu, ls1, 1);
        ls1 += __shfl_xor_sync(0xffffffffu, ls1, 2);
        l0r = l0r * c0 + ls0;
        l1r = l1r * c1 + ls1;
        m0r = nm0; m1r = nm1;

        #pragma unroll
        for (int jn = 0; jn < 4; jn++) {
            Oacc[jn][0] *= c0; Oacc[jn][1] *= c0;
            Oacc[jn][2] *= c1; Oacc[jn][3] *= c1;
        }

        // P -> bf16x2 A fragments
        uint ph[4][4], pl[4][4];
        #pragma unroll
        for (int ks = 0; ks < 4; ks++) {
            split_pair(s[2*ks  ][0], s[2*ks  ][1], ph[ks][0], pl[ks][0]);
            split_pair(s[2*ks  ][2], s[2*ks  ][3], ph[ks][1], pl[ks][1]);
            split_pair(s[2*ks+1][0], s[2*ks+1][1], ph[ks][2], pl[ks][2]);
            split_pair(s[2*ks+1][2], s[2*ks+1][3], ph[ks][3], pl[ks][3]);
        }

        // O += P V
        #pragma unroll
        for (int jn = 0; jn < 4; jn++) {
            int n = jn * 8 + gq;
            #pragma unroll
            for (int ks = 0; ks < 4; ks++) {
                uint b0h = Vhi[bb][n][ks*8 + t], b1h = Vhi[bb][n][ks*8 + t + 4];
                uint b0l = Vlo[bb][n][ks*8 + t], b1l = Vlo[bb][n][ks*8 + t + 4];
                mma_bf16(Oacc[jn], ph[ks][0], ph[ks][1], ph[ks][2], ph[ks][3], b0h, b1h);
                mma_bf16(Oacc[jn], ph[ks][0], ph[ks][1], ph[ks][2], ph[ks][3], b0l, b1l);
                mma_bf16(Oacc[jn], pl[ks][0], pl[ks][1], pl[ks][2], pl[ks][3], b0h, b1h);
            }
        }
    }

    float inv0 = 1.f / l0r, inv1 = 1.f / l1r;
    #pragma unroll
    for (int jn = 0; jn < 4; jn++) {
        int col = head * 32 + jn * 8 + 2 * t;
        *(float2*)&Ob[(size_t)(b * L_ + r0) * 256 + col] =
            make_float2(Oacc[jn][0] * inv0, Oacc[jn][1] * inv0);
        *(float2*)&Ob[(size_t)(b * L_ + r1) * 256 + col] =
            make_float2(Oacc[jn][2] * inv1, Oacc[jn][3] * inv1);
    }
}

// ---------------- combine: acc = h + ffo + O1 + O2 (+planes) ----------------
__global__ void __launch_bounds__(256) combine_kernel(
    const float* __restrict__ O1, const float* __restrict__ O2,
    const float* __restrict__ h, const float* __restrict__ ffo,
    float* __restrict__ acc, uint* __restrict__ ahi, uint* __restrict__ alo)
{
    int tok = blockIdx.x;
    int u = threadIdx.x;
    size_t i = (size_t)tok * 256 + u;
    float o = h[i] + ffo[i] + O1[i] + O2[i];
    acc[i] = o;
    float pn = __shfl_xor_sync(0xffffffffu, o, 1);
    if (!(u & 1)) {
        uint hi, lo; split_pair(o, pn, hi, lo);
        ahi[(size_t)tok * 128 + (u >> 1)] = hi;
        alo[(size_t)tok * 128 + (u >> 1)] = lo;
    }
}

// ---------------- launch -----------------------------------------------------
extern "C" void kernel_launch(void* const* d_in, const int* in_sizes, int n_in,
                              void* d_out, int out_size)
{
    const float* x       = (const float*)d_in[0];
    const float* context = (const float*)d_in[1];
    const float* bn_g = (const float*)d_in[2];
    const float* bn_b = (const float*)d_in[3];
    const float* bn_m = (const float*)d_in[4];
    const float* bn_v = (const float*)d_in[5];
    const float* ln1_g = (const float*)d_in[6];
    const float* ln1_b = (const float*)d_in[7];
    const float* ln2_g = (const float*)d_in[8];
    const float* ln2_b = (const float*)d_in[9];
    const float* ln3_g = (const float*)d_in[10];
    const float* ln3_b = (const float*)d_in[11];
    const float* pin_w = (const float*)d_in[12];
    const float* pin_b = (const float*)d_in[13];
    const float* q_w   = (const float*)d_in[14];
    const float* q_b   = (const float*)d_in[15];
    const float* k_w   = (const float*)d_in[16];
    const float* k_b   = (const float*)d_in[17];
    const float* v_w   = (const float*)d_in[18];
    const float* v_b   = (const float*)d_in[19];
    const float* ff1_w = (const float*)d_in[20];
    const float* ff1_b = (const float*)d_in[21];
    const float* ff2_w = (const float*)d_in[22];
    const float* ff2_b = (const float*)d_in[23];
    const float* pout_w = (const float*)d_in[24];
    const float* pout_b = (const float*)d_in[25];
    float* out = (float*)d_out;

    float *p_h, *p_v1, *p_v2, *p_ffo, *p_acc, *p_O1, *p_O2;
    uint *p_xhi, *p_xlo, *p_cthi, *p_ctlo, *p_hhi, *p_hlo, *p_nhi, *p_nlo;
    uint *p_f1hi, *p_f1lo, *p_ahi, *p_alo;
    uint *p_q1hi, *p_q1lo, *p_k1hi, *p_k1lo, *p_q2hi, *p_q2lo, *p_k2hi, *p_k2lo;
    uint *p_vthi, *p_vtlo;
    uint *w_pin_h, *w_pin_l, *w_q1_h, *w_q1_l, *w_q2_h, *w_q2_l;
    uint *w_k_h, *w_k_l, *w_v_h, *w_v_l, *w_po_h, *w_po_l;
    uint *w_f1_h, *w_f1_l, *w_f2_h, *w_f2_l;
    float *p_bpin, *p_bq1, *p_bq2, *p_bff1;

    cudaGetSymbolAddress((void**)&p_h,    d_h);
    cudaGetSymbolAddress((void**)&p_v1,   d_v1);
    cudaGetSymbolAddress((void**)&p_v2,   d_v2);
    cudaGetSymbolAddress((void**)&p_ffo,  d_ffo);
    cudaGetSymbolAddress((void**)&p_acc,  d_acc);
    cudaGetSymbolAddress((void**)&p_O1,   d_O1);
    cudaGetSymbolAddress((void**)&p_O2,   d_O2);
    cudaGetSymbolAddress((void**)&p_xhi,  d_xhi);
    cudaGetSymbolAddress((void**)&p_xlo,  d_xlo);
    cudaGetSymbolAddress((void**)&p_cthi, d_cthi);
    cudaGetSymbolAddress((void**)&p_ctlo, d_ctlo);
    cudaGetSymbolAddress((void**)&p_hhi,  d_hhi);
    cudaGetSymbolAddress((void**)&p_hlo,  d_hlo);
    cudaGetSymbolAddress((void**)&p_nhi,  d_nhi);
    cudaGetSymbolAddress((void**)&p_nlo,  d_nlo);
    cudaGetSymbolAddress((void**)&p_f1hi, d_f1hi);
    cudaGetSymbolAddress((void**)&p_f1lo, d_f1lo);
    cudaGetSymbolAddress((void**)&p_ahi,  d_ahi);
    cudaGetSymbolAddress((void**)&p_alo,  d_alo);
    cudaGetSymbolAddress((void**)&p_q1hi, d_q1hi);
    cudaGetSymbolAddress((void**)&p_q1lo, d_q1lo);
    cudaGetSymbolAddress((void**)&p_k1hi, d_k1hi);
    cudaGetSymbolAddress((void**)&p_k1lo, d_k1lo);
    cudaGetSymbolAddress((void**)&p_q2hi, d_q2hi);
    cudaGetSymbolAddress((void**)&p_q2lo, d_q2lo);
    cudaGetSymbolAddress((void**)&p_k2hi, d_k2hi);
    cudaGetSymbolAddress((void**)&p_k2lo, d_k2lo);
    cudaGetSymbolAddress((void**)&p_vthi, d_vthi);
    cudaGetSymbolAddress((void**)&p_vtlo, d_vtlo);
    cudaGetSymbolAddress((void**)&w_pin_h, d_Wpin_h);
    cudaGetSymbolAddress((void**)&w_pin_l, d_Wpin_l);
    cudaGetSymbolAddress((void**)&w_q1_h,  d_Wq1_h);
    cudaGetSymbolAddress((void**)&w_q1_l,  d_Wq1_l);
    cudaGetSymbolAddress((void**)&w_q2_h,  d_Wq2_h);
    cudaGetSymbolAddress((void**)&w_q2_l,  d_Wq2_l);
    cudaGetSymbolAddress((void**)&w_k_h,   d_Wk_h);
    cudaGetSymbolAddress((void**)&w_k_l,   d_Wk_l);
    cudaGetSymbolAddress((void**)&w_v_h,   d_Wv_h);
    cudaGetSymbolAddress((void**)&w_v_l,   d_Wv_l);
    cudaGetSymbolAddress((void**)&w_po_h,  d_Wpout_h);
    cudaGetSymbolAddress((void**)&w_po_l,  d_Wpout_l);
    cudaGetSymbolAddress((void**)&w_f1_h,  d_Wff1_h);
    cudaGetSymbolAddress((void**)&w_f1_l,  d_Wff1_l);
    cudaGetSymbolAddress((void**)&w_f2_h,  d_Wff2_h);
    cudaGetSymbolAddress((void**)&w_f2_l,  d_Wff2_l);
    cudaGetSymbolAddress((void**)&p_bpin,  d_bpin);
    cudaGetSymbolAddress((void**)&p_bq1,   d_bq1);
    cudaGetSymbolAddress((void**)&p_bq2,   d_bq2);
    cudaGetSymbolAddress((void**)&p_bff1,  d_bff1);

    // 1. fold + convert weights (parallel) + biases
    prep_w<<<1792, 256>>>(bn_g, bn_v, ln1_g, ln2_g, ln3_g,
                          pin_w, q_w, k_w, v_w, ff1_w, ff2_w, pout_w);
    prep_bias<<<7, 256>>>(bn_g, bn_b, bn_m, bn_v, ln1_b, ln2_b, ln3_b,
                          pin_w, pin_b, q_w, q_b, ff1_w, ff1_b);

    // 2. x / context planes (fused)
    {
        int nw = NTOK * 128;
        dim3 gc((nw + 255) / 256, 2);
        cvt_planes2<<<gc, 256>>>(x, context, p_xhi, p_xlo, p_cthi, p_ctlo, nw);
    }

    auto mkop = [](const uint* Ahi, const uint* Alo, const uint* Whi, const uint* Wlo,
                   const float* bias, const float* resid, float* o,
                   uint* Ohi, uint* Olo, int N, int K, int flags, int start) {
        GOp g; g.Ahi = Ahi; g.Alo = Alo; g.Whi = Whi; g.Wlo = Wlo;
        g.bias = bias; g.resid = resid; g.out = o; g.Ohi = Ohi; g.Olo = Olo;
        g.N = N; g.K = K; g.flags = flags; g.tileStart = start;
        return g;
    };
    const int RT = NTOK / 64;          // 54
    const int T256 = RT * 4;           // 216

    // 3. pin: h = relu(x @ Wpin + bpin) -> fp32 + planes
    {
        GBatch P = {};
        P.op[0] = mkop(p_xhi, p_xlo, w_pin_h, w_pin_l, p_bpin, nullptr,
                       p_h, p_hhi, p_hlo, 256, 256, FOUT | FRELU | FPLANES, 0);
        P.nops = 1;
        gemmT<<<T256, 128>>>(P);
    }

    // 4. hhat planes
    lnorm_kernel<<<NTOK, 256>>>(p_h, p_nhi, p_nlo);

    // 5. projections + ff1
    {
        GBatch P = {};
        P.op[0] = mkop(p_nhi, p_nlo, w_q1_h, w_q1_l, p_bq1, nullptr,
                       nullptr, p_q1hi, p_q1lo, 256, 256, FPLANES, 0);
        P.op[1] = mkop(p_hhi, p_hlo, w_k_h, w_k_l, k_b, nullptr,
                       nullptr, p_k1hi, p_k1lo, 256, 256, FPLANES, T256);
        P.op[2] = mkop(p_hhi, p_hlo, w_v_h, w_v_l, v_b, nullptr,
                       p_v1, nullptr, nullptr, 256, 256, FOUT, T256*2);
        P.op[3] = mkop(p_nhi, p_nlo, w_q2_h, w_q2_l, p_bq2, nullptr,
                       nullptr, p_q2hi, p_q2lo, 256, 256, FPLANES, T256*3);
        P.op[4] = mkop(p_cthi, p_ctlo, w_k_h, w_k_l, k_b, nullptr,
                       nullptr, p_k2hi, p_k2lo, 256, 256, FPLANES, T256*4);
        P.op[5] = mkop(p_cthi, p_ctlo, w_v_h, w_v_l, v_b, nullptr,
                       p_v2, nullptr, nullptr, 256, 256, FOUT, T256*5);
        P.op[6] = mkop(p_nhi, p_nlo, w_f1_h, w_f1_l, p_bff1, nullptr,
                       nullptr, p_f1hi, p_f1lo, 1024, 256, FRELU | FPLANES, T256*6);
        P.nops = 7;
        gemmT<<<T256*6 + RT*16, 128>>>(P);
    }

    // 6. V transpose planes
    {
        dim3 gv(NKT, H_, 4);
        vplanes_T<<<gv, 128>>>(p_v1, p_v2, p_vthi, p_vtlo);
    }

    // 7. attention (tensor cores, pipelined)
    {
        dim3 ga(NKT, H_, 4);
        attn_mma<<<ga, 128>>>(p_q1hi, p_q1lo, p_k1hi, p_k1lo,
                              p_q2hi, p_q2lo, p_k2hi, p_k2lo,
                              p_vthi, p_vtlo, p_O1, p_O2);
    }

    // 8. ff2
    {
        GBatch P = {};
        P.op[0] = mkop(p_f1hi, p_f1lo, w_f2_h, w_f2_l, ff2_b, nullptr,
                       p_ffo, nullptr, nullptr, 256, 1024, FOUT, 0);
        P.nops = 1;
        gemmT<<<T256, 128>>>(P);
    }

    // 9. combine -> acc (+planes)
    combine_kernel<<<NTOK, 256>>>(p_O1, p_O2, p_h, p_ffo, p_acc, p_ahi, p_alo);

    // 10. out = relu(acc @ pout + b) + x
    {
        GBatch P = {};
        P.op[0] = mkop(p_ahi, p_alo, w_po_h, w_po_l, pout_b, x,
                       out, nullptr, nullptr, 256, 256, FOUT | FRELU | FRESID, 0);
        P.nops = 1;
        gemmT<<<T256, 128>>>(P);
    }
}

// round 8
// speedup vs baseline: 3.0318x; 1.1480x over previous
#include <cuda_runtime.h>
#include <math.h>

typedef unsigned long long ull;
typedef unsigned int uint;

#define B_    2
#define L_    1728
#define NTOK  3456
#define C_    256
#define U_    256
#define H_    8
#define HD    32
#define FF_   1024
#define EPS_  1e-3f
#define NKT   27          /* 27 key tiles of 64 */

#define FRELU   1
#define FRESID  2
#define FPLANES 4
#define FOUT    8

// ---------------- cp.async helpers ------------------------------------------
__device__ __forceinline__ void cp16(uint saddr, const void* gptr) {
    asm volatile("cp.async.cg.shared.global [%0], [%1], 16;" :: "r"(saddr), "l"(gptr));
}
__device__ __forceinline__ uint sa(const void* p) {
    return (uint)__cvta_generic_to_shared(p);
}
#define CP_COMMIT() asm volatile("cp.async.commit_group;")
#define CP_WAIT0()  asm volatile("cp.async.wait_group 0;")
#define CP_WAIT2()  asm volatile("cp.async.wait_group 2;")

// ---------------- fast exp2 --------------------------------------------------
__device__ __forceinline__ float ex2(float x) {
    float y; asm("ex2.approx.f32 %0,%1;" : "=f"(y) : "f"(x)); return y;
}

// ---------------- bf16 split helpers ---------------------------------------
__device__ __forceinline__ uint bf16_of(float f) {
    unsigned short u; asm("cvt.rn.bf16.f32 %0,%1;" : "=h"(u) : "f"(f));
    return (uint)u;
}
__device__ __forceinline__ void split_pair(float f0, float f1, uint& hi, uint& lo) {
    uint h0 = bf16_of(f0), h1 = bf16_of(f1);
    hi = h0 | (h1 << 16);
    float r0 = f0 - __uint_as_float(h0 << 16);
    float r1 = f1 - __uint_as_float(h1 << 16);
    lo = bf16_of(r0) | (bf16_of(r1) << 16);
}

// ---------------- mma m16n8k16 bf16 -----------------------------------------
__device__ __forceinline__ void mma_bf16(float* c, uint a0, uint a1, uint a2, uint a3,
                                         uint b0, uint b1) {
    asm volatile("mma.sync.aligned.m16n8k16.row.col.f32.bf16.bf16.f32 "
                 "{%0,%1,%2,%3},{%4,%5,%6,%7},{%8,%9},{%0,%1,%2,%3};"
                 : "+f"(c[0]), "+f"(c[1]), "+f"(c[2]), "+f"(c[3])
                 : "r"(a0), "r"(a1), "r"(a2), "r"(a3), "r"(b0), "r"(b1));
}

// ---------------- scratch ---------------------------------------------------
__device__ float d_h   [NTOK*U_];
__device__ float d_v1  [NTOK*U_];
__device__ float d_v2  [NTOK*U_];
__device__ float d_ffo [NTOK*U_];
__device__ float d_acc [NTOK*U_];
__device__ float d_O1  [NTOK*U_];
__device__ float d_O2  [NTOK*U_];

// activation planes ([M][K/2] packed bf16 pairs)
__device__ uint d_xhi [NTOK*128], d_xlo [NTOK*128];
__device__ uint d_cthi[NTOK*128], d_ctlo[NTOK*128];
__device__ uint d_hhi [NTOK*128], d_hlo [NTOK*128];
__device__ uint d_nhi [NTOK*128], d_nlo [NTOK*128];
__device__ uint d_f1hi[NTOK*512], d_f1lo[NTOK*512];
__device__ uint d_ahi [NTOK*128], d_alo [NTOK*128];
__device__ uint d_q1hi[NTOK*128], d_q1lo[NTOK*128];
__device__ uint d_k1hi[NTOK*128], d_k1lo[NTOK*128];
__device__ uint d_q2hi[NTOK*128], d_q2lo[NTOK*128];
__device__ uint d_k2hi[NTOK*128], d_k2lo[NTOK*128];
// V transposed planes: [group=br*2b*8h (32)][hd=32][864 key-pair words]
__device__ uint d_vthi[32*32*864], d_vtlo[32*32*864];

// weight planes (transposed: [N][K/2])
__device__ uint d_Wpin_h[256*128], d_Wpin_l[256*128];
__device__ uint d_Wq1_h [256*128], d_Wq1_l [256*128];
__device__ uint d_Wq2_h [256*128], d_Wq2_l [256*128];
__device__ uint d_Wk_h  [256*128], d_Wk_l  [256*128];
__device__ uint d_Wv_h  [256*128], d_Wv_l  [256*128];
__device__ uint d_Wpout_h[256*128], d_Wpout_l[256*128];
__device__ uint d_Wff1_h[1024*128], d_Wff1_l[1024*128];
__device__ uint d_Wff2_h[256*512],  d_Wff2_l[256*512];

__device__ float d_bpin[U_], d_bq1[U_], d_bq2[U_], d_bff1[FF_];

// ---------------- prep_all: weights + x/ctx planes + biases (one launch) ----
// blocks [0,1792): weight planes; [1792,3520): x planes; [3520,5248): ctx planes;
// [5248,5472): biases (1 warp per output).
__global__ void __launch_bounds__(256) prep_all(
    const float* __restrict__ x,    const float* __restrict__ ctx,
    const float* __restrict__ bn_g, const float* __restrict__ bn_b,
    const float* __restrict__ bn_m, const float* __restrict__ bn_v,
    const float* __restrict__ ln1_g, const float* __restrict__ ln1_b,
    const float* __restrict__ ln2_g, const float* __restrict__ ln2_b,
    const float* __restrict__ ln3_g, const float* __restrict__ ln3_b,
    const float* __restrict__ pin_w, const float* __restrict__ pin_b,
    const float* __restrict__ q_w,  const float* __restrict__ q_b,
    const float* __restrict__ k_w,  const float* __restrict__ v_w,
    const float* __restrict__ ff1_w, const float* __restrict__ ff1_b,
    const float* __restrict__ ff2_w, const float* __restrict__ pout_w)
{
    int blk = blockIdx.x;
    int tid = threadIdx.x;

    if (blk < 1792) {                       // ---- weight planes ----
        int w = blk * 256 + tid;
        float w0, w1;
        uint *dh, *dl;
        size_t oidx;
        if (w < 196608) {
            int r = w >> 15;
            int idx = w & 32767;
            int u = idx >> 7, k2 = idx & 127;
            int k = k2 * 2;
            oidx = (size_t)u * 128 + k2;
            switch (r) {
            case 0: {
                float s0 = rsqrtf(bn_v[k] + EPS_) * bn_g[k];
                float s1 = rsqrtf(bn_v[k+1] + EPS_) * bn_g[k+1];
                w0 = s0 * pin_w[k*256 + u]; w1 = s1 * pin_w[(k+1)*256 + u];
                dh = d_Wpin_h; dl = d_Wpin_l; } break;
            case 1:
                w0 = ln1_g[k] * q_w[k*256 + u]; w1 = ln1_g[k+1] * q_w[(k+1)*256 + u];
                dh = d_Wq1_h; dl = d_Wq1_l; break;
            case 2:
                w0 = ln2_g[k] * q_w[k*256 + u]; w1 = ln2_g[k+1] * q_w[(k+1)*256 + u];
                dh = d_Wq2_h; dl = d_Wq2_l; break;
            case 3:
                w0 = k_w[k*256 + u]; w1 = k_w[(k+1)*256 + u];
                dh = d_Wk_h; dl = d_Wk_l; break;
            case 4:
                w0 = v_w[k*256 + u]; w1 = v_w[(k+1)*256 + u];
                dh = d_Wv_h; dl = d_Wv_l; break;
            default:
                w0 = pout_w[k*256 + u]; w1 = pout_w[(k+1)*256 + u];
                dh = d_Wpout_h; dl = d_Wpout_l; break;
            }
        } else if (w < 327680) {            // ff1: 1024 x 128
            int idx = w - 196608;
            int u = idx >> 7, k2 = idx & 127;
            int k = k2 * 2;
            oidx = (size_t)u * 128 + k2;
            w0 = ln3_g[k] * ff1_w[k*1024 + u]; w1 = ln3_g[k+1] * ff1_w[(k+1)*1024 + u];
            dh = d_Wff1_h; dl = d_Wff1_l;
        } else {                            // ff2: 256 x 512
            int idx = w - 327680;
            int u = idx >> 9, k2 = idx & 511;
            int k = k2 * 2;
            oidx = (size_t)u * 512 + k2;
            w0 = ff2_w[k*256 + u]; w1 = ff2_w[(k+1)*256 + u];
            dh = d_Wff2_h; dl = d_Wff2_l;
        }
        uint hi, lo; split_pair(w0, w1, hi, lo);
        dh[oidx] = hi; dl[oidx] = lo;
    } else if (blk < 5248) {                // ---- activation planes ----
        int rel = blk - 1792;
        const float* s; uint *ph, *pl;
        if (rel < 1728) { s = x; ph = d_xhi; pl = d_xlo; }
        else { rel -= 1728; s = ctx; ph = d_cthi; pl = d_ctlo; }
        int i = rel * 256 + tid;
        float2 f = ((const float2*)s)[i];
        uint h, l; split_pair(f.x, f.y, h, l);
        ph[i] = h; pl[i] = l;
    } else {                                // ---- biases (warp per output) ----
        int gw = (blk - 5248) * 8 + (tid >> 5);   // 0..1791
        int lane = tid & 31;
        float part = 0.f;
        int u;
        if (gw < 256) {
            u = gw;
            for (int k = lane; k < 256; k += 32) {
                float sc = rsqrtf(bn_v[k] + EPS_) * bn_g[k];
                part += (bn_b[k] - bn_m[k] * sc) * pin_w[k*256 + u];
            }
        } else if (gw < 512) {
            u = gw - 256;
            for (int k = lane; k < 256; k += 32) part += ln1_b[k] * q_w[k*256 + u];
        } else if (gw < 768) {
            u = gw - 512;
            for (int k = lane; k < 256; k += 32) part += ln2_b[k] * q_w[k*256 + u];
        } else {
            u = gw - 768;
            for (int k = lane; k < 256; k += 32) part += ln3_b[k] * ff1_w[k*1024 + u];
        }
        #pragma unroll
        for (int o = 16; o > 0; o >>= 1) part += __shfl_xor_sync(0xffffffffu, part, o);
        if (lane == 0) {
            if (gw < 256)      d_bpin[u] = pin_b[u] + part;
            else if (gw < 512) d_bq1[u]  = q_b[u]  + part;
            else if (gw < 768) d_bq2[u]  = q_b[u]  + part;
            else               d_bff1[u] = ff1_b[u] + part;
        }
    }
}

// ---------------- tensor-core batched GEMM (bf16x3, 4-stage cp.async) -------
struct GOp {
    const uint* Ahi; const uint* Alo;
    const uint* Whi; const uint* Wlo;
    const float* bias; const float* resid;
    float* out; uint* Ohi; uint* Olo;
    int N; int K; int flags; int tileStart;
};
struct GBatch { GOp op[8]; int nops; };

__global__ void __launch_bounds__(128) gemmT(GBatch P)
{
    __shared__ __align__(16) uint As_hi[4][64][12], As_lo[4][64][12];
    __shared__ __align__(16) uint Ws_hi[4][64][12], Ws_lo[4][64][12];

    int bid = blockIdx.x;
    int sel = 0;
    #pragma unroll
    for (int i = 1; i < 8; i++)
        if (i < P.nops && bid >= P.op[i].tileStart) sel = i;
    GOp g = P.op[sel];

    int local = bid - g.tileStart;
    int ntn = g.N >> 6;
    int mt = local / ntn;
    int nt = local - mt * ntn;
    int m0 = mt * 64, n0 = nt * 64;
    int tid = threadIdx.x;
    int warp = tid >> 5, lane = tid & 31;
    int gq = lane >> 2, t = lane & 3;
    int K2 = g.K >> 1;

    float acc[8][4];
    #pragma unroll
    for (int j = 0; j < 8; j++)
        #pragma unroll
        for (int i = 0; i < 4; i++) acc[j][i] = 0.f;

    int frow = tid >> 1;
    int fhf  = (tid & 1) * 4;
    const size_t abase = (size_t)(m0 + frow) * K2 + fhf;
    const size_t wbase = (size_t)(n0 + frow) * K2 + fhf;

    int nc = K2 >> 3;   // K16 chunks

    #pragma unroll
    for (int s = 0; s < 3; s++) {
        if (s < nc) {
            size_t off = (size_t)s * 8;
            cp16(sa(&As_hi[s][frow][fhf]), g.Ahi + abase + off);
            cp16(sa(&As_lo[s][frow][fhf]), g.Alo + abase + off);
            cp16(sa(&Ws_hi[s][frow][fhf]), g.Whi + wbase + off);
            cp16(sa(&Ws_lo[s][frow][fhf]), g.Wlo + wbase + off);
        }
        CP_COMMIT();
    }

    for (int c = 0; c < nc; c++) {
        CP_WAIT2();
        __syncthreads();
        int pc = c + 3;
        if (pc < nc) {
            int nb = pc & 3;
            size_t off = (size_t)pc * 8;
            cp16(sa(&As_hi[nb][frow][fhf]), g.Ahi + abase + off);
            cp16(sa(&As_lo[nb][frow][fhf]), g.Alo + abase + off);
            cp16(sa(&Ws_hi[nb][frow][fhf]), g.Whi + wbase + off);
            cp16(sa(&Ws_lo[nb][frow][fhf]), g.Wlo + wbase + off);
        }
        CP_COMMIT();

        int bb = c & 3;
        int rs = warp * 16;
        uint a0h = As_hi[bb][rs+gq  ][t  ], a1h = As_hi[bb][rs+gq+8][t  ];
        uint a2h = As_hi[bb][rs+gq  ][t+4], a3h = As_hi[bb][rs+gq+8][t+4];
        uint a0l = As_lo[bb][rs+gq  ][t  ], a1l = As_lo[bb][rs+gq+8][t  ];
        uint a2l = As_lo[bb][rs+gq  ][t+4], a3l = As_lo[bb][rs+gq+8][t+4];

        #pragma unroll
        for (int j = 0; j < 8; j++) {
            int n = j*8 + gq;
            uint b0h = Ws_hi[bb][n][t], b1h = Ws_hi[bb][n][t+4];
            uint b0l = Ws_lo[bb][n][t], b1l = Ws_lo[bb][n][t+4];
            mma_bf16(acc[j], a0h, a1h, a2h, a3h, b0h, b1h);
            mma_bf16(acc[j], a0h, a1h, a2h, a3h, b0l, b1l);
            mma_bf16(acc[j], a0l, a1l, a2l, a3l, b0h, b1h);
        }
    }

    int K2o = g.N >> 1;
    int r0 = m0 + warp*16 + gq;
    int r1 = r0 + 8;
    #pragma unroll
    for (int j = 0; j < 8; j++) {
        int c0 = n0 + j*8 + 2*t;
        float b0 = g.bias[c0], b1 = g.bias[c0+1];
        float v00 = acc[j][0] + b0, v01 = acc[j][1] + b1;
        float v10 = acc[j][2] + b0, v11 = acc[j][3] + b1;
        if (g.flags & FRELU) {
            v00 = fmaxf(v00, 0.f); v01 = fmaxf(v01, 0.f);
            v10 = fmaxf(v10, 0.f); v11 = fmaxf(v11, 0.f);
        }
        if (g.flags & FRESID) {
            float2 ra = *(const float2*)&g.resid[(size_t)r0*g.N + c0];
            float2 rb = *(const float2*)&g.resid[(size_t)r1*g.N + c0];
            v00 += ra.x; v01 += ra.y; v10 += rb.x; v11 += rb.y;
        }
        if (g.flags & FOUT) {
            *(float2*)&g.out[(size_t)r0*g.N + c0] = make_float2(v00, v01);
            *(float2*)&g.out[(size_t)r1*g.N + c0] = make_float2(v10, v11);
        }
        if (g.flags & FPLANES) {
            uint h, l;
            split_pair(v00, v01, h, l);
            g.Ohi[(size_t)r0*K2o + (c0>>1)] = h; g.Olo[(size_t)r0*K2o + (c0>>1)] = l;
            split_pair(v10, v11, h, l);
            g.Ohi[(size_t)r1*K2o + (c0>>1)] = h; g.Olo[(size_t)r1*K2o + (c0>>1)] = l;
        }
    }
}

// ---------------- LayerNorm (normalize only) -> planes ----------------------
__global__ void __launch_bounds__(256) lnorm_kernel(const float* __restrict__ h,
                                                    uint* __restrict__ nhi,
                                                    uint* __restrict__ nlo)
{
    int row = blockIdx.x;
    int tid = threadIdx.x;
    float v = h[(size_t)row * 256 + tid];
    __shared__ float red[8];
    float s = v;
    #pragma unroll
    for (int o = 16; o > 0; o >>= 1) s += __shfl_xor_sync(0xffffffffu, s, o);
    if ((tid & 31) == 0) red[tid >> 5] = s;
    __syncthreads();
    float tot = 0.f;
    #pragma unroll
    for (int i = 0; i < 8; i++) tot += red[i];
    float mu = tot * (1.f / 256.f);
    float d = v - mu;
    float s2 = d * d;
    #pragma unroll
    for (int o = 16; o > 0; o >>= 1) s2 += __shfl_xor_sync(0xffffffffu, s2, o);
    __syncthreads();
    if ((tid & 31) == 0) red[tid >> 5] = s2;
    __syncthreads();
    float tot2 = 0.f;
    #pragma unroll
    for (int i = 0; i < 8; i++) tot2 += red[i];
    float var = tot2 * (1.f / 256.f);
    float o = d * rsqrtf(var + EPS_);
    float pn = __shfl_xor_sync(0xffffffffu, o, 1);
    if (!(tid & 1)) {
        uint hi, lo; split_pair(o, pn, hi, lo);
        nhi[(size_t)row * 128 + (tid >> 1)] = hi;
        nlo[(size_t)row * 128 + (tid >> 1)] = lo;
    }
}

// ---------------- V transpose into packed key-pair planes -------------------
__global__ void __launch_bounds__(128) vplanes_T(
    const float* __restrict__ V1, const float* __restrict__ V2,
    uint* __restrict__ vthi, uint* __restrict__ vtlo)
{
    __shared__ float Vs[64][33];
    int tid = threadIdx.x;
    int kt = blockIdx.x;
    int head = blockIdx.y;
    int br = blockIdx.z >> 1, b = blockIdx.z & 1;
    const float* V = br ? V2 : V1;
    #pragma unroll
    for (int i = 0; i < 4; i++) {
        int idx = tid + i * 128;
        int key = idx >> 3, f4 = (idx & 7) * 4;
        const float* p = &V[(size_t)(b * L_ + kt * 64 + key) * 256 + head * 32 + f4];
        float4 t4 = *(const float4*)p;
        Vs[key][f4] = t4.x; Vs[key][f4+1] = t4.y;
        Vs[key][f4+2] = t4.z; Vs[key][f4+3] = t4.w;
    }
    __syncthreads();
    int g = (br * 2 + b) * 8 + head;
    #pragma unroll
    for (int i = 0; i < 8; i++) {
        int widx = tid + i * 128;
        int d = widx >> 5, kp = widx & 31;
        uint hi, lo;
        split_pair(Vs[2*kp][d], Vs[2*kp+1][d], hi, lo);
        size_t o = ((size_t)g * 32 + d) * 864 + kt * 32 + kp;
        vthi[o] = hi; vtlo[o] = lo;
    }
}

// ---------------- tensor-core flash attention (cp.async, exp2 softmax) ------
__global__ void __launch_bounds__(128) attn_mma(
    const uint* __restrict__ Q1hi, const uint* __restrict__ Q1lo,
    const uint* __restrict__ K1hi, const uint* __restrict__ K1lo,
    const uint* __restrict__ Q2hi, const uint* __restrict__ Q2lo,
    const uint* __restrict__ K2hi, const uint* __restrict__ K2lo,
    const uint* __restrict__ VThi, const uint* __restrict__ VTlo,
    float* __restrict__ O1, float* __restrict__ O2)
{
    __shared__ __align__(16) uint Khi[2][64][20], Klo[2][64][20];
    __shared__ __align__(16) uint Vhi[2][32][36], Vlo[2][32][36];

    int tid = threadIdx.x, warp = tid >> 5, lane = tid & 31;
    int gq = lane >> 2, t = lane & 3;
    int qt = blockIdx.x, head = blockIdx.y;
    int br = blockIdx.z >> 1, b = blockIdx.z & 1;
    const uint* Qhi = br ? Q2hi : Q1hi;
    const uint* Qlo = br ? Q2lo : Q1lo;
    const uint* KhG = br ? K2hi : K1hi;
    const uint* KlG = br ? K2lo : K1lo;
    float* Ob = br ? O2 : O1;
    const float scale2 = 0.0625f * 1.44269504089f;   // UNITS^-0.5 * log2(e)

    int vg = (br * 2 + b) * 8 + head;

    int fkey = tid >> 1;
    int fkw  = (tid & 1) * 8;
    int fd   = tid >> 2;
    int fvw  = (tid & 3) * 8;
    const size_t kbase = (size_t)(b * L_ + fkey) * 128 + head * 16 + fkw;
    const size_t vbase = ((size_t)vg * 32 + fd) * 864 + fvw;

    {
        cp16(sa(&Khi[0][fkey][fkw]),   KhG + kbase);
        cp16(sa(&Khi[0][fkey][fkw+4]), KhG + kbase + 4);
        cp16(sa(&Klo[0][fkey][fkw]),   KlG + kbase);
        cp16(sa(&Klo[0][fkey][fkw+4]), KlG + kbase + 4);
        cp16(sa(&Vhi[0][fd][fvw]),     VThi + vbase);
        cp16(sa(&Vhi[0][fd][fvw+4]),   VThi + vbase + 4);
        cp16(sa(&Vlo[0][fd][fvw]),     VTlo + vbase);
        cp16(sa(&Vlo[0][fd][fvw+4]),   VTlo + vbase + 4);
        CP_COMMIT();
    }

    int r0 = qt * 64 + warp * 16 + gq;
    int r1 = r0 + 8;

    uint qh[2][4], ql[2][4];
    {
        size_t q0 = (size_t)(b * L_ + r0) * 128 + head * 16;
        size_t q1 = (size_t)(b * L_ + r1) * 128 + head * 16;
        #pragma unroll
        for (int ks = 0; ks < 2; ks++) {
            qh[ks][0] = Qhi[q0 + ks*8 + t];     qh[ks][1] = Qhi[q1 + ks*8 + t];
            qh[ks][2] = Qhi[q0 + ks*8 + t + 4]; qh[ks][3] = Qhi[q1 + ks*8 + t + 4];
            ql[ks][0] = Qlo[q0 + ks*8 + t];     ql[ks][1] = Qlo[q1 + ks*8 + t];
            ql[ks][2] = Qlo[q0 + ks*8 + t + 4]; ql[ks][3] = Qlo[q1 + ks*8 + t + 4];
        }
    }

    float Oacc[4][4];
    #pragma unroll
    for (int j = 0; j < 4; j++)
        #pragma unroll
        for (int i = 0; i < 4; i++) Oacc[j][i] = 0.f;
    float m0r = -1e30f, m1r = -1e30f, l0r = 0.f, l1r = 0.f;

    for (int kt = 0; kt < NKT; kt++) {
        CP_WAIT0();
        __syncthreads();
        if (kt + 1 < NKT) {
            int nb = (kt + 1) & 1;
            size_t ko = kbase + (size_t)(kt + 1) * 64 * 128;
            size_t vo = vbase + (size_t)(kt + 1) * 32;
            cp16(sa(&Khi[nb][fkey][fkw]),   KhG + ko);
            cp16(sa(&Khi[nb][fkey][fkw+4]), KhG + ko + 4);
            cp16(sa(&Klo[nb][fkey][fkw]),   KlG + ko);
            cp16(sa(&Klo[nb][fkey][fkw+4]), KlG + ko + 4);
            cp16(sa(&Vhi[nb][fd][fvw]),     VThi + vo);
            cp16(sa(&Vhi[nb][fd][fvw+4]),   VThi + vo + 4);
            cp16(sa(&Vlo[nb][fd][fvw]),     VTlo + vo);
            cp16(sa(&Vlo[nb][fd][fvw+4]),   VTlo + vo + 4);
            CP_COMMIT();
        }
        int bb = kt & 1;

        // S = Q K^T, scaled into log2 domain
        float s[8][4];
        #pragma unroll
        for (int j = 0; j < 8; j++) {
            s[j][0] = s[j][1] = s[j][2] = s[j][3] = 0.f;
            int n = j * 8 + gq;
            #pragma unroll
            for (int ks = 0; ks < 2; ks++) {
                uint b0h = Khi[bb][n][ks*8 + t], b1h = Khi[bb][n][ks*8 + t + 4];
                uint b0l = Klo[bb][n][ks*8 + t], b1l = Klo[bb][n][ks*8 + t + 4];
                mma_bf16(s[j], qh[ks][0], qh[ks][1], qh[ks][2], qh[ks][3], b0h, b1h);
                mma_bf16(s[j], qh[ks][0], qh[ks][1], qh[ks][2], qh[ks][3], b0l, b1l);
                mma_bf16(s[j], ql[ks][0], ql[ks][1], ql[ks][2], ql[ks][3], b0h, b1h);
            }
            s[j][0] *= scale2; s[j][1] *= scale2;
            s[j][2] *= scale2; s[j][3] *= scale2;
        }

        // online softmax (base-2)
        float mx0 = -1e30f, mx1 = -1e30f;
        #pragma unroll
        for (int j = 0; j < 8; j++) {
            mx0 = fmaxf(mx0, fmaxf(s[j][0], s[j][1]));
            mx1 = fmaxf(mx1, fmaxf(s[j][2], s[j][3]));
        }
        mx0 = fmaxf(mx0, __shfl_xor_sync(0xffffffffu, mx0, 1));
        mx0 = fmaxf(mx0, __shfl_xor_sync(0xffffffffu, mx0, 2));
        mx1 = fmaxf(mx1, __shfl_xor_sync(0xffffffffu, mx1, 1));
        mx1 = fmaxf(mx1, __shfl_xor_sync(0xffffffffu, mx1, 2));
        float nm0 = fmaxf(m0r, mx0), nm1 = fmaxf(m1r, mx1);
        float c0 = ex2(m0r - nm0), c1 = ex2(m1r - nm1);

        float ls0 = 0.f, ls1 = 0.f;
        #pragma unroll
        for (int j = 0; j < 8; j++) {
            s[j][0] = ex2(s[j][0] - nm0); ls0 += s[j][0];
            s[j][1] = ex2(s[j][1] - nm0); ls0 += s[j][1];
            s[j][2] = ex2(s[j][2] - nm1); ls1 += s[j][2];
            s[j][3] = ex2(s[j][3] - nm1); ls1 += s[j][3];
        }
        ls0 += __shfl_xor_sync(0xffffffffu, ls0, 1);
        ls0 += __shfl_xor_sync(0xffffffffu, ls0, 2);
        ls1 += __shfl_xor_sync(0xffffffffu, ls1, 1);
        ls1 += __shfl_xor_sync(0xffffffffu, ls1, 2);
        l0r = l0r * c0 + ls0;
        l1r = l1r * c1 + ls1;
        m0r = nm0; m1r = nm1;

        #pragma unroll
        for (int jn = 0; jn < 4; jn++) {
            Oacc[jn][0] *= c0; Oacc[jn][1] *= c0;
            Oacc[jn][2] *= c1; Oacc[jn][3] *= c1;
        }

        // P -> bf16x2 A fragments
        uint ph[4][4], pl[4][4];
        #pragma unroll
        for (int ks = 0; ks < 4; ks++) {
            split_pair(s[2*ks  ][0], s[2*ks  ][1], ph[ks][0], pl[ks][0]);
            split_pair(s[2*ks  ][2], s[2*ks  ][3], ph[ks][1], pl[ks][1]);
            split_pair(s[2*ks+1][0], s[2*ks+1][1], ph[ks][2], pl[ks][2]);
            split_pair(s[2*ks+1][2], s[2*ks+1][3], ph[ks][3], pl[ks][3]);
        }

        // O += P V
        #pragma unroll
        for (int jn = 0; jn < 4; jn++) {
            int n = jn * 8 + gq;
            #pragma unroll
            for (int ks = 0; ks < 4; ks++) {
                uint b0h = Vhi[bb][n][ks*8 + t], b1h = Vhi[bb][n][ks*8 + t + 4];
                uint b0l = Vlo[bb][n][ks*8 + t], b1l = Vlo[bb][n][ks*8 + t + 4];
                mma_bf16(Oacc[jn], ph[ks][0], ph[ks][1], ph[ks][2], ph[ks][3], b0h, b1h);
                mma_bf16(Oacc[jn], ph[ks][0], ph[ks][1], ph[ks][2], ph[ks][3], b0l, b1l);
                mma_bf16(Oacc[jn], pl[ks][0], pl[ks][1], pl[ks][2], pl[ks][3], b0h, b1h);
            }
        }
    }

    float inv0 = 1.f / l0r, inv1 = 1.f / l1r;
    #pragma unroll
    for (int jn = 0; jn < 4; jn++) {
        int col = head * 32 + jn * 8 + 2 * t;
        *(float2*)&Ob[(size_t)(b * L_ + r0) * 256 + col] =
            make_float2(Oacc[jn][0] * inv0, Oacc[jn][1] * inv0);
        *(float2*)&Ob[(size_t)(b * L_ + r1) * 256 + col] =
            make_float2(Oacc[jn][2] * inv1, Oacc[jn][3] * inv1);
    }
}

// ---------------- combine: acc = h + ffo + O1 + O2 (+planes) ----------------
__global__ void __launch_bounds__(256) combine_kernel(
    const float* __restrict__ O1, const float* __restrict__ O2,
    const float* __restrict__ h, const float* __restrict__ ffo,
    float* __restrict__ acc, uint* __restrict__ ahi, uint* __restrict__ alo)
{
    int tok = blockIdx.x;
    int u = threadIdx.x;
    size_t i = (size_t)tok * 256 + u;
    float o = h[i] + ffo[i] + O1[i] + O2[i];
    acc[i] = o;
    float pn = __shfl_xor_sync(0xffffffffu, o, 1);
    if (!(u & 1)) {
        uint hi, lo; split_pair(o, pn, hi, lo);
        ahi[(size_t)tok * 128 + (u >> 1)] = hi;
        alo[(size_t)tok * 128 + (u >> 1)] = lo;
    }
}

// ---------------- launch -----------------------------------------------------
extern "C" void kernel_launch(void* const* d_in, const int* in_sizes, int n_in,
                              void* d_out, int out_size)
{
    const float* x       = (const float*)d_in[0];
    const float* context = (const float*)d_in[1];
    const float* bn_g = (const float*)d_in[2];
    const float* bn_b = (const float*)d_in[3];
    const float* bn_m = (const float*)d_in[4];
    const float* bn_v = (const float*)d_in[5];
    const float* ln1_g = (const float*)d_in[6];
    const float* ln1_b = (const float*)d_in[7];
    const float* ln2_g = (const float*)d_in[8];
    const float* ln2_b = (const float*)d_in[9];
    const float* ln3_g = (const float*)d_in[10];
    const float* ln3_b = (const float*)d_in[11];
    const float* pin_w = (const float*)d_in[12];
    const float* pin_b = (const float*)d_in[13];
    const float* q_w   = (const float*)d_in[14];
    const float* q_b   = (const float*)d_in[15];
    const float* k_w   = (const float*)d_in[16];
    const float* k_b   = (const float*)d_in[17];
    const float* v_w   = (const float*)d_in[18];
    const float* v_b   = (const float*)d_in[19];
    const float* ff1_w = (const float*)d_in[20];
    const float* ff1_b = (const float*)d_in[21];
    const float* ff2_w = (const float*)d_in[22];
    const float* ff2_b = (const float*)d_in[23];
    const float* pout_w = (const float*)d_in[24];
    const float* pout_b = (const float*)d_in[25];
    float* out = (float*)d_out;

    float *p_h, *p_v1, *p_v2, *p_ffo, *p_acc, *p_O1, *p_O2;
    uint *p_xhi, *p_xlo, *p_cthi, *p_ctlo, *p_hhi, *p_hlo, *p_nhi, *p_nlo;
    uint *p_f1hi, *p_f1lo, *p_ahi, *p_alo;
    uint *p_q1hi, *p_q1lo, *p_k1hi, *p_k1lo, *p_q2hi, *p_q2lo, *p_k2hi, *p_k2lo;
    uint *p_vthi, *p_vtlo;
    uint *w_pin_h, *w_pin_l, *w_q1_h, *w_q1_l, *w_q2_h, *w_q2_l;
    uint *w_k_h, *w_k_l, *w_v_h, *w_v_l, *w_po_h, *w_po_l;
    uint *w_f1_h, *w_f1_l, *w_f2_h, *w_f2_l;
    float *p_bpin, *p_bq1, *p_bq2, *p_bff1;

    cudaGetSymbolAddress((void**)&p_h,    d_h);
    cudaGetSymbolAddress((void**)&p_v1,   d_v1);
    cudaGetSymbolAddress((void**)&p_v2,   d_v2);
    cudaGetSymbolAddress((void**)&p_ffo,  d_ffo);
    cudaGetSymbolAddress((void**)&p_acc,  d_acc);
    cudaGetSymbolAddress((void**)&p_O1,   d_O1);
    cudaGetSymbolAddress((void**)&p_O2,   d_O2);
    cudaGetSymbolAddress((void**)&p_xhi,  d_xhi);
    cudaGetSymbolAddress((void**)&p_xlo,  d_xlo);
    cudaGetSymbolAddress((void**)&p_cthi, d_cthi);
    cudaGetSymbolAddress((void**)&p_ctlo, d_ctlo);
    cudaGetSymbolAddress((void**)&p_hhi,  d_hhi);
    cudaGetSymbolAddress((void**)&p_hlo,  d_hlo);
    cudaGetSymbolAddress((void**)&p_nhi,  d_nhi);
    cudaGetSymbolAddress((void**)&p_nlo,  d_nlo);
    cudaGetSymbolAddress((void**)&p_f1hi, d_f1hi);
    cudaGetSymbolAddress((void**)&p_f1lo, d_f1lo);
    cudaGetSymbolAddress((void**)&p_ahi,  d_ahi);
    cudaGetSymbolAddress((void**)&p_alo,  d_alo);
    cudaGetSymbolAddress((void**)&p_q1hi, d_q1hi);
    cudaGetSymbolAddress((void**)&p_q1lo, d_q1lo);
    cudaGetSymbolAddress((void**)&p_k1hi, d_k1hi);
    cudaGetSymbolAddress((void**)&p_k1lo, d_k1lo);
    cudaGetSymbolAddress((void**)&p_q2hi, d_q2hi);
    cudaGetSymbolAddress((void**)&p_q2lo, d_q2lo);
    cudaGetSymbolAddress((void**)&p_k2hi, d_k2hi);
    cudaGetSymbolAddress((void**)&p_k2lo, d_k2lo);
    cudaGetSymbolAddress((void**)&p_vthi, d_vthi);
    cudaGetSymbolAddress((void**)&p_vtlo, d_vtlo);
    cudaGetSymbolAddress((void**)&w_pin_h, d_Wpin_h);
    cudaGetSymbolAddress((void**)&w_pin_l, d_Wpin_l);
    cudaGetSymbolAddress((void**)&w_q1_h,  d_Wq1_h);
    cudaGetSymbolAddress((void**)&w_q1_l,  d_Wq1_l);
    cudaGetSymbolAddress((void**)&w_q2_h,  d_Wq2_h);
    cudaGetSymbolAddress((void**)&w_q2_l,  d_Wq2_l);
    cudaGetSymbolAddress((void**)&w_k_h,   d_Wk_h);
    cudaGetSymbolAddress((void**)&w_k_l,   d_Wk_l);
    cudaGetSymbolAddress((void**)&w_v_h,   d_Wv_h);
    cudaGetSymbolAddress((void**)&w_v_l,   d_Wv_l);
    cudaGetSymbolAddress((void**)&w_po_h,  d_Wpout_h);
    cudaGetSymbolAddress((void**)&w_po_l,  d_Wpout_l);
    cudaGetSymbolAddress((void**)&w_f1_h,  d_Wff1_h);
    cudaGetSymbolAddress((void**)&w_f1_l,  d_Wff1_l);
    cudaGetSymbolAddress((void**)&w_f2_h,  d_Wff2_h);
    cudaGetSymbolAddress((void**)&w_f2_l,  d_Wff2_l);
    cudaGetSymbolAddress((void**)&p_bpin,  d_bpin);
    cudaGetSymbolAddress((void**)&p_bq1,   d_bq1);
    cudaGetSymbolAddress((void**)&p_bq2,   d_bq2);
    cudaGetSymbolAddress((void**)&p_bff1,  d_bff1);

    // 1. all prep in one launch
    prep_all<<<5472, 256>>>(x, context, bn_g, bn_b, bn_m, bn_v,
                            ln1_g, ln1_b, ln2_g, ln2_b, ln3_g, ln3_b,
                            pin_w, pin_b, q_w, q_b, k_w, v_w,
                            ff1_w, ff1_b, ff2_w, pout_w);

    auto mkop = [](const uint* Ahi, const uint* Alo, const uint* Whi, const uint* Wlo,
                   const float* bias, const float* resid, float* o,
                   uint* Ohi, uint* Olo, int N, int K, int flags, int start) {
        GOp g; g.Ahi = Ahi; g.Alo = Alo; g.Whi = Whi; g.Wlo = Wlo;
        g.bias = bias; g.resid = resid; g.out = o; g.Ohi = Ohi; g.Olo = Olo;
        g.N = N; g.K = K; g.flags = flags; g.tileStart = start;
        return g;
    };
    const int RT = NTOK / 64;          // 54
    const int T256 = RT * 4;           // 216

    // 2. batch A: pin + k2 + v2 (context projections don't need pin)
    {
        GBatch P = {};
        P.op[0] = mkop(p_xhi, p_xlo, w_pin_h, w_pin_l, p_bpin, nullptr,
                       p_h, p_hhi, p_hlo, 256, 256, FOUT | FRELU | FPLANES, 0);
        P.op[1] = mkop(p_cthi, p_ctlo, w_k_h, w_k_l, k_b, nullptr,
                       nullptr, p_k2hi, p_k2lo, 256, 256, FPLANES, T256);
        P.op[2] = mkop(p_cthi, p_ctlo, w_v_h, w_v_l, v_b, nullptr,
                       p_v2, nullptr, nullptr, 256, 256, FOUT, T256*2);
        P.nops = 3;
        gemmT<<<T256*3, 128>>>(P);
    }

    // 3. hhat planes
    lnorm_kernel<<<NTOK, 256>>>(p_h, p_nhi, p_nlo);

    // 4. batch B: q1, k1, v1, q2, ff1
    {
        GBatch P = {};
        P.op[0] = mkop(p_nhi, p_nlo, w_q1_h, w_q1_l, p_bq1, nullptr,
                       nullptr, p_q1hi, p_q1lo, 256, 256, FPLANES, 0);
        P.op[1] = mkop(p_hhi, p_hlo, w_k_h, w_k_l, k_b, nullptr,
                       nullptr, p_k1hi, p_k1lo, 256, 256, FPLANES, T256);
        P.op[2] = mkop(p_hhi, p_hlo, w_v_h, w_v_l, v_b, nullptr,
                       p_v1, nullptr, nullptr, 256, 256, FOUT, T256*2);
        P.op[3] = mkop(p_nhi, p_nlo, w_q2_h, w_q2_l, p_bq2, nullptr,
                       nullptr, p_q2hi, p_q2lo, 256, 256, FPLANES, T256*3);
        P.op[4] = mkop(p_nhi, p_nlo, w_f1_h, w_f1_l, p_bff1, nullptr,
                       nullptr, p_f1hi, p_f1lo, 1024, 256, FRELU | FPLANES, T256*4);
        P.nops = 5;
        gemmT<<<T256*4 + RT*16, 128>>>(P);   // 864 + 864 = 1728
    }

    // 5. V transpose planes
    {
        dim3 gv(NKT, H_, 4);
        vplanes_T<<<gv, 128>>>(p_v1, p_v2, p_vthi, p_vtlo);
    }

    // 6. attention (tensor cores, pipelined, exp2)
    {
        dim3 ga(NKT, H_, 4);
        attn_mma<<<ga, 128>>>(p_q1hi, p_q1lo, p_k1hi, p_k1lo,
                              p_q2hi, p_q2lo, p_k2hi, p_k2lo,
                              p_vthi, p_vtlo, p_O1, p_O2);
    }

    // 7. ff2
    {
        GBatch P = {};
        P.op[0] = mkop(p_f1hi, p_f1lo, w_f2_h, w_f2_l, ff2_b, nullptr,
                       p_ffo, nullptr, nullptr, 256, 1024, FOUT, 0);
        P.nops = 1;
        gemmT<<<T256, 128>>>(P);
    }

    // 8. combine -> acc (+planes)
    combine_kernel<<<NTOK, 256>>>(p_O1, p_O2, p_h, p_ffo, p_acc, p_ahi, p_alo);

    // 9. out = relu(acc @ pout + b) + x
    {
        GBatch P = {};
        P.op[0] = mkop(p_ahi, p_alo, w_po_h, w_po_l, pout_b, x,
                       out, nullptr, nullptr, 256, 256, FOUT | FRELU | FRESID, 0);
        P.nops = 1;
        gemmT<<<T256, 128>>>(P);
    }
}